// round 9
// baseline (speedup 1.0000x reference)
#include <cuda_runtime.h>
#include <cuda_bf16.h>
#include <math.h>
#include <stdint.h>

// ---------------------------------------------------------------------------
// TimeSformer forward. B=2, T=8, N=196, C=768, H=12, hd=64, depth=12.
// GEMMs: bf16x3 tensor-core (hi/lo split), 128x256 CTA, 64x64 warp tiles,
// 3-stage cp.async pipeline, fused scatter/residual epilogues.
// ---------------------------------------------------------------------------

constexpr int BATCH = 2;
constexpr int TT    = 8;
constexpr int NP    = 196;
constexpr int CD    = 768;
constexpr int NH    = 12;
constexpr int HD    = 64;
constexpr int SEQ   = 1 + TT * NP;          // 1569
constexpr int RT    = BATCH * TT * NP;      // 3136
constexpr int KS    = NP + 1;               // 197
constexpr int RS    = BATCH * TT * KS;      // 3152
constexpr int RX    = BATCH * SEQ;          // 3138
constexpr int GROUPS= BATCH * TT * NH;      // 192
constexpr int DEPTH = 12;

// -------------------------- scratch (device globals) -----------------------
__device__ float g_xb     [(size_t)BATCH * SEQ * CD];
__device__ float g_buf2   [(size_t)BATCH * CD];          // final-LN cls rows
__device__ float g_buf3   [(size_t)RS * CD];             // sproj cls rows
__device__ float g_qkv    [(size_t)RS * 3 * CD];
__device__ float g_scores [(size_t)GROUPS * KS * KS];

// hi/lo split activation buffers
__device__ __nv_bfloat16 g_ln_hi[(size_t)RS * CD];
__device__ __nv_bfloat16 g_ln_lo[(size_t)RS * CD];
__device__ __nv_bfloat16 g_at_hi[(size_t)RS * CD];
__device__ __nv_bfloat16 g_at_lo[(size_t)RS * CD];
__device__ __nv_bfloat16 g_f1_hi[(size_t)RX * 4 * CD];
__device__ __nv_bfloat16 g_f1_lo[(size_t)RX * 4 * CD];
__device__ __nv_bfloat16 g_pa_hi[(size_t)RT * CD];
__device__ __nv_bfloat16 g_pa_lo[(size_t)RT * CD];

// weight split buffers
constexpr size_t SZ_TQKV = (size_t)DEPTH * 3 * CD * CD;
constexpr size_t SZ_CC   = (size_t)DEPTH * CD * CD;
constexpr size_t SZ_FC   = (size_t)DEPTH * 4 * CD * CD;
constexpr size_t W_TQKV  = 0;
constexpr size_t W_TPROJ = W_TQKV + SZ_TQKV;
constexpr size_t W_TFC   = W_TPROJ + SZ_CC;
constexpr size_t W_SQKV  = W_TFC + SZ_CC;
constexpr size_t W_SPROJ = W_SQKV + SZ_TQKV;
constexpr size_t W_FC1   = W_SPROJ + SZ_CC;
constexpr size_t W_FC2   = W_FC1 + SZ_FC;
constexpr size_t W_CONV  = W_FC2 + SZ_FC;
constexpr size_t W_TOTAL = W_CONV + (size_t)CD * CD;

__device__ __nv_bfloat16 g_w_hi[W_TOTAL];
__device__ __nv_bfloat16 g_w_lo[W_TOTAL];

// ------------------------------ split helper --------------------------------
__device__ __forceinline__ void split2(float x, __nv_bfloat16& h, __nv_bfloat16& l)
{
    h = __float2bfloat16(x);
    l = __float2bfloat16(x - __bfloat162float(h));
}

// ------------------------- weight split kernel -------------------------------
__global__ void __launch_bounds__(256) wsplit_kernel(
    const float4* __restrict__ src, __nv_bfloat162* __restrict__ hi,
    __nv_bfloat162* __restrict__ lo, long n4)
{
    long i = blockIdx.x * (long)blockDim.x + threadIdx.x;
    if (i >= n4) return;
    float4 v = src[i];
    __nv_bfloat16 h0,l0,h1,l1,h2,l2,h3,l3;
    split2(v.x, h0, l0); split2(v.y, h1, l1);
    split2(v.z, h2, l2); split2(v.w, h3, l3);
    hi[2*i]   = __halves2bfloat162(h0, h1);
    hi[2*i+1] = __halves2bfloat162(h2, h3);
    lo[2*i]   = __halves2bfloat162(l0, l1);
    lo[2*i+1] = __halves2bfloat162(l2, l3);
}

// ------------------------- bf16x3 tensor-core GEMM ---------------------------
// C[m,n] = sum_k A[m,k]*W[n,k] + bias[n].  3 MMA terms: hh + hl + lh.
// modes: 0 f32->C | 1 GELU->bf16 hi/lo | 2 bf16 hi/lo
//        3 time-scatter += xb | 4 += xb (residual) | 5 space-scatter += xb

__device__ __forceinline__ void cpa16(uint32_t dst, const void* src, int srcsz)
{
    asm volatile("cp.async.ca.shared.global [%0], [%1], 16, %2;"
                 :: "r"(dst), "l"(src), "r"(srcsz));
}
__device__ __forceinline__ void ldmx4(uint32_t& r0, uint32_t& r1,
                                      uint32_t& r2, uint32_t& r3, uint32_t addr)
{
    asm volatile("ldmatrix.sync.aligned.m8n8.x4.shared.b16 {%0,%1,%2,%3}, [%4];"
        : "=r"(r0), "=r"(r1), "=r"(r2), "=r"(r3) : "r"(addr));
}
__device__ __forceinline__ void mma_bf(float* c, const uint32_t* a, const uint32_t* b)
{
    asm volatile("mma.sync.aligned.m16n8k16.row.col.f32.bf16.bf16.f32 "
        "{%0,%1,%2,%3}, {%4,%5,%6,%7}, {%8,%9}, {%0,%1,%2,%3};"
        : "+f"(c[0]), "+f"(c[1]), "+f"(c[2]), "+f"(c[3])
        : "r"(a[0]), "r"(a[1]), "r"(a[2]), "r"(a[3]), "r"(b[0]), "r"(b[1]));
}

// stage layout (bf16 elems): [Ah 128x40][Al 128x40][Wh 256x40][Wl 256x40]
constexpr int ST_ELEMS = 128*40*2 + 256*40*2;            // 30720
constexpr int GEMM_SMEM = 3 * ST_ELEMS * 2;              // 184320 B
#define OA(s, arr, row, col) ((s)*ST_ELEMS + (arr)*128*40 + (row)*40 + (col))
#define OW(s, arr, row, col) ((s)*ST_ELEMS + 2*128*40 + (arr)*256*40 + (row)*40 + (col))

__global__ void __launch_bounds__(256, 1) bf_gemm_kernel(
    const __nv_bfloat16* __restrict__ Ah, const __nv_bfloat16* __restrict__ Al,
    const __nv_bfloat16* __restrict__ Wh, const __nv_bfloat16* __restrict__ Wl,
    const float* __restrict__ bias, float* __restrict__ C,
    __nv_bfloat16* __restrict__ Oh, __nv_bfloat16* __restrict__ Ol,
    int M, int N, int K, int mode)
{
    extern __shared__ __align__(16) __nv_bfloat16 sm[];
    const uint32_t smb = (uint32_t)__cvta_generic_to_shared(sm);

    const int tid  = threadIdx.x;
    const int wid  = tid >> 5;
    const int lane = tid & 31;
    const int wm   = wid & 1;           // 0..1  -> 64-row warp tile
    const int wn   = wid >> 1;          // 0..3  -> 64-col warp tile
    const int g    = lane >> 2;
    const int q    = lane & 3;
    const int row0 = blockIdx.y * 128;
    const int col0 = blockIdx.x * 256;

    float acc[4][8][4];
    #pragma unroll
    for (int i = 0; i < 4; i++)
        #pragma unroll
        for (int j = 0; j < 8; j++)
            #pragma unroll
            for (int v = 0; v < 4; v++) acc[i][j][v] = 0.f;

    const int T = K / 32;

    auto prefetch = [&](int t, int s) {
        const int k0 = t * 32;
        // A arrays: 512 16B-chunks each -> 2 per thread
        #pragma unroll
        for (int i = 0; i < 2; i++) {
            int ch = tid * 2 + i;
            int row = ch >> 2, c4 = ch & 3;
            int gr = row0 + row;
            int ok = (gr < M) ? 16 : 0;
            size_t off = (size_t)(gr < M ? gr : 0) * K + k0 + c4 * 8;
            cpa16(smb + OA(s, 0, row, c4*8) * 2, Ah + off, ok);
            cpa16(smb + OA(s, 1, row, c4*8) * 2, Al + off, ok);
        }
        // W arrays: 1024 chunks each -> 4 per thread
        #pragma unroll
        for (int i = 0; i < 4; i++) {
            int ch = tid * 4 + i;
            int row = ch >> 2, c4 = ch & 3;
            size_t off = (size_t)(col0 + row) * K + k0 + c4 * 8;
            cpa16(smb + OW(s, 0, row, c4*8) * 2, Wh + off, 16);
            cpa16(smb + OW(s, 1, row, c4*8) * 2, Wl + off, 16);
        }
        asm volatile("cp.async.commit_group;" ::: "memory");
    };

    prefetch(0, 0);
    prefetch(1, 1);

    const int fr = lane & 15;
    for (int t = 0; t < T; t++) {
        const int s = t % 3;
        if (t == T - 1)
            asm volatile("cp.async.wait_group 0;" ::: "memory");
        else
            asm volatile("cp.async.wait_group 1;" ::: "memory");
        __syncthreads();
        if (t + 2 < T) prefetch(t + 2, (t + 2) % 3);

        #pragma unroll
        for (int kh = 0; kh < 32; kh += 16) {
            const int fc = kh + (lane >> 4) * 8;
            uint32_t bh[8][2], bl[8][2];
            #pragma unroll
            for (int pr = 0; pr < 4; pr++) {
                int nr = wn * 64 + pr * 16 + fr;
                uint32_t r0, r1, r2, r3;
                ldmx4(r0, r1, r2, r3, smb + OW(s, 0, nr, fc) * 2);
                bh[2*pr][0] = r0; bh[2*pr+1][0] = r1;
                bh[2*pr][1] = r2; bh[2*pr+1][1] = r3;
                ldmx4(r0, r1, r2, r3, smb + OW(s, 1, nr, fc) * 2);
                bl[2*pr][0] = r0; bl[2*pr+1][0] = r1;
                bl[2*pr][1] = r2; bl[2*pr+1][1] = r3;
            }
            #pragma unroll
            for (int mt = 0; mt < 4; mt++) {
                int mr = wm * 64 + mt * 16 + fr;
                uint32_t ah[4], al[4];
                ldmx4(ah[0], ah[1], ah[2], ah[3], smb + OA(s, 0, mr, fc) * 2);
                ldmx4(al[0], al[1], al[2], al[3], smb + OA(s, 1, mr, fc) * 2);
                #pragma unroll
                for (int nt = 0; nt < 8; nt++) {
                    mma_bf(acc[mt][nt], ah, bh[nt]);   // hi*hi
                    mma_bf(acc[mt][nt], ah, bl[nt]);   // hi*lo
                    mma_bf(acc[mt][nt], al, bh[nt]);   // lo*hi
                }
            }
        }
        __syncthreads();
    }

    // ------------------------------ epilogue --------------------------------
    #pragma unroll
    for (int mt = 0; mt < 4; mt++) {
        int r0 = row0 + wm * 64 + mt * 16 + g;
        #pragma unroll
        for (int h = 0; h < 2; h++) {
            int r = r0 + 8 * h;
            if (r >= M) continue;
            // row -> destination base for scatter modes
            size_t xbase = 0; bool is_cls = false;
            if (mode == 3) {
                int tt = r % TT; int bn = r / TT; int n = bn % NP; int b = bn / NP;
                xbase = ((size_t)b * SEQ + 1 + tt * NP + n) * CD;
            } else if (mode == 4) {
                xbase = (size_t)r * CD;
            } else if (mode == 5) {
                int m = r % KS; int bt = r / KS; int tt = bt % TT; int b = bt / TT;
                if (m == 0) { is_cls = true; xbase = (size_t)r * CD; }
                else xbase = ((size_t)b * SEQ + 1 + tt * NP + (m - 1)) * CD;
            }
            #pragma unroll
            for (int nt = 0; nt < 8; nt++) {
                int cc = col0 + wn * 64 + nt * 8 + 2 * q;
                float v0 = acc[mt][nt][2*h]     + bias[cc];
                float v1 = acc[mt][nt][2*h + 1] + bias[cc + 1];
                if (mode == 0) {
                    *(float2*)&C[(size_t)r * N + cc] = make_float2(v0, v1);
                } else if (mode == 1 || mode == 2) {
                    if (mode == 1) { v0 = v0 * normcdff(v0); v1 = v1 * normcdff(v1); }
                    __nv_bfloat16 h0, l0, h1, l1;
                    split2(v0, h0, l0); split2(v1, h1, l1);
                    *(__nv_bfloat162*)&Oh[(size_t)r * N + cc] = __halves2bfloat162(h0, h1);
                    *(__nv_bfloat162*)&Ol[(size_t)r * N + cc] = __halves2bfloat162(l0, l1);
                } else if (mode == 5 && is_cls) {
                    *(float2*)&g_buf3[xbase + cc] = make_float2(v0, v1);
                } else {
                    float2 old = *(float2*)&g_xb[xbase + cc];
                    old.x += v0; old.y += v1;
                    *(float2*)&g_xb[xbase + cc] = old;
                }
            }
        }
    }
}

// ------------------------------ LayerNorm -----------------------------------
__device__ __forceinline__ float blk_sum(float v, float* smr)
{
    const int lane = threadIdx.x & 31, w = threadIdx.x >> 5;
    #pragma unroll
    for (int o = 16; o; o >>= 1) v += __shfl_xor_sync(0xffffffffu, v, o);
    if (lane == 0) smr[w] = v;
    __syncthreads();
    if (threadIdx.x == 0) {
        float t = 0.f;
        #pragma unroll
        for (int i = 0; i < 8; i++) t += smr[i];
        smr[8] = t;
    }
    __syncthreads();
    float t = smr[8];
    __syncthreads();
    return t;
}

// LN with fused gather; output split bf16 hi/lo.
// gm 0: in + r*CD.  gm 1: time gather from g_xb.  gm 2: space gather from g_xb.
__global__ void __launch_bounds__(256) ln_hl_kernel(
    const float* __restrict__ in, const float* __restrict__ w,
    const float* __restrict__ b, __nv_bfloat16* __restrict__ oh,
    __nv_bfloat16* __restrict__ ol, int gm)
{
    __shared__ float smr[9];
    const int r = blockIdx.x;
    const float* x;
    if (gm == 0) {
        x = in + (size_t)r * CD;
    } else if (gm == 1) {
        int t = r % TT; int bn = r / TT; int n = bn % NP; int bb = bn / NP;
        x = in + ((size_t)bb * SEQ + 1 + t * NP + n) * CD;
    } else {
        int m = r % KS; int bt = r / KS; int t = bt % TT; int bb = bt / TT;
        x = in + ((m == 0) ? ((size_t)bb * SEQ) * CD
                           : ((size_t)bb * SEQ + 1 + t * NP + (m - 1)) * CD);
    }
    const int t = threadIdx.x;
    float v0 = x[t], v1 = x[t + 256], v2 = x[t + 512];
    float tot = blk_sum(v0 + v1 + v2, smr);
    float mean = tot * (1.0f / CD);
    float d0 = v0 - mean, d1 = v1 - mean, d2 = v2 - mean;
    float tot2 = blk_sum(d0 * d0 + d1 * d1 + d2 * d2, smr);
    float inv = rsqrtf(tot2 * (1.0f / CD) + 1e-6f);
    size_t base = (size_t)r * CD;
    float o0 = d0 * inv * w[t]       + b[t];
    float o1 = d1 * inv * w[t + 256] + b[t + 256];
    float o2 = d2 * inv * w[t + 512] + b[t + 512];
    split2(o0, oh[base + t],       ol[base + t]);
    split2(o1, oh[base + t + 256], ol[base + t + 256]);
    split2(o2, oh[base + t + 512], ol[base + t + 512]);
}

// final LN on the 2 cls rows only
__global__ void __launch_bounds__(256) ln_cls_kernel(
    const float* __restrict__ w, const float* __restrict__ b)
{
    __shared__ float smr[9];
    const float* x = g_xb + (size_t)blockIdx.x * SEQ * CD;
    const int t = threadIdx.x;
    float v0 = x[t], v1 = x[t + 256], v2 = x[t + 512];
    float tot = blk_sum(v0 + v1 + v2, smr);
    float mean = tot * (1.0f / CD);
    float d0 = v0 - mean, d1 = v1 - mean, d2 = v2 - mean;
    float tot2 = blk_sum(d0 * d0 + d1 * d1 + d2 * d2, smr);
    float inv = rsqrtf(tot2 * (1.0f / CD) + 1e-6f);
    float* o = g_buf2 + (size_t)blockIdx.x * CD;
    o[t]       = d0 * inv * w[t]       + b[t];
    o[t + 256] = d1 * inv * w[t + 256] + b[t + 256];
    o[t + 512] = d2 * inv * w[t + 512] + b[t + 512];
}

// ------------------------- Time attention (seq=8) ---------------------------
__global__ void __launch_bounds__(64) time_attn_kernel()
{
    const int g = blockIdx.x;
    const int h = g % NH;
    const int bn = g / NH;
    const int lane = threadIdx.x;
    __shared__ float Q[TT][HD + 1], Kk[TT][HD + 1], V[TT][HD + 1];
    __shared__ float P[TT][TT + 1];
    #pragma unroll
    for (int t = 0; t < TT; t++) {
        size_t base = ((size_t)(bn * TT + t)) * (3 * CD) + h * HD + lane;
        Q[t][lane]  = g_qkv[base];
        Kk[t][lane] = g_qkv[base + CD];
        V[t][lane]  = g_qkv[base + 2 * CD];
    }
    __syncthreads();
    const int tq = lane >> 3, tk = lane & 7;
    float s = 0.f;
    #pragma unroll
    for (int d = 0; d < HD; d++) s += Q[tq][d] * Kk[tk][d];
    P[tq][tk] = s * 0.125f;
    __syncthreads();
    if (lane < TT) {
        float m = -1e30f;
        #pragma unroll
        for (int k = 0; k < TT; k++) m = fmaxf(m, P[lane][k]);
        float sum = 0.f;
        #pragma unroll
        for (int k = 0; k < TT; k++) { float e = expf(P[lane][k] - m); P[lane][k] = e; sum += e; }
        float inv = 1.f / sum;
        #pragma unroll
        for (int k = 0; k < TT; k++) P[lane][k] *= inv;
    }
    __syncthreads();
    #pragma unroll
    for (int t = 0; t < TT; t++) {
        float a = 0.f;
        #pragma unroll
        for (int k = 0; k < TT; k++) a += P[t][k] * V[k][lane];
        size_t idx = ((size_t)(bn * TT + t)) * CD + h * HD + lane;
        split2(a, g_at_hi[idx], g_at_lo[idx]);
    }
}

// ------------------------- Space attention (seq=197) ------------------------
__global__ void __launch_bounds__(256) space_scores_kernel()
{
    const int g = blockIdx.x;
    const int h = g % NH, bt = g / NH;
    const int q0 = blockIdx.y * 32, k0 = blockIdx.z * 64;
    __shared__ float Qs[32][HD + 1];
    __shared__ float Ksm[64][HD + 1];
    const int tid = threadIdx.x;
    for (int i = tid; i < 32 * 64; i += 256) {
        int r = i >> 6, d = i & 63; int gq = q0 + r;
        Qs[r][d] = (gq < KS) ? g_qkv[((size_t)(bt * KS + gq)) * (3 * CD) + h * HD + d] : 0.f;
    }
    for (int i = tid; i < 64 * 64; i += 256) {
        int r = i >> 6, d = i & 63; int gk = k0 + r;
        Ksm[r][d] = (gk < KS) ? g_qkv[((size_t)(bt * KS + gk)) * (3 * CD) + CD + h * HD + d] : 0.f;
    }
    __syncthreads();
    const int kc = tid & 63, qb = tid >> 6;
    float s[8];
    #pragma unroll
    for (int i = 0; i < 8; i++) s[i] = 0.f;
    #pragma unroll
    for (int d = 0; d < HD; d++) {
        float kv = Ksm[kc][d];
        #pragma unroll
        for (int i = 0; i < 8; i++) s[i] = fmaf(Qs[qb + 4 * i][d], kv, s[i]);
    }
    const int gk = k0 + kc;
    if (gk < KS) {
        #pragma unroll
        for (int i = 0; i < 8; i++) {
            int gq = q0 + qb + 4 * i;
            if (gq < KS) g_scores[((size_t)g * KS + gq) * KS + gk] = s[i] * 0.125f;
        }
    }
}

// 8 rows per block (1 warp each)
__global__ void __launch_bounds__(256) softmax197_kernel()
{
    const size_t row = blockIdx.x * 8 + (threadIdx.x >> 5);
    if (row >= (size_t)GROUPS * KS) return;
    float* p = g_scores + row * KS;
    const int lane = threadIdx.x & 31;
    float vals[7];
    float m = -1e30f;
    #pragma unroll
    for (int i = 0; i < 7; i++) {
        int j = lane + 32 * i;
        vals[i] = (j < KS) ? p[j] : -1e30f;
        m = fmaxf(m, vals[i]);
    }
    #pragma unroll
    for (int o = 16; o; o >>= 1) m = fmaxf(m, __shfl_xor_sync(0xffffffffu, m, o));
    float s = 0.f;
    #pragma unroll
    for (int i = 0; i < 7; i++) {
        int j = lane + 32 * i;
        if (j < KS) { vals[i] = expf(vals[i] - m); s += vals[i]; }
    }
    #pragma unroll
    for (int o = 16; o; o >>= 1) s += __shfl_xor_sync(0xffffffffu, s, o);
    float inv = 1.f / s;
    #pragma unroll
    for (int i = 0; i < 7; i++) {
        int j = lane + 32 * i;
        if (j < KS) p[j] = vals[i] * inv;
    }
}

__global__ void __launch_bounds__(256) space_pv_kernel()
{
    const int g = blockIdx.x;
    const int h = g % NH, bt = g / NH;
    const int q0 = blockIdx.y * 32;
    __shared__ float Ps[32][33];
    __shared__ float Vs[32][HD + 1];
    const int tid = threadIdx.x;
    const int dc = tid & 63, qb = tid >> 6;
    float acc[8];
    #pragma unroll
    for (int i = 0; i < 8; i++) acc[i] = 0.f;
    for (int c0 = 0; c0 < KS; c0 += 32) {
        for (int i = tid; i < 32 * 32; i += 256) {
            int r = i >> 5, c = i & 31; int gq = q0 + r, gk = c0 + c;
            Ps[r][c] = (gq < KS && gk < KS) ? g_scores[((size_t)g * KS + gq) * KS + gk] : 0.f;
        }
        for (int i = tid; i < 32 * 64; i += 256) {
            int r = i >> 6, d = i & 63; int gk = c0 + r;
            Vs[r][d] = (gk < KS) ? g_qkv[((size_t)(bt * KS + gk)) * (3 * CD) + 2 * CD + h * HD + d] : 0.f;
        }
        __syncthreads();
        #pragma unroll
        for (int kk = 0; kk < 32; kk++) {
            float vv = Vs[kk][dc];
            #pragma unroll
            for (int i = 0; i < 8; i++) acc[i] = fmaf(Ps[qb + 4 * i][kk], vv, acc[i]);
        }
        __syncthreads();
    }
    #pragma unroll
    for (int i = 0; i < 8; i++) {
        int gq = q0 + qb + 4 * i;
        if (gq < KS) {
            size_t idx = ((size_t)(bt * KS + gq)) * CD + h * HD + dc;
            split2(acc[i], g_at_hi[idx], g_at_lo[idx]);
        }
    }
}

// --------------------------- elementwise helpers ----------------------------
__global__ void patchify_kernel(const float* __restrict__ x)
{
    int i = blockIdx.x * blockDim.x + threadIdx.x;
    if (i >= RT * CD) return;
    int k = i % CD; int r = i / CD;
    int n = r % NP; int bt = r / NP; int t = bt % TT; int b = bt / TT;
    int ci = k >> 8; int rem = k & 255; int py = rem >> 4; int px = rem & 15;
    int nh = n / 14, nw = n % 14;
    size_t src = ((((size_t)b * 3 + ci) * TT + t) * 224 + (nh * 16 + py)) * 224 + (nw * 16 + px);
    split2(x[src], g_pa_hi[i], g_pa_lo[i]);
}

__global__ void init_cls_kernel(const float* __restrict__ cls_token,
                                const float* __restrict__ pos_embed)
{
    int i = blockIdx.x * blockDim.x + threadIdx.x;
    if (i >= BATCH * CD) return;
    int b = i / CD, c = i % CD;
    g_xb[((size_t)b * SEQ) * CD + c] = cls_token[c] + pos_embed[c];
}

// patch-embed GEMM wrote buf3 (mode 0); add pos+time embeds into xb
__global__ void init_patch_kernel(const float* __restrict__ pos_embed,
                                  const float* __restrict__ time_embed)
{
    int i = blockIdx.x * blockDim.x + threadIdx.x;
    if (i >= RT * CD) return;
    int c = i % CD; int r = i / CD;
    int n = r % NP; int bt = r / NP; int t = bt % TT; int b = bt / TT;
    g_xb[((size_t)b * SEQ + 1 + t * NP + n) * CD + c] =
        g_buf3[i] + pos_embed[(size_t)(1 + n) * CD + c] + time_embed[(size_t)t * CD + c];
}

__global__ void combine_cls_kernel()
{
    int i = blockIdx.x * blockDim.x + threadIdx.x;
    if (i >= BATCH * CD) return;
    int b = i / CD, c = i % CD;
    float s = 0.f;
    #pragma unroll
    for (int t = 0; t < TT; t++)
        s += g_buf3[((size_t)((b * TT + t) * KS)) * CD + c];
    g_xb[((size_t)b * SEQ) * CD + c] += s * (1.f / TT);
}

// ------------------------------- head ---------------------------------------
__global__ void __launch_bounds__(256) head_kernel(
    const float* __restrict__ hw, const float* __restrict__ hb,
    float* __restrict__ out)
{
    const int warp = threadIdx.x >> 5, lane = threadIdx.x & 31;
    const int o = blockIdx.x * 8 + warp;
    if (o >= BATCH * 1000) return;
    const int b = o / 1000, j = o % 1000;
    const float* xr = g_buf2 + (size_t)b * CD;
    const float* wr = hw + (size_t)j * CD;
    float s = 0.f;
    for (int k = lane; k < CD; k += 32) s += xr[k] * wr[k];
    #pragma unroll
    for (int off = 16; off; off >>= 1) s += __shfl_down_sync(0xffffffffu, s, off);
    if (lane == 0) out[o] = s + hb[j];
}

// ------------------------------ launcher ------------------------------------
static inline int cdiv(int a, int b) { return (a + b - 1) / b; }

static void gemm_bf(const __nv_bfloat16* Ah, const __nv_bfloat16* Al,
                    const __nv_bfloat16* Wh, const __nv_bfloat16* Wl,
                    const float* bias, float* C,
                    __nv_bfloat16* Oh, __nv_bfloat16* Ol,
                    int M, int N, int K, int mode)
{
    dim3 gr(N / 256, cdiv(M, 128));
    bf_gemm_kernel<<<gr, 256, GEMM_SMEM>>>(Ah, Al, Wh, Wl, bias, C, Oh, Ol,
                                           M, N, K, mode);
}

static void wsplit(const float* src, __nv_bfloat16* hi, __nv_bfloat16* lo, size_t n)
{
    long n4 = (long)(n / 4);
    wsplit_kernel<<<(int)((n4 + 255) / 256), 256>>>(
        (const float4*)src, (__nv_bfloat162*)hi, (__nv_bfloat162*)lo, n4);
}

extern "C" void kernel_launch(void* const* d_in, const int* in_sizes, int n_in,
                              void* d_out, int out_size)
{
    const float* x          = (const float*)d_in[0];
    const float* conv_w     = (const float*)d_in[1];
    const float* conv_b     = (const float*)d_in[2];
    const float* cls_token  = (const float*)d_in[3];
    const float* pos_embed  = (const float*)d_in[4];
    const float* time_embed = (const float*)d_in[5];
    const float* tn_w   = (const float*)d_in[6];
    const float* tn_b   = (const float*)d_in[7];
    const float* tqkv_w = (const float*)d_in[8];
    const float* tqkv_b = (const float*)d_in[9];
    const float* tproj_w= (const float*)d_in[10];
    const float* tproj_b= (const float*)d_in[11];
    const float* tfc_w  = (const float*)d_in[12];
    const float* tfc_b  = (const float*)d_in[13];
    const float* n1_w   = (const float*)d_in[14];
    const float* n1_b   = (const float*)d_in[15];
    const float* sqkv_w = (const float*)d_in[16];
    const float* sqkv_b = (const float*)d_in[17];
    const float* sproj_w= (const float*)d_in[18];
    const float* sproj_b= (const float*)d_in[19];
    const float* n2_w   = (const float*)d_in[20];
    const float* n2_b   = (const float*)d_in[21];
    const float* fc1_w  = (const float*)d_in[22];
    const float* fc1_b  = (const float*)d_in[23];
    const float* fc2_w  = (const float*)d_in[24];
    const float* fc2_b  = (const float*)d_in[25];
    const float* norm_w = (const float*)d_in[26];
    const float* norm_b = (const float*)d_in[27];
    const float* head_w = (const float*)d_in[28];
    const float* head_b = (const float*)d_in[29];

    float *xb, *buf3, *qkv;
    cudaGetSymbolAddress((void**)&xb,   g_xb);
    cudaGetSymbolAddress((void**)&buf3, g_buf3);
    cudaGetSymbolAddress((void**)&qkv,  g_qkv);

    __nv_bfloat16 *whi, *wlo, *lnh, *lnl, *ath, *atl, *f1h, *f1l, *pah, *pal;
    cudaGetSymbolAddress((void**)&whi, g_w_hi);
    cudaGetSymbolAddress((void**)&wlo, g_w_lo);
    cudaGetSymbolAddress((void**)&lnh, g_ln_hi);
    cudaGetSymbolAddress((void**)&lnl, g_ln_lo);
    cudaGetSymbolAddress((void**)&ath, g_at_hi);
    cudaGetSymbolAddress((void**)&atl, g_at_lo);
    cudaGetSymbolAddress((void**)&f1h, g_f1_hi);
    cudaGetSymbolAddress((void**)&f1l, g_f1_lo);
    cudaGetSymbolAddress((void**)&pah, g_pa_hi);
    cudaGetSymbolAddress((void**)&pal, g_pa_lo);

    cudaFuncSetAttribute(bf_gemm_kernel,
                         cudaFuncAttributeMaxDynamicSharedMemorySize, GEMM_SMEM);

    const int EB = 256;

    // ---- split all weights into bf16 hi/lo ----
    wsplit(tqkv_w,  whi + W_TQKV,  wlo + W_TQKV,  SZ_TQKV);
    wsplit(tproj_w, whi + W_TPROJ, wlo + W_TPROJ, SZ_CC);
    wsplit(tfc_w,   whi + W_TFC,   wlo + W_TFC,   SZ_CC);
    wsplit(sqkv_w,  whi + W_SQKV,  wlo + W_SQKV,  SZ_TQKV);
    wsplit(sproj_w, whi + W_SPROJ, wlo + W_SPROJ, SZ_CC);
    wsplit(fc1_w,   whi + W_FC1,   wlo + W_FC1,   SZ_FC);
    wsplit(fc2_w,   whi + W_FC2,   wlo + W_FC2,   SZ_FC);
    wsplit(conv_w,  whi + W_CONV,  wlo + W_CONV,  (size_t)CD * CD);

    // ---- patch embedding + pos/time embed + cls init ----
    patchify_kernel<<<cdiv(RT * CD, EB), EB>>>(x);
    gemm_bf(pah, pal, whi + W_CONV, wlo + W_CONV, conv_b, buf3, nullptr, nullptr,
            RT, CD, CD, 0);
    init_cls_kernel<<<cdiv(BATCH * CD, EB), EB>>>(cls_token, pos_embed);
    init_patch_kernel<<<cdiv(RT * CD, EB), EB>>>(pos_embed, time_embed);

    // ---- transformer blocks ----
    for (int l = 0; l < DEPTH; l++) {
        size_t o3 = (size_t)l * 3 * CD * CD;
        size_t o1 = (size_t)l * CD * CD;
        size_t o4 = (size_t)l * 4 * CD * CD;

        // ===== time attention =====
        ln_hl_kernel<<<RT, 256>>>(xb, tn_w + (size_t)l * CD, tn_b + (size_t)l * CD,
                                  lnh, lnl, 1);
        gemm_bf(lnh, lnl, whi + W_TQKV + o3, wlo + W_TQKV + o3,
                tqkv_b + (size_t)l * 3 * CD, qkv, nullptr, nullptr,
                RT, 3 * CD, CD, 0);
        time_attn_kernel<<<(RT / TT) * NH, 64>>>();
        gemm_bf(ath, atl, whi + W_TPROJ + o1, wlo + W_TPROJ + o1,
                tproj_b + (size_t)l * CD, nullptr, f1h, f1l,
                RT, CD, CD, 2);
        gemm_bf(f1h, f1l, whi + W_TFC + o1, wlo + W_TFC + o1,
                tfc_b + (size_t)l * CD, nullptr, nullptr, nullptr,
                RT, CD, CD, 3);                       // scatter-add into xb

        // ===== space attention =====
        ln_hl_kernel<<<RS, 256>>>(xb, n1_w + (size_t)l * CD, n1_b + (size_t)l * CD,
                                  lnh, lnl, 2);
        gemm_bf(lnh, lnl, whi + W_SQKV + o3, wlo + W_SQKV + o3,
                sqkv_b + (size_t)l * 3 * CD, qkv, nullptr, nullptr,
                RS, 3 * CD, CD, 0);
        {
            dim3 gr(GROUPS, cdiv(KS, 32), cdiv(KS, 64));
            space_scores_kernel<<<gr, 256>>>();
        }
        softmax197_kernel<<<cdiv(GROUPS * KS, 8), 256>>>();
        {
            dim3 gr(GROUPS, cdiv(KS, 32));
            space_pv_kernel<<<gr, 256>>>();
        }
        gemm_bf(ath, atl, whi + W_SPROJ + o1, wlo + W_SPROJ + o1,
                sproj_b + (size_t)l * CD, nullptr, nullptr, nullptr,
                RS, CD, CD, 5);                       // scatter-add + cls->buf3
        combine_cls_kernel<<<cdiv(BATCH * CD, EB), EB>>>();

        // ===== MLP =====
        ln_hl_kernel<<<RX, 256>>>(xb, n2_w + (size_t)l * CD, n2_b + (size_t)l * CD,
                                  lnh, lnl, 0);
        gemm_bf(lnh, lnl, whi + W_FC1 + o4, wlo + W_FC1 + o4,
                fc1_b + (size_t)l * 4 * CD, nullptr, f1h, f1l,
                RX, 4 * CD, CD, 1);
        gemm_bf(f1h, f1l, whi + W_FC2 + o4, wlo + W_FC2 + o4,
                fc2_b + (size_t)l * CD, nullptr, nullptr, nullptr,
                RX, CD, 4 * CD, 4);                   // residual add into xb
    }

    // ---- final norm (cls rows only) + head ----
    ln_cls_kernel<<<BATCH, 256>>>(norm_w, norm_b);
    head_kernel<<<cdiv(BATCH * 1000, 8), 256>>>(head_w, head_b, (float*)d_out);
}

// round 11
// speedup vs baseline: 1.5887x; 1.5887x over previous
#include <cuda_runtime.h>
#include <cuda_bf16.h>
#include <math.h>
#include <stdint.h>

// ---------------------------------------------------------------------------
// TimeSformer forward. B=2, T=8, N=196, C=768, H=12, hd=64, depth=12.
// GEMMs: bf16x3 tensor-core (hi/lo split), 128x128 CTA, 64x32 warp tiles,
// 2-stage cp.async pipeline (R6 config), fused scatter/residual epilogues.
// ---------------------------------------------------------------------------

constexpr int BATCH = 2;
constexpr int TT    = 8;
constexpr int NP    = 196;
constexpr int CD    = 768;
constexpr int NH    = 12;
constexpr int HD    = 64;
constexpr int SEQ   = 1 + TT * NP;          // 1569
constexpr int RT    = BATCH * TT * NP;      // 3136
constexpr int KS    = NP + 1;               // 197
constexpr int RS    = BATCH * TT * KS;      // 3152
constexpr int RX    = BATCH * SEQ;          // 3138
constexpr int GROUPS= BATCH * TT * NH;      // 192
constexpr int DEPTH = 12;

// -------------------------- scratch (device globals) -----------------------
__device__ float g_xb     [(size_t)BATCH * SEQ * CD];
__device__ float g_buf2   [(size_t)BATCH * CD];          // final-LN cls rows
__device__ float g_buf3   [(size_t)RS * CD];             // patch embed / sproj cls rows
__device__ float g_qkv    [(size_t)RS * 3 * CD];
__device__ float g_scores [(size_t)GROUPS * KS * KS];

// hi/lo split activation buffers
__device__ __nv_bfloat16 g_ln_hi[(size_t)RS * CD];
__device__ __nv_bfloat16 g_ln_lo[(size_t)RS * CD];
__device__ __nv_bfloat16 g_at_hi[(size_t)RS * CD];
__device__ __nv_bfloat16 g_at_lo[(size_t)RS * CD];
__device__ __nv_bfloat16 g_f1_hi[(size_t)RX * 4 * CD];
__device__ __nv_bfloat16 g_f1_lo[(size_t)RX * 4 * CD];
__device__ __nv_bfloat16 g_pa_hi[(size_t)RT * CD];
__device__ __nv_bfloat16 g_pa_lo[(size_t)RT * CD];

// weight split buffers
constexpr size_t SZ_TQKV = (size_t)DEPTH * 3 * CD * CD;
constexpr size_t SZ_CC   = (size_t)DEPTH * CD * CD;
constexpr size_t SZ_FC   = (size_t)DEPTH * 4 * CD * CD;
constexpr size_t W_TQKV  = 0;
constexpr size_t W_TPROJ = W_TQKV + SZ_TQKV;
constexpr size_t W_TFC   = W_TPROJ + SZ_CC;
constexpr size_t W_SQKV  = W_TFC + SZ_CC;
constexpr size_t W_SPROJ = W_SQKV + SZ_TQKV;
constexpr size_t W_FC1   = W_SPROJ + SZ_CC;
constexpr size_t W_FC2   = W_FC1 + SZ_FC;
constexpr size_t W_CONV  = W_FC2 + SZ_FC;
constexpr size_t W_TOTAL = W_CONV + (size_t)CD * CD;

__device__ __nv_bfloat16 g_w_hi[W_TOTAL];
__device__ __nv_bfloat16 g_w_lo[W_TOTAL];

// ------------------------------ split helper --------------------------------
__device__ __forceinline__ void split2(float x, __nv_bfloat16& h, __nv_bfloat16& l)
{
    h = __float2bfloat16(x);
    l = __float2bfloat16(x - __bfloat162float(h));
}

// ------------------------- weight split kernel -------------------------------
__global__ void __launch_bounds__(256) wsplit_kernel(
    const float4* __restrict__ src, __nv_bfloat162* __restrict__ hi,
    __nv_bfloat162* __restrict__ lo, long n4)
{
    long i = blockIdx.x * (long)blockDim.x + threadIdx.x;
    if (i >= n4) return;
    float4 v = src[i];
    __nv_bfloat16 h0,l0,h1,l1,h2,l2,h3,l3;
    split2(v.x, h0, l0); split2(v.y, h1, l1);
    split2(v.z, h2, l2); split2(v.w, h3, l3);
    hi[2*i]   = __halves2bfloat162(h0, h1);
    hi[2*i+1] = __halves2bfloat162(h2, h3);
    lo[2*i]   = __halves2bfloat162(l0, l1);
    lo[2*i+1] = __halves2bfloat162(l2, l3);
}

// ------------------------- bf16x3 tensor-core GEMM ---------------------------
// C[m,n] = sum_k A[m,k]*W[n,k] + bias[n].  3 MMA terms: hh + hl + lh.
// modes: 0 f32->C | 1 GELU->bf16 hi/lo | 2 bf16 hi/lo
//        3 time-scatter += xb | 4 += xb (residual) | 5 space-scatter += xb

__device__ __forceinline__ void cpa16(uint32_t dst, const void* src, int srcsz)
{
    asm volatile("cp.async.ca.shared.global [%0], [%1], 16, %2;"
                 :: "r"(dst), "l"(src), "r"(srcsz));
}
__device__ __forceinline__ void ldmx4(uint32_t& r0, uint32_t& r1,
                                      uint32_t& r2, uint32_t& r3, uint32_t addr)
{
    asm volatile("ldmatrix.sync.aligned.m8n8.x4.shared.b16 {%0,%1,%2,%3}, [%4];"
        : "=r"(r0), "=r"(r1), "=r"(r2), "=r"(r3) : "r"(addr));
}
__device__ __forceinline__ void mma_bf(float* c, const uint32_t* a, const uint32_t* b)
{
    asm volatile("mma.sync.aligned.m16n8k16.row.col.f32.bf16.bf16.f32 "
        "{%0,%1,%2,%3}, {%4,%5,%6,%7}, {%8,%9}, {%0,%1,%2,%3};"
        : "+f"(c[0]), "+f"(c[1]), "+f"(c[2]), "+f"(c[3])
        : "r"(a[0]), "r"(a[1]), "r"(a[2]), "r"(a[3]), "r"(b[0]), "r"(b[1]));
}

// smem: [stage(2)][arr(4: Ah,Al,Wh,Wl)][row(128)][col(40 bf16, 80B stride)]
#define SOFF(s, arr, row, col) (((((s)*4 + (arr))*128 + (row))*40 + (col)))
constexpr int GEMM_SMEM = 2 * 4 * 128 * 40 * 2;   // 81920 bytes

__global__ void __launch_bounds__(256) bf_gemm_kernel(
    const __nv_bfloat16* __restrict__ Ah, const __nv_bfloat16* __restrict__ Al,
    const __nv_bfloat16* __restrict__ Wh, const __nv_bfloat16* __restrict__ Wl,
    const float* __restrict__ bias, float* __restrict__ C,
    __nv_bfloat16* __restrict__ Oh, __nv_bfloat16* __restrict__ Ol,
    int M, int N, int K, int mode)
{
    extern __shared__ __align__(16) __nv_bfloat16 sm[];
    const uint32_t smb = (uint32_t)__cvta_generic_to_shared(sm);

    const int tid  = threadIdx.x;
    const int wid  = tid >> 5;
    const int lane = tid & 31;
    const int wm   = wid >> 2;          // 0..1  (64-row warp tile)
    const int wn   = wid & 3;           // 0..3  (32-col warp tile)
    const int g    = lane >> 2;
    const int q    = lane & 3;
    const int row0 = blockIdx.y * 128;
    const int col0 = blockIdx.x * 128;

    float acc[4][4][4];
    #pragma unroll
    for (int i = 0; i < 4; i++)
        #pragma unroll
        for (int j = 0; j < 4; j++)
            #pragma unroll
            for (int v = 0; v < 4; v++) acc[i][j][v] = 0.f;

    const int lrow = tid >> 1;          // 0..127
    const int c0b  = (tid & 1) * 2;     // 16B-chunk base {0,2}

    const int T = K / 32;

    auto prefetch = [&](int t, int s) {
        const int k0 = t * 32;
        int gr = row0 + lrow;
        int av = (gr < M) ? 16 : 0;
        size_t aoff = (size_t)(gr < M ? gr : 0) * K + k0;
        size_t boff = (size_t)(col0 + lrow) * K + k0;
        #pragma unroll
        for (int c = c0b; c < c0b + 2; c++) {
            cpa16(smb + SOFF(s, 0, lrow, c*8) * 2, Ah + aoff + c*8, av);
            cpa16(smb + SOFF(s, 1, lrow, c*8) * 2, Al + aoff + c*8, av);
            cpa16(smb + SOFF(s, 2, lrow, c*8) * 2, Wh + boff + c*8, 16);
            cpa16(smb + SOFF(s, 3, lrow, c*8) * 2, Wl + boff + c*8, 16);
        }
        asm volatile("cp.async.commit_group;" ::: "memory");
    };

    prefetch(0, 0);

    const int fr = lane & 15;
    for (int t = 0; t < T; t++) {
        const int s = t & 1;
        asm volatile("cp.async.wait_group 0;" ::: "memory");
        __syncthreads();
        if (t + 1 < T) prefetch(t + 1, (t + 1) & 1);

        #pragma unroll
        for (int kh = 0; kh < 32; kh += 16) {
            const int fc = kh + (lane >> 4) * 8;
            uint32_t bh[4][2], bl[4][2];
            #pragma unroll
            for (int pr = 0; pr < 2; pr++) {
                int nr = wn * 32 + pr * 16 + fr;
                uint32_t r0, r1, r2, r3;
                ldmx4(r0, r1, r2, r3, smb + SOFF(s, 2, nr, fc) * 2);
                bh[2*pr][0] = r0; bh[2*pr+1][0] = r1;
                bh[2*pr][1] = r2; bh[2*pr+1][1] = r3;
                ldmx4(r0, r1, r2, r3, smb + SOFF(s, 3, nr, fc) * 2);
                bl[2*pr][0] = r0; bl[2*pr+1][0] = r1;
                bl[2*pr][1] = r2; bl[2*pr+1][1] = r3;
            }
            #pragma unroll
            for (int mt = 0; mt < 4; mt++) {
                int mr = wm * 64 + mt * 16 + fr;
                uint32_t ah[4], al[4];
                ldmx4(ah[0], ah[1], ah[2], ah[3], smb + SOFF(s, 0, mr, fc) * 2);
                ldmx4(al[0], al[1], al[2], al[3], smb + SOFF(s, 1, mr, fc) * 2);
                #pragma unroll
                for (int nt = 0; nt < 4; nt++) {
                    mma_bf(acc[mt][nt], ah, bh[nt]);   // hi*hi
                    mma_bf(acc[mt][nt], ah, bl[nt]);   // hi*lo
                    mma_bf(acc[mt][nt], al, bh[nt]);   // lo*hi
                }
            }
        }
        __syncthreads();
    }

    // ------------------------------ epilogue --------------------------------
    #pragma unroll
    for (int mt = 0; mt < 4; mt++) {
        int r0 = row0 + wm * 64 + mt * 16 + g;
        #pragma unroll
        for (int h = 0; h < 2; h++) {
            int r = r0 + 8 * h;
            if (r >= M) continue;
            size_t xbase = 0; bool is_cls = false;
            if (mode == 3) {
                int tt = r % TT; int bn = r / TT; int n = bn % NP; int b = bn / NP;
                xbase = ((size_t)b * SEQ + 1 + tt * NP + n) * CD;
            } else if (mode == 4) {
                xbase = (size_t)r * CD;
            } else if (mode == 5) {
                int m = r % KS; int bt = r / KS; int tt = bt % TT; int b = bt / TT;
                if (m == 0) { is_cls = true; xbase = (size_t)r * CD; }
                else xbase = ((size_t)b * SEQ + 1 + tt * NP + (m - 1)) * CD;
            }
            #pragma unroll
            for (int nt = 0; nt < 4; nt++) {
                int cc = col0 + wn * 32 + nt * 8 + 2 * q;
                float v0 = acc[mt][nt][2*h]     + bias[cc];
                float v1 = acc[mt][nt][2*h + 1] + bias[cc + 1];
                if (mode == 0) {
                    *(float2*)&C[(size_t)r * N + cc] = make_float2(v0, v1);
                } else if (mode == 1 || mode == 2) {
                    if (mode == 1) { v0 = v0 * normcdff(v0); v1 = v1 * normcdff(v1); }
                    __nv_bfloat16 h0, l0, h1, l1;
                    split2(v0, h0, l0); split2(v1, h1, l1);
                    *(__nv_bfloat162*)&Oh[(size_t)r * N + cc] = __halves2bfloat162(h0, h1);
                    *(__nv_bfloat162*)&Ol[(size_t)r * N + cc] = __halves2bfloat162(l0, l1);
                } else if (mode == 5 && is_cls) {
                    *(float2*)&g_buf3[xbase + cc] = make_float2(v0, v1);
                } else {
                    float2 old = *(float2*)&g_xb[xbase + cc];
                    old.x += v0; old.y += v1;
                    *(float2*)&g_xb[xbase + cc] = old;
                }
            }
        }
    }
}

// ------------------------------ LayerNorm -----------------------------------
__device__ __forceinline__ float blk_sum(float v, float* smr)
{
    const int lane = threadIdx.x & 31, w = threadIdx.x >> 5;
    #pragma unroll
    for (int o = 16; o; o >>= 1) v += __shfl_xor_sync(0xffffffffu, v, o);
    if (lane == 0) smr[w] = v;
    __syncthreads();
    if (threadIdx.x == 0) {
        float t = 0.f;
        #pragma unroll
        for (int i = 0; i < 8; i++) t += smr[i];
        smr[8] = t;
    }
    __syncthreads();
    float t = smr[8];
    __syncthreads();
    return t;
}

// LN with fused gather; output split bf16 hi/lo.
// gm 0: in + r*CD.  gm 1: time gather from g_xb.  gm 2: space gather from g_xb.
__global__ void __launch_bounds__(256) ln_hl_kernel(
    const float* __restrict__ in, const float* __restrict__ w,
    const float* __restrict__ b, __nv_bfloat16* __restrict__ oh,
    __nv_bfloat16* __restrict__ ol, int gm)
{
    __shared__ float smr[9];
    const int r = blockIdx.x;
    const float* x;
    if (gm == 0) {
        x = in + (size_t)r * CD;
    } else if (gm == 1) {
        int t = r % TT; int bn = r / TT; int n = bn % NP; int bb = bn / NP;
        x = in + ((size_t)bb * SEQ + 1 + t * NP + n) * CD;
    } else {
        int m = r % KS; int bt = r / KS; int t = bt % TT; int bb = bt / TT;
        x = in + ((m == 0) ? ((size_t)bb * SEQ) * CD
                           : ((size_t)bb * SEQ + 1 + t * NP + (m - 1)) * CD);
    }
    const int t = threadIdx.x;
    float v0 = x[t], v1 = x[t + 256], v2 = x[t + 512];
    float tot = blk_sum(v0 + v1 + v2, smr);
    float mean = tot * (1.0f / CD);
    float d0 = v0 - mean, d1 = v1 - mean, d2 = v2 - mean;
    float tot2 = blk_sum(d0 * d0 + d1 * d1 + d2 * d2, smr);
    float inv = rsqrtf(tot2 * (1.0f / CD) + 1e-6f);
    size_t base = (size_t)r * CD;
    float o0 = d0 * inv * w[t]       + b[t];
    float o1 = d1 * inv * w[t + 256] + b[t + 256];
    float o2 = d2 * inv * w[t + 512] + b[t + 512];
    split2(o0, oh[base + t],       ol[base + t]);
    split2(o1, oh[base + t + 256], ol[base + t + 256]);
    split2(o2, oh[base + t + 512], ol[base + t + 512]);
}

// final LN on the 2 cls rows only
__global__ void __launch_bounds__(256) ln_cls_kernel(
    const float* __restrict__ w, const float* __restrict__ b)
{
    __shared__ float smr[9];
    const float* x = g_xb + (size_t)blockIdx.x * SEQ * CD;
    const int t = threadIdx.x;
    float v0 = x[t], v1 = x[t + 256], v2 = x[t + 512];
    float tot = blk_sum(v0 + v1 + v2, smr);
    float mean = tot * (1.0f / CD);
    float d0 = v0 - mean, d1 = v1 - mean, d2 = v2 - mean;
    float tot2 = blk_sum(d0 * d0 + d1 * d1 + d2 * d2, smr);
    float inv = rsqrtf(tot2 * (1.0f / CD) + 1e-6f);
    float* o = g_buf2 + (size_t)blockIdx.x * CD;
    o[t]       = d0 * inv * w[t]       + b[t];
    o[t + 256] = d1 * inv * w[t + 256] + b[t + 256];
    o[t + 512] = d2 * inv * w[t + 512] + b[t + 512];
}

// ------------------------- Time attention (seq=8) ---------------------------
__global__ void __launch_bounds__(64) time_attn_kernel()
{
    const int g = blockIdx.x;
    const int h = g % NH;
    const int bn = g / NH;
    const int lane = threadIdx.x;
    __shared__ float Q[TT][HD + 1], Kk[TT][HD + 1], V[TT][HD + 1];
    __shared__ float P[TT][TT + 1];
    #pragma unroll
    for (int t = 0; t < TT; t++) {
        size_t base = ((size_t)(bn * TT + t)) * (3 * CD) + h * HD + lane;
        Q[t][lane]  = g_qkv[base];
        Kk[t][lane] = g_qkv[base + CD];
        V[t][lane]  = g_qkv[base + 2 * CD];
    }
    __syncthreads();
    const int tq = lane >> 3, tk = lane & 7;
    float s = 0.f;
    #pragma unroll
    for (int d = 0; d < HD; d++) s += Q[tq][d] * Kk[tk][d];
    P[tq][tk] = s * 0.125f;
    __syncthreads();
    if (lane < TT) {
        float m = -1e30f;
        #pragma unroll
        for (int k = 0; k < TT; k++) m = fmaxf(m, P[lane][k]);
        float sum = 0.f;
        #pragma unroll
        for (int k = 0; k < TT; k++) { float e = expf(P[lane][k] - m); P[lane][k] = e; sum += e; }
        float inv = 1.f / sum;
        #pragma unroll
        for (int k = 0; k < TT; k++) P[lane][k] *= inv;
    }
    __syncthreads();
    #pragma unroll
    for (int t = 0; t < TT; t++) {
        float a = 0.f;
        #pragma unroll
        for (int k = 0; k < TT; k++) a += P[t][k] * V[k][lane];
        size_t idx = ((size_t)(bn * TT + t)) * CD + h * HD + lane;
        split2(a, g_at_hi[idx], g_at_lo[idx]);
    }
}

// ------------------------- Space attention (seq=197) ------------------------
__global__ void __launch_bounds__(256) space_scores_kernel()
{
    const int g = blockIdx.x;
    const int h = g % NH, bt = g / NH;
    const int q0 = blockIdx.y * 32, k0 = blockIdx.z * 64;
    __shared__ float Qs[32][HD + 1];
    __shared__ float Ksm[64][HD + 1];
    const int tid = threadIdx.x;
    for (int i = tid; i < 32 * 64; i += 256) {
        int r = i >> 6, d = i & 63; int gq = q0 + r;
        Qs[r][d] = (gq < KS) ? g_qkv[((size_t)(bt * KS + gq)) * (3 * CD) + h * HD + d] : 0.f;
    }
    for (int i = tid; i < 64 * 64; i += 256) {
        int r = i >> 6, d = i & 63; int gk = k0 + r;
        Ksm[r][d] = (gk < KS) ? g_qkv[((size_t)(bt * KS + gk)) * (3 * CD) + CD + h * HD + d] : 0.f;
    }
    __syncthreads();
    const int kc = tid & 63, qb = tid >> 6;
    float s[8];
    #pragma unroll
    for (int i = 0; i < 8; i++) s[i] = 0.f;
    #pragma unroll
    for (int d = 0; d < HD; d++) {
        float kv = Ksm[kc][d];
        #pragma unroll
        for (int i = 0; i < 8; i++) s[i] = fmaf(Qs[qb + 4 * i][d], kv, s[i]);
    }
    const int gk = k0 + kc;
    if (gk < KS) {
        #pragma unroll
        for (int i = 0; i < 8; i++) {
            int gq = q0 + qb + 4 * i;
            if (gq < KS) g_scores[((size_t)g * KS + gq) * KS + gk] = s[i] * 0.125f;
        }
    }
}

// 8 rows per block (1 warp each)
__global__ void __launch_bounds__(256) softmax197_kernel()
{
    const size_t row = blockIdx.x * 8 + (threadIdx.x >> 5);
    if (row >= (size_t)GROUPS * KS) return;
    float* p = g_scores + row * KS;
    const int lane = threadIdx.x & 31;
    float vals[7];
    float m = -1e30f;
    #pragma unroll
    for (int i = 0; i < 7; i++) {
        int j = lane + 32 * i;
        vals[i] = (j < KS) ? p[j] : -1e30f;
        m = fmaxf(m, vals[i]);
    }
    #pragma unroll
    for (int o = 16; o; o >>= 1) m = fmaxf(m, __shfl_xor_sync(0xffffffffu, m, o));
    float s = 0.f;
    #pragma unroll
    for (int i = 0; i < 7; i++) {
        int j = lane + 32 * i;
        if (j < KS) { vals[i] = expf(vals[i] - m); s += vals[i]; }
    }
    #pragma unroll
    for (int o = 16; o; o >>= 1) s += __shfl_xor_sync(0xffffffffu, s, o);
    float inv = 1.f / s;
    #pragma unroll
    for (int i = 0; i < 7; i++) {
        int j = lane + 32 * i;
        if (j < KS) p[j] = vals[i] * inv;
    }
}

__global__ void __launch_bounds__(256) space_pv_kernel()
{
    const int g = blockIdx.x;
    const int h = g % NH, bt = g / NH;
    const int q0 = blockIdx.y * 32;
    __shared__ float Ps[32][33];
    __shared__ float Vs[32][HD + 1];
    const int tid = threadIdx.x;
    const int dc = tid & 63, qb = tid >> 6;
    float acc[8];
    #pragma unroll
    for (int i = 0; i < 8; i++) acc[i] = 0.f;
    for (int c0 = 0; c0 < KS; c0 += 32) {
        for (int i = tid; i < 32 * 32; i += 256) {
            int r = i >> 5, c = i & 31; int gq = q0 + r, gk = c0 + c;
            Ps[r][c] = (gq < KS && gk < KS) ? g_scores[((size_t)g * KS + gq) * KS + gk] : 0.f;
        }
        for (int i = tid; i < 32 * 64; i += 256) {
            int r = i >> 6, d = i & 63; int gk = c0 + r;
            Vs[r][d] = (gk < KS) ? g_qkv[((size_t)(bt * KS + gk)) * (3 * CD) + 2 * CD + h * HD + d] : 0.f;
        }
        __syncthreads();
        #pragma unroll
        for (int kk = 0; kk < 32; kk++) {
            float vv = Vs[kk][dc];
            #pragma unroll
            for (int i = 0; i < 8; i++) acc[i] = fmaf(Ps[qb + 4 * i][kk], vv, acc[i]);
        }
        __syncthreads();
    }
    #pragma unroll
    for (int i = 0; i < 8; i++) {
        int gq = q0 + qb + 4 * i;
        if (gq < KS) {
            size_t idx = ((size_t)(bt * KS + gq)) * CD + h * HD + dc;
            split2(acc[i], g_at_hi[idx], g_at_lo[idx]);
        }
    }
}

// --------------------------- elementwise helpers ----------------------------
__global__ void patchify_kernel(const float* __restrict__ x)
{
    int i = blockIdx.x * blockDim.x + threadIdx.x;
    if (i >= RT * CD) return;
    int k = i % CD; int r = i / CD;
    int n = r % NP; int bt = r / NP; int t = bt % TT; int b = bt / TT;
    int ci = k >> 8; int rem = k & 255; int py = rem >> 4; int px = rem & 15;
    int nh = n / 14, nw = n % 14;
    size_t src = ((((size_t)b * 3 + ci) * TT + t) * 224 + (nh * 16 + py)) * 224 + (nw * 16 + px);
    split2(x[src], g_pa_hi[i], g_pa_lo[i]);
}

__global__ void init_cls_kernel(const float* __restrict__ cls_token,
                                const float* __restrict__ pos_embed)
{
    int i = blockIdx.x * blockDim.x + threadIdx.x;
    if (i >= BATCH * CD) return;
    int b = i / CD, c = i % CD;
    g_xb[((size_t)b * SEQ) * CD + c] = cls_token[c] + pos_embed[c];
}

// patch-embed GEMM wrote buf3 (mode 0); add pos+time embeds into xb
__global__ void init_patch_kernel(const float* __restrict__ pos_embed,
                                  const float* __restrict__ time_embed)
{
    int i = blockIdx.x * blockDim.x + threadIdx.x;
    if (i >= RT * CD) return;
    int c = i % CD; int r = i / CD;
    int n = r % NP; int bt = r / NP; int t = bt % TT; int b = bt / TT;
    g_xb[((size_t)b * SEQ + 1 + t * NP + n) * CD + c] =
        g_buf3[i] + pos_embed[(size_t)(1 + n) * CD + c] + time_embed[(size_t)t * CD + c];
}

__global__ void combine_cls_kernel()
{
    int i = blockIdx.x * blockDim.x + threadIdx.x;
    if (i >= BATCH * CD) return;
    int b = i / CD, c = i % CD;
    float s = 0.f;
    #pragma unroll
    for (int t = 0; t < TT; t++)
        s += g_buf3[((size_t)((b * TT + t) * KS)) * CD + c];
    g_xb[((size_t)b * SEQ) * CD + c] += s * (1.f / TT);
}

// ------------------------------- head ---------------------------------------
__global__ void __launch_bounds__(256) head_kernel(
    const float* __restrict__ hw, const float* __restrict__ hb,
    float* __restrict__ out)
{
    const int warp = threadIdx.x >> 5, lane = threadIdx.x & 31;
    const int o = blockIdx.x * 8 + warp;
    if (o >= BATCH * 1000) return;
    const int b = o / 1000, j = o % 1000;
    const float* xr = g_buf2 + (size_t)b * CD;
    const float* wr = hw + (size_t)j * CD;
    float s = 0.f;
    for (int k = lane; k < CD; k += 32) s += xr[k] * wr[k];
    #pragma unroll
    for (int off = 16; off; off >>= 1) s += __shfl_down_sync(0xffffffffu, s, off);
    if (lane == 0) out[o] = s + hb[j];
}

// ------------------------------ launcher ------------------------------------
static inline int cdiv(int a, int b) { return (a + b - 1) / b; }

static void gemm_bf(const __nv_bfloat16* Ah, const __nv_bfloat16* Al,
                    const __nv_bfloat16* Wh, const __nv_bfloat16* Wl,
                    const float* bias, float* C,
                    __nv_bfloat16* Oh, __nv_bfloat16* Ol,
                    int M, int N, int K, int mode)
{
    dim3 gr(N / 128, cdiv(M, 128));
    bf_gemm_kernel<<<gr, 256, GEMM_SMEM>>>(Ah, Al, Wh, Wl, bias, C, Oh, Ol,
                                           M, N, K, mode);
}

static void wsplit(const float* src, __nv_bfloat16* hi, __nv_bfloat16* lo, size_t n)
{
    long n4 = (long)(n / 4);
    wsplit_kernel<<<(int)((n4 + 255) / 256), 256>>>(
        (const float4*)src, (__nv_bfloat162*)hi, (__nv_bfloat162*)lo, n4);
}

extern "C" void kernel_launch(void* const* d_in, const int* in_sizes, int n_in,
                              void* d_out, int out_size)
{
    const float* x          = (const float*)d_in[0];
    const float* conv_w     = (const float*)d_in[1];
    const float* conv_b     = (const float*)d_in[2];
    const float* cls_token  = (const float*)d_in[3];
    const float* pos_embed  = (const float*)d_in[4];
    const float* time_embed = (const float*)d_in[5];
    const float* tn_w   = (const float*)d_in[6];
    const float* tn_b   = (const float*)d_in[7];
    const float* tqkv_w = (const float*)d_in[8];
    const float* tqkv_b = (const float*)d_in[9];
    const float* tproj_w= (const float*)d_in[10];
    const float* tproj_b= (const float*)d_in[11];
    const float* tfc_w  = (const float*)d_in[12];
    const float* tfc_b  = (const float*)d_in[13];
    const float* n1_w   = (const float*)d_in[14];
    const float* n1_b   = (const float*)d_in[15];
    const float* sqkv_w = (const float*)d_in[16];
    const float* sqkv_b = (const float*)d_in[17];
    const float* sproj_w= (const float*)d_in[18];
    const float* sproj_b= (const float*)d_in[19];
    const float* n2_w   = (const float*)d_in[20];
    const float* n2_b   = (const float*)d_in[21];
    const float* fc1_w  = (const float*)d_in[22];
    const float* fc1_b  = (const float*)d_in[23];
    const float* fc2_w  = (const float*)d_in[24];
    const float* fc2_b  = (const float*)d_in[25];
    const float* norm_w = (const float*)d_in[26];
    const float* norm_b = (const float*)d_in[27];
    const float* head_w = (const float*)d_in[28];
    const float* head_b = (const float*)d_in[29];

    float *xb, *buf3, *qkv;
    cudaGetSymbolAddress((void**)&xb,   g_xb);
    cudaGetSymbolAddress((void**)&buf3, g_buf3);
    cudaGetSymbolAddress((void**)&qkv,  g_qkv);

    __nv_bfloat16 *whi, *wlo, *lnh, *lnl, *ath, *atl, *f1h, *f1l, *pah, *pal;
    cudaGetSymbolAddress((void**)&whi, g_w_hi);
    cudaGetSymbolAddress((void**)&wlo, g_w_lo);
    cudaGetSymbolAddress((void**)&lnh, g_ln_hi);
    cudaGetSymbolAddress((void**)&lnl, g_ln_lo);
    cudaGetSymbolAddress((void**)&ath, g_at_hi);
    cudaGetSymbolAddress((void**)&atl, g_at_lo);
    cudaGetSymbolAddress((void**)&f1h, g_f1_hi);
    cudaGetSymbolAddress((void**)&f1l, g_f1_lo);
    cudaGetSymbolAddress((void**)&pah, g_pa_hi);
    cudaGetSymbolAddress((void**)&pal, g_pa_lo);

    cudaFuncSetAttribute(bf_gemm_kernel,
                         cudaFuncAttributeMaxDynamicSharedMemorySize, GEMM_SMEM);

    const int EB = 256;

    // ---- split all weights into bf16 hi/lo ----
    wsplit(tqkv_w,  whi + W_TQKV,  wlo + W_TQKV,  SZ_TQKV);
    wsplit(tproj_w, whi + W_TPROJ, wlo + W_TPROJ, SZ_CC);
    wsplit(tfc_w,   whi + W_TFC,   wlo + W_TFC,   SZ_CC);
    wsplit(sqkv_w,  whi + W_SQKV,  wlo + W_SQKV,  SZ_TQKV);
    wsplit(sproj_w, whi + W_SPROJ, wlo + W_SPROJ, SZ_CC);
    wsplit(fc1_w,   whi + W_FC1,   wlo + W_FC1,   SZ_FC);
    wsplit(fc2_w,   whi + W_FC2,   wlo + W_FC2,   SZ_FC);
    wsplit(conv_w,  whi + W_CONV,  wlo + W_CONV,  (size_t)CD * CD);

    // ---- patch embedding + pos/time embed + cls init ----
    patchify_kernel<<<cdiv(RT * CD, EB), EB>>>(x);
    gemm_bf(pah, pal, whi + W_CONV, wlo + W_CONV, conv_b, buf3, nullptr, nullptr,
            RT, CD, CD, 0);
    init_cls_kernel<<<cdiv(BATCH * CD, EB), EB>>>(cls_token, pos_embed);
    init_patch_kernel<<<cdiv(RT * CD, EB), EB>>>(pos_embed, time_embed);

    // ---- transformer blocks ----
    for (int l = 0; l < DEPTH; l++) {
        size_t o3 = (size_t)l * 3 * CD * CD;
        size_t o1 = (size_t)l * CD * CD;
        size_t o4 = (size_t)l * 4 * CD * CD;

        // ===== time attention =====
        ln_hl_kernel<<<RT, 256>>>(xb, tn_w + (size_t)l * CD, tn_b + (size_t)l * CD,
                                  lnh, lnl, 1);
        gemm_bf(lnh, lnl, whi + W_TQKV + o3, wlo + W_TQKV + o3,
                tqkv_b + (size_t)l * 3 * CD, qkv, nullptr, nullptr,
                RT, 3 * CD, CD, 0);
        time_attn_kernel<<<(RT / TT) * NH, 64>>>();
        gemm_bf(ath, atl, whi + W_TPROJ + o1, wlo + W_TPROJ + o1,
                tproj_b + (size_t)l * CD, nullptr, f1h, f1l,
                RT, CD, CD, 2);
        gemm_bf(f1h, f1l, whi + W_TFC + o1, wlo + W_TFC + o1,
                tfc_b + (size_t)l * CD, nullptr, nullptr, nullptr,
                RT, CD, CD, 3);                       // scatter-add into xb

        // ===== space attention =====
        ln_hl_kernel<<<RS, 256>>>(xb, n1_w + (size_t)l * CD, n1_b + (size_t)l * CD,
                                  lnh, lnl, 2);
        gemm_bf(lnh, lnl, whi + W_SQKV + o3, wlo + W_SQKV + o3,
                sqkv_b + (size_t)l * 3 * CD, qkv, nullptr, nullptr,
                RS, 3 * CD, CD, 0);
        {
            dim3 gr(GROUPS, cdiv(KS, 32), cdiv(KS, 64));
            space_scores_kernel<<<gr, 256>>>();
        }
        softmax197_kernel<<<cdiv(GROUPS * KS, 8), 256>>>();
        {
            dim3 gr(GROUPS, cdiv(KS, 32));
            space_pv_kernel<<<gr, 256>>>();
        }
        gemm_bf(ath, atl, whi + W_SPROJ + o1, wlo + W_SPROJ + o1,
                sproj_b + (size_t)l * CD, nullptr, nullptr, nullptr,
                RS, CD, CD, 5);                       // scatter-add + cls->buf3
        combine_cls_kernel<<<cdiv(BATCH * CD, EB), EB>>>();

        // ===== MLP =====
        ln_hl_kernel<<<RX, 256>>>(xb, n2_w + (size_t)l * CD, n2_b + (size_t)l * CD,
                                  lnh, lnl, 0);
        gemm_bf(lnh, lnl, whi + W_FC1 + o4, wlo + W_FC1 + o4,
                fc1_b + (size_t)l * 4 * CD, nullptr, f1h, f1l,
                RX, 4 * CD, CD, 1);
        gemm_bf(f1h, f1l, whi + W_FC2 + o4, wlo + W_FC2 + o4,
                fc2_b + (size_t)l * CD, nullptr, nullptr, nullptr,
                RX, CD, 4 * CD, 4);                   // residual add into xb
    }

    // ---- final norm (cls rows only) + head ----
    ln_cls_kernel<<<BATCH, 256>>>(norm_w, norm_b);
    head_kernel<<<cdiv(BATCH * 1000, 8), 256>>>(head_w, head_b, (float*)d_out);
}

// round 12
// speedup vs baseline: 1.7297x; 1.0888x over previous
#include <cuda_runtime.h>
#include <cuda_bf16.h>
#include <math.h>
#include <stdint.h>

// ---------------------------------------------------------------------------
// TimeSformer forward. B=2, T=8, N=196, C=768, H=12, hd=64, depth=12.
// GEMMs: bf16x3 tensor-core (hi/lo split), 128x128 CTA, 64x32 warp tiles.
// tproj*tfc pre-merged into one weight; space attention fully fused.
// ---------------------------------------------------------------------------

constexpr int BATCH = 2;
constexpr int TT    = 8;
constexpr int NP    = 196;
constexpr int CD    = 768;
constexpr int NH    = 12;
constexpr int HD    = 64;
constexpr int SEQ   = 1 + TT * NP;          // 1569
constexpr int RT    = BATCH * TT * NP;      // 3136
constexpr int KS    = NP + 1;               // 197
constexpr int RS    = BATCH * TT * KS;      // 3152
constexpr int RX    = BATCH * SEQ;          // 3138
constexpr int GROUPS= BATCH * TT * NH;      // 192
constexpr int DEPTH = 12;

// -------------------------- scratch (device globals) -----------------------
__device__ float g_xb     [(size_t)BATCH * SEQ * CD];
__device__ float g_buf2   [(size_t)BATCH * CD];          // final-LN cls rows
__device__ float g_buf3   [(size_t)RS * CD];             // patch embed / sproj cls rows
__device__ float g_qkv    [(size_t)RS * 3 * CD];
__device__ float g_wc     [(size_t)DEPTH * CD * CD];     // merged tfc@tproj f32
__device__ float g_bc     [(size_t)DEPTH * CD];          // merged bias
__device__ float g_zero   [CD];                          // zero bias

// hi/lo split activation buffers
__device__ __nv_bfloat16 g_ln_hi[(size_t)RS * CD];
__device__ __nv_bfloat16 g_ln_lo[(size_t)RS * CD];
__device__ __nv_bfloat16 g_at_hi[(size_t)RS * CD];
__device__ __nv_bfloat16 g_at_lo[(size_t)RS * CD];
__device__ __nv_bfloat16 g_f1_hi[(size_t)RX * 4 * CD];   // also tprojT scratch
__device__ __nv_bfloat16 g_f1_lo[(size_t)RX * 4 * CD];
__device__ __nv_bfloat16 g_pa_hi[(size_t)RT * CD];
__device__ __nv_bfloat16 g_pa_lo[(size_t)RT * CD];

// weight split buffers
constexpr size_t SZ_TQKV = (size_t)DEPTH * 3 * CD * CD;
constexpr size_t SZ_CC   = (size_t)DEPTH * CD * CD;
constexpr size_t SZ_FC   = (size_t)DEPTH * 4 * CD * CD;
constexpr size_t W_TQKV  = 0;
constexpr size_t W_TFC   = W_TQKV + SZ_TQKV;             // holds MERGED Wc splits
constexpr size_t W_SQKV  = W_TFC + SZ_CC;
constexpr size_t W_SPROJ = W_SQKV + SZ_TQKV;
constexpr size_t W_FC1   = W_SPROJ + SZ_CC;
constexpr size_t W_FC2   = W_FC1 + SZ_FC;
constexpr size_t W_CONV  = W_FC2 + SZ_FC;
constexpr size_t W_TOTAL = W_CONV + (size_t)CD * CD;

__device__ __nv_bfloat16 g_w_hi[W_TOTAL];
__device__ __nv_bfloat16 g_w_lo[W_TOTAL];

// ------------------------------ split helper --------------------------------
__device__ __forceinline__ void split2(float x, __nv_bfloat16& h, __nv_bfloat16& l)
{
    h = __float2bfloat16(x);
    l = __float2bfloat16(x - __bfloat162float(h));
}

// ------------------------- weight split kernel -------------------------------
__global__ void __launch_bounds__(256) wsplit_kernel(
    const float4* __restrict__ src, __nv_bfloat162* __restrict__ hi,
    __nv_bfloat162* __restrict__ lo, long n4)
{
    long i = blockIdx.x * (long)blockDim.x + threadIdx.x;
    if (i >= n4) return;
    float4 v = src[i];
    __nv_bfloat16 h0,l0,h1,l1,h2,l2,h3,l3;
    split2(v.x, h0, l0); split2(v.y, h1, l1);
    split2(v.z, h2, l2); split2(v.w, h3, l3);
    hi[2*i]   = __halves2bfloat162(h0, h1);
    hi[2*i+1] = __halves2bfloat162(h2, h3);
    lo[2*i]   = __halves2bfloat162(l0, l1);
    lo[2*i+1] = __halves2bfloat162(l2, l3);
}

// transpose + split: out[x][y] = src[y][x], per layer; out to bf16 hi/lo
__global__ void tsplit_kernel(const float* __restrict__ src,
                              __nv_bfloat16* __restrict__ oh,
                              __nv_bfloat16* __restrict__ ol)
{
    __shared__ float t[32][33];
    const int l = blockIdx.z;
    const int x0 = blockIdx.x * 32, y0 = blockIdx.y * 32;
    const float* s = src + (size_t)l * CD * CD;
    for (int a = threadIdx.y; a < 32; a += 8)
        t[a][threadIdx.x] = s[(size_t)(y0 + a) * CD + x0 + threadIdx.x];
    __syncthreads();
    __nv_bfloat16* ohl = oh + (size_t)l * CD * CD;
    __nv_bfloat16* oll = ol + (size_t)l * CD * CD;
    for (int a = threadIdx.y; a < 32; a += 8) {
        float v = t[threadIdx.x][a];
        size_t idx = (size_t)(x0 + a) * CD + y0 + threadIdx.x;
        split2(v, ohl[idx], oll[idx]);
    }
}

// bc[l,i] = sum_k tfc_w[l,i,k] * tproj_b[l,k] + tfc_b[l,i]
__global__ void __launch_bounds__(256) bias_merge_kernel(
    const float* __restrict__ tfcw, const float* __restrict__ tprojb,
    const float* __restrict__ tfcb)
{
    const int warp = threadIdx.x >> 5, lane = threadIdx.x & 31;
    const int o = blockIdx.x * 8 + warp;
    if (o >= DEPTH * CD) return;
    const int l = o / CD, i = o % CD;
    const float* wr = tfcw + ((size_t)l * CD + i) * CD;
    const float* br = tprojb + (size_t)l * CD;
    float s = 0.f;
    for (int k = lane; k < CD; k += 32) s += wr[k] * br[k];
    #pragma unroll
    for (int off = 16; off; off >>= 1) s += __shfl_down_sync(0xffffffffu, s, off);
    if (lane == 0) g_bc[o] = s + tfcb[o];
}

// ------------------------- bf16x3 tensor-core GEMM ---------------------------
// C[m,n] = sum_k A[m,k]*W[n,k] + bias[n].  3 MMA terms: hh + hl + lh.
// modes: 0 f32->C | 1 GELU->bf16 hi/lo | 2 bf16 hi/lo
//        3 time-scatter += xb | 4 += xb (residual) | 5 space-scatter += xb
// sA/sW/sC: per-blockIdx.z element strides (batched mode-0 use only).

__device__ __forceinline__ void cpa16(uint32_t dst, const void* src, int srcsz)
{
    asm volatile("cp.async.ca.shared.global [%0], [%1], 16, %2;"
                 :: "r"(dst), "l"(src), "r"(srcsz));
}
__device__ __forceinline__ void ldmx4(uint32_t& r0, uint32_t& r1,
                                      uint32_t& r2, uint32_t& r3, uint32_t addr)
{
    asm volatile("ldmatrix.sync.aligned.m8n8.x4.shared.b16 {%0,%1,%2,%3}, [%4];"
        : "=r"(r0), "=r"(r1), "=r"(r2), "=r"(r3) : "r"(addr));
}
__device__ __forceinline__ void mma_bf(float* c, const uint32_t* a, const uint32_t* b)
{
    asm volatile("mma.sync.aligned.m16n8k16.row.col.f32.bf16.bf16.f32 "
        "{%0,%1,%2,%3}, {%4,%5,%6,%7}, {%8,%9}, {%0,%1,%2,%3};"
        : "+f"(c[0]), "+f"(c[1]), "+f"(c[2]), "+f"(c[3])
        : "r"(a[0]), "r"(a[1]), "r"(a[2]), "r"(a[3]), "r"(b[0]), "r"(b[1]));
}

// smem: [stage(2)][arr(4: Ah,Al,Wh,Wl)][row(128)][col(40 bf16, 80B stride)]
#define SOFF(s, arr, row, col) (((((s)*4 + (arr))*128 + (row))*40 + (col)))
constexpr int GEMM_SMEM = 2 * 4 * 128 * 40 * 2;   // 81920 bytes

__global__ void __launch_bounds__(256) bf_gemm_kernel(
    const __nv_bfloat16* __restrict__ Ah, const __nv_bfloat16* __restrict__ Al,
    const __nv_bfloat16* __restrict__ Wh, const __nv_bfloat16* __restrict__ Wl,
    const float* __restrict__ bias, float* __restrict__ C,
    __nv_bfloat16* __restrict__ Oh, __nv_bfloat16* __restrict__ Ol,
    int M, int N, int K, int mode, long sA, long sW, long sC)
{
    extern __shared__ __align__(16) __nv_bfloat16 sm[];
    const uint32_t smb = (uint32_t)__cvta_generic_to_shared(sm);

    const long z = blockIdx.z;
    Ah += z * sA; Al += z * sA;
    Wh += z * sW; Wl += z * sW;
    if (C) C += z * sC;

    const int tid  = threadIdx.x;
    const int wid  = tid >> 5;
    const int lane = tid & 31;
    const int wm   = wid >> 2;          // 0..1  (64-row warp tile)
    const int wn   = wid & 3;           // 0..3  (32-col warp tile)
    const int g    = lane >> 2;
    const int q    = lane & 3;
    const int row0 = blockIdx.y * 128;
    const int col0 = blockIdx.x * 128;

    float acc[4][4][4];
    #pragma unroll
    for (int i = 0; i < 4; i++)
        #pragma unroll
        for (int j = 0; j < 4; j++)
            #pragma unroll
            for (int v = 0; v < 4; v++) acc[i][j][v] = 0.f;

    const int lrow = tid >> 1;          // 0..127
    const int c0b  = (tid & 1) * 2;     // 16B-chunk base {0,2}

    const int T = K / 32;

    auto prefetch = [&](int t, int s) {
        const int k0 = t * 32;
        int gr = row0 + lrow;
        int av = (gr < M) ? 16 : 0;
        size_t aoff = (size_t)(gr < M ? gr : 0) * K + k0;
        size_t boff = (size_t)(col0 + lrow) * K + k0;
        #pragma unroll
        for (int c = c0b; c < c0b + 2; c++) {
            cpa16(smb + SOFF(s, 0, lrow, c*8) * 2, Ah + aoff + c*8, av);
            cpa16(smb + SOFF(s, 1, lrow, c*8) * 2, Al + aoff + c*8, av);
            cpa16(smb + SOFF(s, 2, lrow, c*8) * 2, Wh + boff + c*8, 16);
            cpa16(smb + SOFF(s, 3, lrow, c*8) * 2, Wl + boff + c*8, 16);
        }
        asm volatile("cp.async.commit_group;" ::: "memory");
    };

    prefetch(0, 0);

    const int fr = lane & 15;
    for (int t = 0; t < T; t++) {
        const int s = t & 1;
        asm volatile("cp.async.wait_group 0;" ::: "memory");
        __syncthreads();
        if (t + 1 < T) prefetch(t + 1, (t + 1) & 1);

        #pragma unroll
        for (int kh = 0; kh < 32; kh += 16) {
            const int fc = kh + (lane >> 4) * 8;
            uint32_t bh[4][2], bl[4][2];
            #pragma unroll
            for (int pr = 0; pr < 2; pr++) {
                int nr = wn * 32 + pr * 16 + fr;
                uint32_t r0, r1, r2, r3;
                ldmx4(r0, r1, r2, r3, smb + SOFF(s, 2, nr, fc) * 2);
                bh[2*pr][0] = r0; bh[2*pr+1][0] = r1;
                bh[2*pr][1] = r2; bh[2*pr+1][1] = r3;
                ldmx4(r0, r1, r2, r3, smb + SOFF(s, 3, nr, fc) * 2);
                bl[2*pr][0] = r0; bl[2*pr+1][0] = r1;
                bl[2*pr][1] = r2; bl[2*pr+1][1] = r3;
            }
            #pragma unroll
            for (int mt = 0; mt < 4; mt++) {
                int mr = wm * 64 + mt * 16 + fr;
                uint32_t ah[4], al[4];
                ldmx4(ah[0], ah[1], ah[2], ah[3], smb + SOFF(s, 0, mr, fc) * 2);
                ldmx4(al[0], al[1], al[2], al[3], smb + SOFF(s, 1, mr, fc) * 2);
                #pragma unroll
                for (int nt = 0; nt < 4; nt++) {
                    mma_bf(acc[mt][nt], ah, bh[nt]);   // hi*hi
                    mma_bf(acc[mt][nt], ah, bl[nt]);   // hi*lo
                    mma_bf(acc[mt][nt], al, bh[nt]);   // lo*hi
                }
            }
        }
        __syncthreads();
    }

    // ------------------------------ epilogue --------------------------------
    #pragma unroll
    for (int mt = 0; mt < 4; mt++) {
        int r0 = row0 + wm * 64 + mt * 16 + g;
        #pragma unroll
        for (int h = 0; h < 2; h++) {
            int r = r0 + 8 * h;
            if (r >= M) continue;
            size_t xbase = 0; bool is_cls = false;
            if (mode == 3) {
                int tt = r % TT; int bn = r / TT; int n = bn % NP; int b = bn / NP;
                xbase = ((size_t)b * SEQ + 1 + tt * NP + n) * CD;
            } else if (mode == 4) {
                xbase = (size_t)r * CD;
            } else if (mode == 5) {
                int m = r % KS; int bt = r / KS; int tt = bt % TT; int b = bt / TT;
                if (m == 0) { is_cls = true; xbase = (size_t)r * CD; }
                else xbase = ((size_t)b * SEQ + 1 + tt * NP + (m - 1)) * CD;
            }
            #pragma unroll
            for (int nt = 0; nt < 4; nt++) {
                int cc = col0 + wn * 32 + nt * 8 + 2 * q;
                float v0 = acc[mt][nt][2*h]     + bias[cc];
                float v1 = acc[mt][nt][2*h + 1] + bias[cc + 1];
                if (mode == 0) {
                    *(float2*)&C[(size_t)r * N + cc] = make_float2(v0, v1);
                } else if (mode == 1 || mode == 2) {
                    if (mode == 1) { v0 = v0 * normcdff(v0); v1 = v1 * normcdff(v1); }
                    __nv_bfloat16 h0, l0, h1, l1;
                    split2(v0, h0, l0); split2(v1, h1, l1);
                    *(__nv_bfloat162*)&Oh[(size_t)r * N + cc] = __halves2bfloat162(h0, h1);
                    *(__nv_bfloat162*)&Ol[(size_t)r * N + cc] = __halves2bfloat162(l0, l1);
                } else if (mode == 5 && is_cls) {
                    *(float2*)&g_buf3[xbase + cc] = make_float2(v0, v1);
                } else {
                    float2 old = *(float2*)&g_xb[xbase + cc];
                    old.x += v0; old.y += v1;
                    *(float2*)&g_xb[xbase + cc] = old;
                }
            }
        }
    }
}

// ------------------------------ LayerNorm -----------------------------------
__device__ __forceinline__ float blk_sum(float v, float* smr)
{
    const int lane = threadIdx.x & 31, w = threadIdx.x >> 5;
    #pragma unroll
    for (int o = 16; o; o >>= 1) v += __shfl_xor_sync(0xffffffffu, v, o);
    if (lane == 0) smr[w] = v;
    __syncthreads();
    if (threadIdx.x == 0) {
        float t = 0.f;
        #pragma unroll
        for (int i = 0; i < 8; i++) t += smr[i];
        smr[8] = t;
    }
    __syncthreads();
    float t = smr[8];
    __syncthreads();
    return t;
}

// LN with fused gather; output split bf16 hi/lo.
// gm 0: in + r*CD.  gm 1: time gather from g_xb.  gm 2: space gather from g_xb.
__global__ void __launch_bounds__(256) ln_hl_kernel(
    const float* __restrict__ in, const float* __restrict__ w,
    const float* __restrict__ b, __nv_bfloat16* __restrict__ oh,
    __nv_bfloat16* __restrict__ ol, int gm)
{
    __shared__ float smr[9];
    const int r = blockIdx.x;
    const float* x;
    if (gm == 0) {
        x = in + (size_t)r * CD;
    } else if (gm == 1) {
        int t = r % TT; int bn = r / TT; int n = bn % NP; int bb = bn / NP;
        x = in + ((size_t)bb * SEQ + 1 + t * NP + n) * CD;
    } else {
        int m = r % KS; int bt = r / KS; int t = bt % TT; int bb = bt / TT;
        x = in + ((m == 0) ? ((size_t)bb * SEQ) * CD
                           : ((size_t)bb * SEQ + 1 + t * NP + (m - 1)) * CD);
    }
    const int t = threadIdx.x;
    float v0 = x[t], v1 = x[t + 256], v2 = x[t + 512];
    float tot = blk_sum(v0 + v1 + v2, smr);
    float mean = tot * (1.0f / CD);
    float d0 = v0 - mean, d1 = v1 - mean, d2 = v2 - mean;
    float tot2 = blk_sum(d0 * d0 + d1 * d1 + d2 * d2, smr);
    float inv = rsqrtf(tot2 * (1.0f / CD) + 1e-6f);
    size_t base = (size_t)r * CD;
    float o0 = d0 * inv * w[t]       + b[t];
    float o1 = d1 * inv * w[t + 256] + b[t + 256];
    float o2 = d2 * inv * w[t + 512] + b[t + 512];
    split2(o0, oh[base + t],       ol[base + t]);
    split2(o1, oh[base + t + 256], ol[base + t + 256]);
    split2(o2, oh[base + t + 512], ol[base + t + 512]);
}

// final LN on the 2 cls rows only
__global__ void __launch_bounds__(256) ln_cls_kernel(
    const float* __restrict__ w, const float* __restrict__ b)
{
    __shared__ float smr[9];
    const float* x = g_xb + (size_t)blockIdx.x * SEQ * CD;
    const int t = threadIdx.x;
    float v0 = x[t], v1 = x[t + 256], v2 = x[t + 512];
    float tot = blk_sum(v0 + v1 + v2, smr);
    float mean = tot * (1.0f / CD);
    float d0 = v0 - mean, d1 = v1 - mean, d2 = v2 - mean;
    float tot2 = blk_sum(d0 * d0 + d1 * d1 + d2 * d2, smr);
    float inv = rsqrtf(tot2 * (1.0f / CD) + 1e-6f);
    float* o = g_buf2 + (size_t)blockIdx.x * CD;
    o[t]       = d0 * inv * w[t]       + b[t];
    o[t + 256] = d1 * inv * w[t + 256] + b[t + 256];
    o[t + 512] = d2 * inv * w[t + 512] + b[t + 512];
}

// ------------------------- Time attention (seq=8) ---------------------------
__global__ void __launch_bounds__(64) time_attn_kernel()
{
    const int g = blockIdx.x;
    const int h = g % NH;
    const int bn = g / NH;
    const int lane = threadIdx.x;
    __shared__ float Q[TT][HD + 1], Kk[TT][HD + 1], V[TT][HD + 1];
    __shared__ float P[TT][TT + 1];
    #pragma unroll
    for (int t = 0; t < TT; t++) {
        size_t base = ((size_t)(bn * TT + t)) * (3 * CD) + h * HD + lane;
        Q[t][lane]  = g_qkv[base];
        Kk[t][lane] = g_qkv[base + CD];
        V[t][lane]  = g_qkv[base + 2 * CD];
    }
    __syncthreads();
    const int tq = lane >> 3, tk = lane & 7;
    float s = 0.f;
    #pragma unroll
    for (int d = 0; d < HD; d++) s += Q[tq][d] * Kk[tk][d];
    P[tq][tk] = s * 0.125f;
    __syncthreads();
    if (lane < TT) {
        float m = -1e30f;
        #pragma unroll
        for (int k = 0; k < TT; k++) m = fmaxf(m, P[lane][k]);
        float sum = 0.f;
        #pragma unroll
        for (int k = 0; k < TT; k++) { float e = expf(P[lane][k] - m); P[lane][k] = e; sum += e; }
        float inv = 1.f / sum;
        #pragma unroll
        for (int k = 0; k < TT; k++) P[lane][k] *= inv;
    }
    __syncthreads();
    #pragma unroll
    for (int t = 0; t < TT; t++) {
        float a = 0.f;
        #pragma unroll
        for (int k = 0; k < TT; k++) a += P[t][k] * V[k][lane];
        size_t idx = ((size_t)(bn * TT + t)) * CD + h * HD + lane;
        split2(a, g_at_hi[idx], g_at_lo[idx]);
    }
}

// ------------------- Fused space attention (seq=197) ------------------------
// One block per (group, q-tile of 32). Scores kept in SMEM through softmax.
constexpr int SA_SMEM = (96 * (HD + 1) + 32 * 256) * 4;   // 57728 bytes

__global__ void __launch_bounds__(256) space_attn_kernel()
{
    extern __shared__ float sa[];
    float (*Qs)[HD + 1]  = (float(*)[HD + 1])sa;
    float (*KVs)[HD + 1] = (float(*)[HD + 1])(sa + 32 * (HD + 1));
    float (*Ss)[256]     = (float(*)[256])(sa + 96 * (HD + 1));

    const int g = blockIdx.x;          // bt*NH + h
    const int h = g % NH, bt = g / NH;
    const int q0 = blockIdx.y * 32;
    const int tid = threadIdx.x;
    const int kc = tid & 63, qb = tid >> 6;

    // load Q tile
    for (int i = tid; i < 32 * 64; i += 256) {
        int r = i >> 6, d = i & 63; int gq = q0 + r;
        Qs[r][d] = (gq < KS)
            ? g_qkv[((size_t)(bt * KS + gq)) * (3 * CD) + h * HD + d] : 0.f;
    }

    // scores: loop K tiles of 64
    for (int kt = 0; kt < 4; kt++) {
        const int k0 = kt * 64;
        __syncthreads();
        for (int i = tid; i < 64 * 64; i += 256) {
            int r = i >> 6, d = i & 63; int gk = k0 + r;
            KVs[r][d] = (gk < KS)
                ? g_qkv[((size_t)(bt * KS + gk)) * (3 * CD) + CD + h * HD + d] : 0.f;
        }
        __syncthreads();
        float s[8];
        #pragma unroll
        for (int i = 0; i < 8; i++) s[i] = 0.f;
        #pragma unroll
        for (int d = 0; d < HD; d++) {
            float kv = KVs[kc][d];
            #pragma unroll
            for (int i = 0; i < 8; i++) s[i] = fmaf(Qs[qb + 4 * i][d], kv, s[i]);
        }
        #pragma unroll
        for (int i = 0; i < 8; i++) Ss[qb + 4 * i][k0 + kc] = s[i] * 0.125f;
    }
    __syncthreads();

    // softmax: warp w handles rows 4w..4w+3
    {
        const int lane = tid & 31;
        const int rbase = (tid >> 5) * 4;
        for (int rr = 0; rr < 4; rr++) {
            const int r = rbase + rr;
            float vals[7];
            float m = -1e30f;
            #pragma unroll
            for (int i = 0; i < 7; i++) {
                int j = lane + 32 * i;
                vals[i] = (j < KS) ? Ss[r][j] : -1e30f;
                m = fmaxf(m, vals[i]);
            }
            #pragma unroll
            for (int o = 16; o; o >>= 1) m = fmaxf(m, __shfl_xor_sync(0xffffffffu, m, o));
            float sum = 0.f;
            #pragma unroll
            for (int i = 0; i < 7; i++) {
                int j = lane + 32 * i;
                if (j < KS) { vals[i] = expf(vals[i] - m); sum += vals[i]; }
            }
            #pragma unroll
            for (int o = 16; o; o >>= 1) sum += __shfl_xor_sync(0xffffffffu, sum, o);
            float inv = 1.f / sum;
            #pragma unroll
            for (int i = 0; i < 7; i++) {
                int j = lane + 32 * i;
                if (j < KS) Ss[r][j] = vals[i] * inv;
            }
        }
    }
    __syncthreads();

    // P @ V: loop V tiles of 64 (V rows >=KS are zero, so stale S cols are harmless)
    float acc[8];
    #pragma unroll
    for (int i = 0; i < 8; i++) acc[i] = 0.f;
    for (int kt = 0; kt < 4; kt++) {
        const int k0 = kt * 64;
        for (int i = tid; i < 64 * 64; i += 256) {
            int r = i >> 6, d = i & 63; int gk = k0 + r;
            KVs[r][d] = (gk < KS)
                ? g_qkv[((size_t)(bt * KS + gk)) * (3 * CD) + 2 * CD + h * HD + d] : 0.f;
        }
        __syncthreads();
        #pragma unroll
        for (int kk = 0; kk < 64; kk++) {
            float vv = KVs[kk][kc];
            #pragma unroll
            for (int i = 0; i < 8; i++) acc[i] = fmaf(Ss[qb + 4 * i][k0 + kk], vv, acc[i]);
        }
        __syncthreads();
    }

    #pragma unroll
    for (int i = 0; i < 8; i++) {
        int gq = q0 + qb + 4 * i;
        if (gq < KS) {
            size_t idx = ((size_t)(bt * KS + gq)) * CD + h * HD + kc;
            split2(acc[i], g_at_hi[idx], g_at_lo[idx]);
        }
    }
}

// --------------------------- elementwise helpers ----------------------------
__global__ void patchify_kernel(const float* __restrict__ x)
{
    int i = blockIdx.x * blockDim.x + threadIdx.x;
    if (i >= RT * CD) return;
    int k = i % CD; int r = i / CD;
    int n = r % NP; int bt = r / NP; int t = bt % TT; int b = bt / TT;
    int ci = k >> 8; int rem = k & 255; int py = rem >> 4; int px = rem & 15;
    int nh = n / 14, nw = n % 14;
    size_t src = ((((size_t)b * 3 + ci) * TT + t) * 224 + (nh * 16 + py)) * 224 + (nw * 16 + px);
    split2(x[src], g_pa_hi[i], g_pa_lo[i]);
}

__global__ void init_cls_kernel(const float* __restrict__ cls_token,
                                const float* __restrict__ pos_embed)
{
    int i = blockIdx.x * blockDim.x + threadIdx.x;
    if (i >= BATCH * CD) return;
    int b = i / CD, c = i % CD;
    g_xb[((size_t)b * SEQ) * CD + c] = cls_token[c] + pos_embed[c];
}

__global__ void init_patch_kernel(const float* __restrict__ pos_embed,
                                  const float* __restrict__ time_embed)
{
    int i = blockIdx.x * blockDim.x + threadIdx.x;
    if (i >= RT * CD) return;
    int c = i % CD; int r = i / CD;
    int n = r % NP; int bt = r / NP; int t = bt % TT; int b = bt / TT;
    g_xb[((size_t)b * SEQ + 1 + t * NP + n) * CD + c] =
        g_buf3[i] + pos_embed[(size_t)(1 + n) * CD + c] + time_embed[(size_t)t * CD + c];
}

__global__ void combine_cls_kernel()
{
    int i = blockIdx.x * blockDim.x + threadIdx.x;
    if (i >= BATCH * CD) return;
    int b = i / CD, c = i % CD;
    float s = 0.f;
    #pragma unroll
    for (int t = 0; t < TT; t++)
        s += g_buf3[((size_t)((b * TT + t) * KS)) * CD + c];
    g_xb[((size_t)b * SEQ) * CD + c] += s * (1.f / TT);
}

// ------------------------------- head ---------------------------------------
__global__ void __launch_bounds__(256) head_kernel(
    const float* __restrict__ hw, const float* __restrict__ hb,
    float* __restrict__ out)
{
    const int warp = threadIdx.x >> 5, lane = threadIdx.x & 31;
    const int o = blockIdx.x * 8 + warp;
    if (o >= BATCH * 1000) return;
    const int b = o / 1000, j = o % 1000;
    const float* xr = g_buf2 + (size_t)b * CD;
    const float* wr = hw + (size_t)j * CD;
    float s = 0.f;
    for (int k = lane; k < CD; k += 32) s += xr[k] * wr[k];
    #pragma unroll
    for (int off = 16; off; off >>= 1) s += __shfl_down_sync(0xffffffffu, s, off);
    if (lane == 0) out[o] = s + hb[j];
}

// ------------------------------ launcher ------------------------------------
static inline int cdiv(int a, int b) { return (a + b - 1) / b; }

static void gemm_bf(const __nv_bfloat16* Ah, const __nv_bfloat16* Al,
                    const __nv_bfloat16* Wh, const __nv_bfloat16* Wl,
                    const float* bias, float* C,
                    __nv_bfloat16* Oh, __nv_bfloat16* Ol,
                    int M, int N, int K, int mode)
{
    dim3 gr(N / 128, cdiv(M, 128));
    bf_gemm_kernel<<<gr, 256, GEMM_SMEM>>>(Ah, Al, Wh, Wl, bias, C, Oh, Ol,
                                           M, N, K, mode, 0, 0, 0);
}

static void wsplit(const float* src, __nv_bfloat16* hi, __nv_bfloat16* lo, size_t n)
{
    long n4 = (long)(n / 4);
    wsplit_kernel<<<(int)((n4 + 255) / 256), 256>>>(
        (const float4*)src, (__nv_bfloat162*)hi, (__nv_bfloat162*)lo, n4);
}

extern "C" void kernel_launch(void* const* d_in, const int* in_sizes, int n_in,
                              void* d_out, int out_size)
{
    const float* x          = (const float*)d_in[0];
    const float* conv_w     = (const float*)d_in[1];
    const float* conv_b     = (const float*)d_in[2];
    const float* cls_token  = (const float*)d_in[3];
    const float* pos_embed  = (const float*)d_in[4];
    const float* time_embed = (const float*)d_in[5];
    const float* tn_w   = (const float*)d_in[6];
    const float* tn_b   = (const float*)d_in[7];
    const float* tqkv_w = (const float*)d_in[8];
    const float* tqkv_b = (const float*)d_in[9];
    const float* tproj_w= (const float*)d_in[10];
    const float* tproj_b= (const float*)d_in[11];
    const float* tfc_w  = (const float*)d_in[12];
    const float* tfc_b  = (const float*)d_in[13];
    const float* n1_w   = (const float*)d_in[14];
    const float* n1_b   = (const float*)d_in[15];
    const float* sqkv_w = (const float*)d_in[16];
    const float* sqkv_b = (const float*)d_in[17];
    const float* sproj_w= (const float*)d_in[18];
    const float* sproj_b= (const float*)d_in[19];
    const float* n2_w   = (const float*)d_in[20];
    const float* n2_b   = (const float*)d_in[21];
    const float* fc1_w  = (const float*)d_in[22];
    const float* fc1_b  = (const float*)d_in[23];
    const float* fc2_w  = (const float*)d_in[24];
    const float* fc2_b  = (const float*)d_in[25];
    const float* norm_w = (const float*)d_in[26];
    const float* norm_b = (const float*)d_in[27];
    const float* head_w = (const float*)d_in[28];
    const float* head_b = (const float*)d_in[29];

    float *xb, *buf3, *qkv, *wc, *bc, *zero;
    cudaGetSymbolAddress((void**)&xb,   g_xb);
    cudaGetSymbolAddress((void**)&buf3, g_buf3);
    cudaGetSymbolAddress((void**)&qkv,  g_qkv);
    cudaGetSymbolAddress((void**)&wc,   g_wc);
    cudaGetSymbolAddress((void**)&bc,   g_bc);
    cudaGetSymbolAddress((void**)&zero, g_zero);

    __nv_bfloat16 *whi, *wlo, *lnh, *lnl, *ath, *atl, *f1h, *f1l, *pah, *pal;
    cudaGetSymbolAddress((void**)&whi, g_w_hi);
    cudaGetSymbolAddress((void**)&wlo, g_w_lo);
    cudaGetSymbolAddress((void**)&lnh, g_ln_hi);
    cudaGetSymbolAddress((void**)&lnl, g_ln_lo);
    cudaGetSymbolAddress((void**)&ath, g_at_hi);
    cudaGetSymbolAddress((void**)&atl, g_at_lo);
    cudaGetSymbolAddress((void**)&f1h, g_f1_hi);
    cudaGetSymbolAddress((void**)&f1l, g_f1_lo);
    cudaGetSymbolAddress((void**)&pah, g_pa_hi);
    cudaGetSymbolAddress((void**)&pal, g_pa_lo);

    cudaFuncSetAttribute(bf_gemm_kernel,
                         cudaFuncAttributeMaxDynamicSharedMemorySize, GEMM_SMEM);
    cudaFuncSetAttribute(space_attn_kernel,
                         cudaFuncAttributeMaxDynamicSharedMemorySize, SA_SMEM);

    const int EB = 256;

    // ---- split weights into bf16 hi/lo ----
    wsplit(tqkv_w,  whi + W_TQKV,  wlo + W_TQKV,  SZ_TQKV);
    wsplit(tfc_w,   whi + W_TFC,   wlo + W_TFC,   SZ_CC);
    wsplit(sqkv_w,  whi + W_SQKV,  wlo + W_SQKV,  SZ_TQKV);
    wsplit(sproj_w, whi + W_SPROJ, wlo + W_SPROJ, SZ_CC);
    wsplit(fc1_w,   whi + W_FC1,   wlo + W_FC1,   SZ_FC);
    wsplit(fc2_w,   whi + W_FC2,   wlo + W_FC2,   SZ_FC);
    wsplit(conv_w,  whi + W_CONV,  wlo + W_CONV,  (size_t)CD * CD);

    // ---- merge tproj into tfc: Wc = tfc_w @ tproj_w, bc = tfc_w@tproj_b + tfc_b
    {
        dim3 tb(32, 8);
        dim3 tg(CD / 32, CD / 32, DEPTH);
        tsplit_kernel<<<tg, tb>>>(tproj_w, f1h, f1l);     // tproj^T splits
        dim3 gw(CD / 128, CD / 128, DEPTH);
        bf_gemm_kernel<<<gw, 256, GEMM_SMEM>>>(
            whi + W_TFC, wlo + W_TFC, f1h, f1l, zero, wc, nullptr, nullptr,
            CD, CD, CD, 0, (long)CD * CD, (long)CD * CD, (long)CD * CD);
        bias_merge_kernel<<<cdiv(DEPTH * CD, 8), 256>>>(tfc_w, tproj_b, tfc_b);
        wsplit(wc, whi + W_TFC, wlo + W_TFC, SZ_CC);      // overwrite with merged
    }

    // ---- patch embedding + pos/time embed + cls init ----
    patchify_kernel<<<cdiv(RT * CD, EB), EB>>>(x);
    gemm_bf(pah, pal, whi + W_CONV, wlo + W_CONV, conv_b, buf3, nullptr, nullptr,
            RT, CD, CD, 0);
    init_cls_kernel<<<cdiv(BATCH * CD, EB), EB>>>(cls_token, pos_embed);
    init_patch_kernel<<<cdiv(RT * CD, EB), EB>>>(pos_embed, time_embed);

    // ---- transformer blocks ----
    for (int l = 0; l < DEPTH; l++) {
        size_t o3 = (size_t)l * 3 * CD * CD;
        size_t o1 = (size_t)l * CD * CD;
        size_t o4 = (size_t)l * 4 * CD * CD;

        // ===== time attention =====
        ln_hl_kernel<<<RT, 256>>>(xb, tn_w + (size_t)l * CD, tn_b + (size_t)l * CD,
                                  lnh, lnl, 1);
        gemm_bf(lnh, lnl, whi + W_TQKV + o3, wlo + W_TQKV + o3,
                tqkv_b + (size_t)l * 3 * CD, qkv, nullptr, nullptr,
                RT, 3 * CD, CD, 0);
        time_attn_kernel<<<(RT / TT) * NH, 64>>>();
        gemm_bf(ath, atl, whi + W_TFC + o1, wlo + W_TFC + o1,
                bc + (size_t)l * CD, nullptr, nullptr, nullptr,
                RT, CD, CD, 3);                       // merged proj+fc, scatter-add

        // ===== space attention =====
        ln_hl_kernel<<<RS, 256>>>(xb, n1_w + (size_t)l * CD, n1_b + (size_t)l * CD,
                                  lnh, lnl, 2);
        gemm_bf(lnh, lnl, whi + W_SQKV + o3, wlo + W_SQKV + o3,
                sqkv_b + (size_t)l * 3 * CD, qkv, nullptr, nullptr,
                RS, 3 * CD, CD, 0);
        {
            dim3 gr(GROUPS, cdiv(KS, 32));
            space_attn_kernel<<<gr, 256, SA_SMEM>>>();
        }
        gemm_bf(ath, atl, whi + W_SPROJ + o1, wlo + W_SPROJ + o1,
                sproj_b + (size_t)l * CD, nullptr, nullptr, nullptr,
                RS, CD, CD, 5);                       // scatter-add + cls->buf3
        combine_cls_kernel<<<cdiv(BATCH * CD, EB), EB>>>();

        // ===== MLP =====
        ln_hl_kernel<<<RX, 256>>>(xb, n2_w + (size_t)l * CD, n2_b + (size_t)l * CD,
                                  lnh, lnl, 0);
        gemm_bf(lnh, lnl, whi + W_FC1 + o4, wlo + W_FC1 + o4,
                fc1_b + (size_t)l * 4 * CD, nullptr, f1h, f1l,
                RX, 4 * CD, CD, 1);
        gemm_bf(f1h, f1l, whi + W_FC2 + o4, wlo + W_FC2 + o4,
                fc2_b + (size_t)l * CD, nullptr, nullptr, nullptr,
                RX, CD, 4 * CD, 4);                   // residual add into xb
    }

    // ---- final norm (cls rows only) + head ----
    ln_cls_kernel<<<BATCH, 256>>>(norm_w, norm_b);
    head_kernel<<<cdiv(BATCH * 1000, 8), 256>>>(head_w, head_b, (float*)d_out);
}

// round 13
// speedup vs baseline: 1.7350x; 1.0031x over previous
#include <cuda_runtime.h>
#include <cuda_bf16.h>
#include <math.h>
#include <stdint.h>

// ---------------------------------------------------------------------------
// TimeSformer forward. B=2, T=8, N=196, C=768, H=12, hd=64, depth=12.
// GEMMs: bf16x3 tensor-core (hi/lo split). 128x128 CTA for wide-N,
// 64x128 CTA (3-stage) for N=768 GEMMs. tproj*tfc merged; space attn fused.
// ---------------------------------------------------------------------------

constexpr int BATCH = 2;
constexpr int TT    = 8;
constexpr int NP    = 196;
constexpr int CD    = 768;
constexpr int NH    = 12;
constexpr int HD    = 64;
constexpr int SEQ   = 1 + TT * NP;          // 1569
constexpr int RT    = BATCH * TT * NP;      // 3136
constexpr int KS    = NP + 1;               // 197
constexpr int RS    = BATCH * TT * KS;      // 3152
constexpr int RX    = BATCH * SEQ;          // 3138
constexpr int GROUPS= BATCH * TT * NH;      // 192
constexpr int DEPTH = 12;

// -------------------------- scratch (device globals) -----------------------
__device__ float g_xb     [(size_t)BATCH * SEQ * CD];
__device__ float g_buf2   [(size_t)BATCH * CD];
__device__ float g_buf3   [(size_t)RS * CD];
__device__ float g_qkv    [(size_t)RS * 3 * CD];
__device__ float g_wc     [(size_t)DEPTH * CD * CD];
__device__ float g_bc     [(size_t)DEPTH * CD];
__device__ float g_zero   [CD];

__device__ __nv_bfloat16 g_ln_hi[(size_t)RS * CD];
__device__ __nv_bfloat16 g_ln_lo[(size_t)RS * CD];
__device__ __nv_bfloat16 g_at_hi[(size_t)RS * CD];
__device__ __nv_bfloat16 g_at_lo[(size_t)RS * CD];
__device__ __nv_bfloat16 g_f1_hi[(size_t)RX * 4 * CD];
__device__ __nv_bfloat16 g_f1_lo[(size_t)RX * 4 * CD];
__device__ __nv_bfloat16 g_pa_hi[(size_t)RT * CD];
__device__ __nv_bfloat16 g_pa_lo[(size_t)RT * CD];

constexpr size_t SZ_TQKV = (size_t)DEPTH * 3 * CD * CD;
constexpr size_t SZ_CC   = (size_t)DEPTH * CD * CD;
constexpr size_t SZ_FC   = (size_t)DEPTH * 4 * CD * CD;
constexpr size_t W_TQKV  = 0;
constexpr size_t W_TFC   = W_TQKV + SZ_TQKV;
constexpr size_t W_SQKV  = W_TFC + SZ_CC;
constexpr size_t W_SPROJ = W_SQKV + SZ_TQKV;
constexpr size_t W_FC1   = W_SPROJ + SZ_CC;
constexpr size_t W_FC2   = W_FC1 + SZ_FC;
constexpr size_t W_CONV  = W_FC2 + SZ_FC;
constexpr size_t W_TOTAL = W_CONV + (size_t)CD * CD;

__device__ __nv_bfloat16 g_w_hi[W_TOTAL];
__device__ __nv_bfloat16 g_w_lo[W_TOTAL];

// ------------------------------ split helper --------------------------------
__device__ __forceinline__ void split2(float x, __nv_bfloat16& h, __nv_bfloat16& l)
{
    h = __float2bfloat16(x);
    l = __float2bfloat16(x - __bfloat162float(h));
}

// ------------------------- weight split kernels ------------------------------
__global__ void __launch_bounds__(256) wsplit_kernel(
    const float4* __restrict__ src, __nv_bfloat162* __restrict__ hi,
    __nv_bfloat162* __restrict__ lo, long n4)
{
    long i = blockIdx.x * (long)blockDim.x + threadIdx.x;
    if (i >= n4) return;
    float4 v = src[i];
    __nv_bfloat16 h0,l0,h1,l1,h2,l2,h3,l3;
    split2(v.x, h0, l0); split2(v.y, h1, l1);
    split2(v.z, h2, l2); split2(v.w, h3, l3);
    hi[2*i]   = __halves2bfloat162(h0, h1);
    hi[2*i+1] = __halves2bfloat162(h2, h3);
    lo[2*i]   = __halves2bfloat162(l0, l1);
    lo[2*i+1] = __halves2bfloat162(l2, l3);
}

__global__ void tsplit_kernel(const float* __restrict__ src,
                              __nv_bfloat16* __restrict__ oh,
                              __nv_bfloat16* __restrict__ ol)
{
    __shared__ float t[32][33];
    const int l = blockIdx.z;
    const int x0 = blockIdx.x * 32, y0 = blockIdx.y * 32;
    const float* s = src + (size_t)l * CD * CD;
    for (int a = threadIdx.y; a < 32; a += 8)
        t[a][threadIdx.x] = s[(size_t)(y0 + a) * CD + x0 + threadIdx.x];
    __syncthreads();
    __nv_bfloat16* ohl = oh + (size_t)l * CD * CD;
    __nv_bfloat16* oll = ol + (size_t)l * CD * CD;
    for (int a = threadIdx.y; a < 32; a += 8) {
        float v = t[threadIdx.x][a];
        size_t idx = (size_t)(x0 + a) * CD + y0 + threadIdx.x;
        split2(v, ohl[idx], oll[idx]);
    }
}

__global__ void __launch_bounds__(256) bias_merge_kernel(
    const float* __restrict__ tfcw, const float* __restrict__ tprojb,
    const float* __restrict__ tfcb)
{
    const int warp = threadIdx.x >> 5, lane = threadIdx.x & 31;
    const int o = blockIdx.x * 8 + warp;
    if (o >= DEPTH * CD) return;
    const int l = o / CD, i = o % CD;
    const float* wr = tfcw + ((size_t)l * CD + i) * CD;
    const float* br = tprojb + (size_t)l * CD;
    float s = 0.f;
    for (int k = lane; k < CD; k += 32) s += wr[k] * br[k];
    #pragma unroll
    for (int off = 16; off; off >>= 1) s += __shfl_down_sync(0xffffffffu, s, off);
    if (lane == 0) g_bc[o] = s + tfcb[o];
}

// ------------------------- GEMM common pieces --------------------------------
__device__ __forceinline__ void cpa16(uint32_t dst, const void* src, int srcsz)
{
    asm volatile("cp.async.ca.shared.global [%0], [%1], 16, %2;"
                 :: "r"(dst), "l"(src), "r"(srcsz));
}
__device__ __forceinline__ void ldmx4(uint32_t& r0, uint32_t& r1,
                                      uint32_t& r2, uint32_t& r3, uint32_t addr)
{
    asm volatile("ldmatrix.sync.aligned.m8n8.x4.shared.b16 {%0,%1,%2,%3}, [%4];"
        : "=r"(r0), "=r"(r1), "=r"(r2), "=r"(r3) : "r"(addr));
}
__device__ __forceinline__ void mma_bf(float* c, const uint32_t* a, const uint32_t* b)
{
    asm volatile("mma.sync.aligned.m16n8k16.row.col.f32.bf16.bf16.f32 "
        "{%0,%1,%2,%3}, {%4,%5,%6,%7}, {%8,%9}, {%0,%1,%2,%3};"
        : "+f"(c[0]), "+f"(c[1]), "+f"(c[2]), "+f"(c[3])
        : "r"(a[0]), "r"(a[1]), "r"(a[2]), "r"(a[3]), "r"(b[0]), "r"(b[1]));
}

// epilogue shared by both GEMMs: handles one (r, cc) float2
// modes: 0 f32->C | 1 GELU->bf16 hi/lo | 2 bf16 hi/lo
//        3 time-scatter += xb | 4 += xb | 5 space-scatter += xb (cls->buf3)
__device__ __forceinline__ void gemm_epilogue_pair(
    int r, int cc, int N, float v0, float v1, int mode,
    float* C, __nv_bfloat16* Oh, __nv_bfloat16* Ol)
{
    if (mode == 0) {
        *(float2*)&C[(size_t)r * N + cc] = make_float2(v0, v1);
    } else if (mode == 1 || mode == 2) {
        if (mode == 1) { v0 = v0 * normcdff(v0); v1 = v1 * normcdff(v1); }
        __nv_bfloat16 h0, l0, h1, l1;
        split2(v0, h0, l0); split2(v1, h1, l1);
        *(__nv_bfloat162*)&Oh[(size_t)r * N + cc] = __halves2bfloat162(h0, h1);
        *(__nv_bfloat162*)&Ol[(size_t)r * N + cc] = __halves2bfloat162(l0, l1);
    } else {
        size_t xbase; bool is_cls = false;
        if (mode == 3) {
            int tt = r % TT; int bn = r / TT; int n = bn % NP; int b = bn / NP;
            xbase = ((size_t)b * SEQ + 1 + tt * NP + n) * CD;
        } else if (mode == 4) {
            xbase = (size_t)r * CD;
        } else {
            int m = r % KS; int bt = r / KS; int tt = bt % TT; int b = bt / TT;
            if (m == 0) { is_cls = true; xbase = (size_t)r * CD; }
            else xbase = ((size_t)b * SEQ + 1 + tt * NP + (m - 1)) * CD;
        }
        if (is_cls) {
            *(float2*)&g_buf3[xbase + cc] = make_float2(v0, v1);
        } else {
            float2 old = *(float2*)&g_xb[xbase + cc];
            old.x += v0; old.y += v1;
            *(float2*)&g_xb[xbase + cc] = old;
        }
    }
}

// ---------------------- bf16x3 GEMM, 128x128 CTA -----------------------------
#define SOFF(s, arr, row, col) (((((s)*4 + (arr))*128 + (row))*40 + (col)))
constexpr int GEMM_SMEM = 2 * 4 * 128 * 40 * 2;   // 81920 bytes

__global__ void __launch_bounds__(256) bf_gemm_kernel(
    const __nv_bfloat16* __restrict__ Ah, const __nv_bfloat16* __restrict__ Al,
    const __nv_bfloat16* __restrict__ Wh, const __nv_bfloat16* __restrict__ Wl,
    const float* __restrict__ bias, float* __restrict__ C,
    __nv_bfloat16* __restrict__ Oh, __nv_bfloat16* __restrict__ Ol,
    int M, int N, int K, int mode, long sA, long sW, long sC)
{
    extern __shared__ __align__(16) __nv_bfloat16 sm[];
    const uint32_t smb = (uint32_t)__cvta_generic_to_shared(sm);

    const long z = blockIdx.z;
    Ah += z * sA; Al += z * sA;
    Wh += z * sW; Wl += z * sW;
    if (C) C += z * sC;

    int bx = blockIdx.x, by = blockIdx.y;
    if (by & 1) bx = gridDim.x - 1 - bx;       // serpentine for L2 reuse

    const int tid  = threadIdx.x;
    const int wid  = tid >> 5;
    const int lane = tid & 31;
    const int wm   = wid >> 2;
    const int wn   = wid & 3;
    const int g    = lane >> 2;
    const int q    = lane & 3;
    const int row0 = by * 128;
    const int col0 = bx * 128;

    float acc[4][4][4];
    #pragma unroll
    for (int i = 0; i < 4; i++)
        #pragma unroll
        for (int j = 0; j < 4; j++)
            #pragma unroll
            for (int v = 0; v < 4; v++) acc[i][j][v] = 0.f;

    const int lrow = tid >> 1;
    const int c0b  = (tid & 1) * 2;
    const int T = K / 32;

    auto prefetch = [&](int t, int s) {
        const int k0 = t * 32;
        int gr = row0 + lrow;
        int av = (gr < M) ? 16 : 0;
        size_t aoff = (size_t)(gr < M ? gr : 0) * K + k0;
        size_t boff = (size_t)(col0 + lrow) * K + k0;
        #pragma unroll
        for (int c = c0b; c < c0b + 2; c++) {
            cpa16(smb + SOFF(s, 0, lrow, c*8) * 2, Ah + aoff + c*8, av);
            cpa16(smb + SOFF(s, 1, lrow, c*8) * 2, Al + aoff + c*8, av);
            cpa16(smb + SOFF(s, 2, lrow, c*8) * 2, Wh + boff + c*8, 16);
            cpa16(smb + SOFF(s, 3, lrow, c*8) * 2, Wl + boff + c*8, 16);
        }
        asm volatile("cp.async.commit_group;" ::: "memory");
    };

    prefetch(0, 0);

    const int fr = lane & 15;
    for (int t = 0; t < T; t++) {
        const int s = t & 1;
        asm volatile("cp.async.wait_group 0;" ::: "memory");
        __syncthreads();
        if (t + 1 < T) prefetch(t + 1, (t + 1) & 1);

        #pragma unroll
        for (int kh = 0; kh < 32; kh += 16) {
            const int fc = kh + (lane >> 4) * 8;
            uint32_t bh[4][2], bl[4][2];
            #pragma unroll
            for (int pr = 0; pr < 2; pr++) {
                int nr = wn * 32 + pr * 16 + fr;
                uint32_t r0, r1, r2, r3;
                ldmx4(r0, r1, r2, r3, smb + SOFF(s, 2, nr, fc) * 2);
                bh[2*pr][0] = r0; bh[2*pr+1][0] = r1;
                bh[2*pr][1] = r2; bh[2*pr+1][1] = r3;
                ldmx4(r0, r1, r2, r3, smb + SOFF(s, 3, nr, fc) * 2);
                bl[2*pr][0] = r0; bl[2*pr+1][0] = r1;
                bl[2*pr][1] = r2; bl[2*pr+1][1] = r3;
            }
            #pragma unroll
            for (int mt = 0; mt < 4; mt++) {
                int mr = wm * 64 + mt * 16 + fr;
                uint32_t ah[4], al[4];
                ldmx4(ah[0], ah[1], ah[2], ah[3], smb + SOFF(s, 0, mr, fc) * 2);
                ldmx4(al[0], al[1], al[2], al[3], smb + SOFF(s, 1, mr, fc) * 2);
                #pragma unroll
                for (int nt = 0; nt < 4; nt++) {
                    mma_bf(acc[mt][nt], ah, bh[nt]);
                    mma_bf(acc[mt][nt], ah, bl[nt]);
                    mma_bf(acc[mt][nt], al, bh[nt]);
                }
            }
        }
        __syncthreads();
    }

    #pragma unroll
    for (int mt = 0; mt < 4; mt++) {
        int r0 = row0 + wm * 64 + mt * 16 + g;
        #pragma unroll
        for (int h = 0; h < 2; h++) {
            int r = r0 + 8 * h;
            if (r >= M) continue;
            #pragma unroll
            for (int nt = 0; nt < 4; nt++) {
                int cc = col0 + wn * 32 + nt * 8 + 2 * q;
                float v0 = acc[mt][nt][2*h]     + bias[cc];
                float v1 = acc[mt][nt][2*h + 1] + bias[cc + 1];
                gemm_epilogue_pair(r, cc, N, v0, v1, mode, C, Oh, Ol);
            }
        }
    }
}

// ---------------------- bf16x3 GEMM, 64x128 CTA, 3-stage ---------------------
constexpr int ST64 = 2*64*40 + 2*128*40;          // 15360 elems per stage
constexpr int GEMM64_SMEM = 3 * ST64 * 2;         // 92160 bytes
#define O64A(s, arr, row, col) ((s)*ST64 + (arr)*64*40 + (row)*40 + (col))
#define O64W(s, arr, row, col) ((s)*ST64 + 2*64*40 + (arr)*128*40 + (row)*40 + (col))

__global__ void __launch_bounds__(256) bf_gemm64_kernel(
    const __nv_bfloat16* __restrict__ Ah, const __nv_bfloat16* __restrict__ Al,
    const __nv_bfloat16* __restrict__ Wh, const __nv_bfloat16* __restrict__ Wl,
    const float* __restrict__ bias, float* __restrict__ C,
    __nv_bfloat16* __restrict__ Oh, __nv_bfloat16* __restrict__ Ol,
    int M, int N, int K, int mode)
{
    extern __shared__ __align__(16) __nv_bfloat16 sm[];
    const uint32_t smb = (uint32_t)__cvta_generic_to_shared(sm);

    int bx = blockIdx.x, by = blockIdx.y;
    if (by & 1) bx = gridDim.x - 1 - bx;

    const int tid  = threadIdx.x;
    const int wid  = tid >> 5;
    const int lane = tid & 31;
    const int wm   = wid >> 2;          // 0..1 (32-row warp tile)
    const int wn   = wid & 3;           // 0..3 (32-col warp tile)
    const int g    = lane >> 2;
    const int q    = lane & 3;
    const int row0 = by * 64;
    const int col0 = bx * 128;

    float acc[2][4][4];
    #pragma unroll
    for (int i = 0; i < 2; i++)
        #pragma unroll
        for (int j = 0; j < 4; j++)
            #pragma unroll
            for (int v = 0; v < 4; v++) acc[i][j][v] = 0.f;

    const int T = K / 32;

    auto prefetch = [&](int t, int s) {
        const int k0 = t * 32;
        // A: 64 rows x 4 chunks = 256 chunks, 1 per thread
        {
            int row = tid >> 2, c4 = tid & 3;
            int gr = row0 + row;
            int av = (gr < M) ? 16 : 0;
            size_t aoff = (size_t)(gr < M ? gr : 0) * K + k0 + c4 * 8;
            cpa16(smb + O64A(s, 0, row, c4*8) * 2, Ah + aoff, av);
            cpa16(smb + O64A(s, 1, row, c4*8) * 2, Al + aoff, av);
        }
        // W: 128 rows x 4 chunks = 512 chunks, 2 per thread
        #pragma unroll
        for (int i = 0; i < 2; i++) {
            int ch = tid * 2 + i;
            int row = ch >> 2, c4 = ch & 3;
            size_t boff = (size_t)(col0 + row) * K + k0 + c4 * 8;
            cpa16(smb + O64W(s, 0, row, c4*8) * 2, Wh + boff, 16);
            cpa16(smb + O64W(s, 1, row, c4*8) * 2, Wl + boff, 16);
        }
        asm volatile("cp.async.commit_group;" ::: "memory");
    };

    prefetch(0, 0);
    if (T > 1) prefetch(1, 1);

    const int fr = lane & 15;
    for (int t = 0; t < T; t++) {
        const int s = t % 3;
        if (t == T - 1)
            asm volatile("cp.async.wait_group 0;" ::: "memory");
        else
            asm volatile("cp.async.wait_group 1;" ::: "memory");
        __syncthreads();
        if (t + 2 < T) prefetch(t + 2, (t + 2) % 3);

        #pragma unroll
        for (int kh = 0; kh < 32; kh += 16) {
            const int fc = kh + (lane >> 4) * 8;
            uint32_t bh[4][2], bl[4][2];
            #pragma unroll
            for (int pr = 0; pr < 2; pr++) {
                int nr = wn * 32 + pr * 16 + fr;
                uint32_t r0, r1, r2, r3;
                ldmx4(r0, r1, r2, r3, smb + O64W(s, 0, nr, fc) * 2);
                bh[2*pr][0] = r0; bh[2*pr+1][0] = r1;
                bh[2*pr][1] = r2; bh[2*pr+1][1] = r3;
                ldmx4(r0, r1, r2, r3, smb + O64W(s, 1, nr, fc) * 2);
                bl[2*pr][0] = r0; bl[2*pr+1][0] = r1;
                bl[2*pr][1] = r2; bl[2*pr+1][1] = r3;
            }
            #pragma unroll
            for (int mt = 0; mt < 2; mt++) {
                int mr = wm * 32 + mt * 16 + fr;
                uint32_t ah[4], al[4];
                ldmx4(ah[0], ah[1], ah[2], ah[3], smb + O64A(s, 0, mr, fc) * 2);
                ldmx4(al[0], al[1], al[2], al[3], smb + O64A(s, 1, mr, fc) * 2);
                #pragma unroll
                for (int nt = 0; nt < 4; nt++) {
                    mma_bf(acc[mt][nt], ah, bh[nt]);
                    mma_bf(acc[mt][nt], ah, bl[nt]);
                    mma_bf(acc[mt][nt], al, bh[nt]);
                }
            }
        }
        __syncthreads();
    }

    #pragma unroll
    for (int mt = 0; mt < 2; mt++) {
        int r0 = row0 + wm * 32 + mt * 16 + g;
        #pragma unroll
        for (int h = 0; h < 2; h++) {
            int r = r0 + 8 * h;
            if (r >= M) continue;
            #pragma unroll
            for (int nt = 0; nt < 4; nt++) {
                int cc = col0 + wn * 32 + nt * 8 + 2 * q;
                float v0 = acc[mt][nt][2*h]     + bias[cc];
                float v1 = acc[mt][nt][2*h + 1] + bias[cc + 1];
                gemm_epilogue_pair(r, cc, N, v0, v1, mode, C, Oh, Ol);
            }
        }
    }
}

// ------------------------------ LayerNorm -----------------------------------
__device__ __forceinline__ float blk_sum(float v, float* smr)
{
    const int lane = threadIdx.x & 31, w = threadIdx.x >> 5;
    #pragma unroll
    for (int o = 16; o; o >>= 1) v += __shfl_xor_sync(0xffffffffu, v, o);
    if (lane == 0) smr[w] = v;
    __syncthreads();
    if (threadIdx.x == 0) {
        float t = 0.f;
        #pragma unroll
        for (int i = 0; i < 8; i++) t += smr[i];
        smr[8] = t;
    }
    __syncthreads();
    float t = smr[8];
    __syncthreads();
    return t;
}

__global__ void __launch_bounds__(256) ln_hl_kernel(
    const float* __restrict__ in, const float* __restrict__ w,
    const float* __restrict__ b, __nv_bfloat16* __restrict__ oh,
    __nv_bfloat16* __restrict__ ol, int gm)
{
    __shared__ float smr[9];
    const int r = blockIdx.x;
    const float* x;
    if (gm == 0) {
        x = in + (size_t)r * CD;
    } else if (gm == 1) {
        int t = r % TT; int bn = r / TT; int n = bn % NP; int bb = bn / NP;
        x = in + ((size_t)bb * SEQ + 1 + t * NP + n) * CD;
    } else {
        int m = r % KS; int bt = r / KS; int t = bt % TT; int bb = bt / TT;
        x = in + ((m == 0) ? ((size_t)bb * SEQ) * CD
                           : ((size_t)bb * SEQ + 1 + t * NP + (m - 1)) * CD);
    }
    const int t = threadIdx.x;
    float v0 = x[t], v1 = x[t + 256], v2 = x[t + 512];
    float tot = blk_sum(v0 + v1 + v2, smr);
    float mean = tot * (1.0f / CD);
    float d0 = v0 - mean, d1 = v1 - mean, d2 = v2 - mean;
    float tot2 = blk_sum(d0 * d0 + d1 * d1 + d2 * d2, smr);
    float inv = rsqrtf(tot2 * (1.0f / CD) + 1e-6f);
    size_t base = (size_t)r * CD;
    float o0 = d0 * inv * w[t]       + b[t];
    float o1 = d1 * inv * w[t + 256] + b[t + 256];
    float o2 = d2 * inv * w[t + 512] + b[t + 512];
    split2(o0, oh[base + t],       ol[base + t]);
    split2(o1, oh[base + t + 256], ol[base + t + 256]);
    split2(o2, oh[base + t + 512], ol[base + t + 512]);
}

__global__ void __launch_bounds__(256) ln_cls_kernel(
    const float* __restrict__ w, const float* __restrict__ b)
{
    __shared__ float smr[9];
    const float* x = g_xb + (size_t)blockIdx.x * SEQ * CD;
    const int t = threadIdx.x;
    float v0 = x[t], v1 = x[t + 256], v2 = x[t + 512];
    float tot = blk_sum(v0 + v1 + v2, smr);
    float mean = tot * (1.0f / CD);
    float d0 = v0 - mean, d1 = v1 - mean, d2 = v2 - mean;
    float tot2 = blk_sum(d0 * d0 + d1 * d1 + d2 * d2, smr);
    float inv = rsqrtf(tot2 * (1.0f / CD) + 1e-6f);
    float* o = g_buf2 + (size_t)blockIdx.x * CD;
    o[t]       = d0 * inv * w[t]       + b[t];
    o[t + 256] = d1 * inv * w[t + 256] + b[t + 256];
    o[t + 512] = d2 * inv * w[t + 512] + b[t + 512];
}

// ------------------------- Time attention (seq=8) ---------------------------
__global__ void __launch_bounds__(64) time_attn_kernel()
{
    const int g = blockIdx.x;
    const int h = g % NH;
    const int bn = g / NH;
    const int lane = threadIdx.x;
    __shared__ float Q[TT][HD + 1], Kk[TT][HD + 1], V[TT][HD + 1];
    __shared__ float P[TT][TT + 1];
    #pragma unroll
    for (int t = 0; t < TT; t++) {
        size_t base = ((size_t)(bn * TT + t)) * (3 * CD) + h * HD + lane;
        Q[t][lane]  = g_qkv[base];
        Kk[t][lane] = g_qkv[base + CD];
        V[t][lane]  = g_qkv[base + 2 * CD];
    }
    __syncthreads();
    const int tq = lane >> 3, tk = lane & 7;
    float s = 0.f;
    #pragma unroll
    for (int d = 0; d < HD; d++) s += Q[tq][d] * Kk[tk][d];
    P[tq][tk] = s * 0.125f;
    __syncthreads();
    if (lane < TT) {
        float m = -1e30f;
        #pragma unroll
        for (int k = 0; k < TT; k++) m = fmaxf(m, P[lane][k]);
        float sum = 0.f;
        #pragma unroll
        for (int k = 0; k < TT; k++) { float e = expf(P[lane][k] - m); P[lane][k] = e; sum += e; }
        float inv = 1.f / sum;
        #pragma unroll
        for (int k = 0; k < TT; k++) P[lane][k] *= inv;
    }
    __syncthreads();
    #pragma unroll
    for (int t = 0; t < TT; t++) {
        float a = 0.f;
        #pragma unroll
        for (int k = 0; k < TT; k++) a += P[t][k] * V[k][lane];
        size_t idx = ((size_t)(bn * TT + t)) * CD + h * HD + lane;
        split2(a, g_at_hi[idx], g_at_lo[idx]);
    }
}

// ------------------- Fused space attention (seq=197) ------------------------
constexpr int SA_SMEM = (96 * (HD + 1) + 32 * 256) * 4;   // 57728 bytes

__global__ void __launch_bounds__(256) space_attn_kernel()
{
    extern __shared__ float sa[];
    float (*Qs)[HD + 1]  = (float(*)[HD + 1])sa;
    float (*KVs)[HD + 1] = (float(*)[HD + 1])(sa + 32 * (HD + 1));
    float (*Ss)[256]     = (float(*)[256])(sa + 96 * (HD + 1));

    const int g = blockIdx.x;
    const int h = g % NH, bt = g / NH;
    const int q0 = blockIdx.y * 32;
    const int tid = threadIdx.x;
    const int kc = tid & 63, qb = tid >> 6;

    for (int i = tid; i < 32 * 64; i += 256) {
        int r = i >> 6, d = i & 63; int gq = q0 + r;
        Qs[r][d] = (gq < KS)
            ? g_qkv[((size_t)(bt * KS + gq)) * (3 * CD) + h * HD + d] : 0.f;
    }

    for (int kt = 0; kt < 4; kt++) {
        const int k0 = kt * 64;
        __syncthreads();
        for (int i = tid; i < 64 * 64; i += 256) {
            int r = i >> 6, d = i & 63; int gk = k0 + r;
            KVs[r][d] = (gk < KS)
                ? g_qkv[((size_t)(bt * KS + gk)) * (3 * CD) + CD + h * HD + d] : 0.f;
        }
        __syncthreads();
        float s[8];
        #pragma unroll
        for (int i = 0; i < 8; i++) s[i] = 0.f;
        #pragma unroll
        for (int d = 0; d < HD; d++) {
            float kv = KVs[kc][d];
            #pragma unroll
            for (int i = 0; i < 8; i++) s[i] = fmaf(Qs[qb + 4 * i][d], kv, s[i]);
        }
        #pragma unroll
        for (int i = 0; i < 8; i++) Ss[qb + 4 * i][k0 + kc] = s[i] * 0.125f;
    }
    __syncthreads();

    {
        const int lane = tid & 31;
        const int rbase = (tid >> 5) * 4;
        for (int rr = 0; rr < 4; rr++) {
            const int r = rbase + rr;
            float vals[7];
            float m = -1e30f;
            #pragma unroll
            for (int i = 0; i < 7; i++) {
                int j = lane + 32 * i;
                vals[i] = (j < KS) ? Ss[r][j] : -1e30f;
                m = fmaxf(m, vals[i]);
            }
            #pragma unroll
            for (int o = 16; o; o >>= 1) m = fmaxf(m, __shfl_xor_sync(0xffffffffu, m, o));
            float sum = 0.f;
            #pragma unroll
            for (int i = 0; i < 7; i++) {
                int j = lane + 32 * i;
                if (j < KS) { vals[i] = expf(vals[i] - m); sum += vals[i]; }
            }
            #pragma unroll
            for (int o = 16; o; o >>= 1) sum += __shfl_xor_sync(0xffffffffu, sum, o);
            float inv = 1.f / sum;
            #pragma unroll
            for (int i = 0; i < 7; i++) {
                int j = lane + 32 * i;
                if (j < KS) Ss[r][j] = vals[i] * inv;
            }
        }
    }
    __syncthreads();

    float acc[8];
    #pragma unroll
    for (int i = 0; i < 8; i++) acc[i] = 0.f;
    for (int kt = 0; kt < 4; kt++) {
        const int k0 = kt * 64;
        for (int i = tid; i < 64 * 64; i += 256) {
            int r = i >> 6, d = i & 63; int gk = k0 + r;
            KVs[r][d] = (gk < KS)
                ? g_qkv[((size_t)(bt * KS + gk)) * (3 * CD) + 2 * CD + h * HD + d] : 0.f;
        }
        __syncthreads();
        #pragma unroll
        for (int kk = 0; kk < 64; kk++) {
            float vv = KVs[kk][kc];
            #pragma unroll
            for (int i = 0; i < 8; i++) acc[i] = fmaf(Ss[qb + 4 * i][k0 + kk], vv, acc[i]);
        }
        __syncthreads();
    }

    #pragma unroll
    for (int i = 0; i < 8; i++) {
        int gq = q0 + qb + 4 * i;
        if (gq < KS) {
            size_t idx = ((size_t)(bt * KS + gq)) * CD + h * HD + kc;
            split2(acc[i], g_at_hi[idx], g_at_lo[idx]);
        }
    }
}

// --------------------------- elementwise helpers ----------------------------
__global__ void patchify_kernel(const float* __restrict__ x)
{
    int i = blockIdx.x * blockDim.x + threadIdx.x;
    if (i >= RT * CD) return;
    int k = i % CD; int r = i / CD;
    int n = r % NP; int bt = r / NP; int t = bt % TT; int b = bt / TT;
    int ci = k >> 8; int rem = k & 255; int py = rem >> 4; int px = rem & 15;
    int nh = n / 14, nw = n % 14;
    size_t src = ((((size_t)b * 3 + ci) * TT + t) * 224 + (nh * 16 + py)) * 224 + (nw * 16 + px);
    split2(x[src], g_pa_hi[i], g_pa_lo[i]);
}

__global__ void init_cls_kernel(const float* __restrict__ cls_token,
                                const float* __restrict__ pos_embed)
{
    int i = blockIdx.x * blockDim.x + threadIdx.x;
    if (i >= BATCH * CD) return;
    int b = i / CD, c = i % CD;
    g_xb[((size_t)b * SEQ) * CD + c] = cls_token[c] + pos_embed[c];
}

__global__ void init_patch_kernel(const float* __restrict__ pos_embed,
                                  const float* __restrict__ time_embed)
{
    int i = blockIdx.x * blockDim.x + threadIdx.x;
    if (i >= RT * CD) return;
    int c = i % CD; int r = i / CD;
    int n = r % NP; int bt = r / NP; int t = bt % TT; int b = bt / TT;
    g_xb[((size_t)b * SEQ + 1 + t * NP + n) * CD + c] =
        g_buf3[i] + pos_embed[(size_t)(1 + n) * CD + c] + time_embed[(size_t)t * CD + c];
}

__global__ void combine_cls_kernel()
{
    int i = blockIdx.x * blockDim.x + threadIdx.x;
    if (i >= BATCH * CD) return;
    int b = i / CD, c = i % CD;
    float s = 0.f;
    #pragma unroll
    for (int t = 0; t < TT; t++)
        s += g_buf3[((size_t)((b * TT + t) * KS)) * CD + c];
    g_xb[((size_t)b * SEQ) * CD + c] += s * (1.f / TT);
}

// ------------------------------- head ---------------------------------------
__global__ void __launch_bounds__(256) head_kernel(
    const float* __restrict__ hw, const float* __restrict__ hb,
    float* __restrict__ out)
{
    const int warp = threadIdx.x >> 5, lane = threadIdx.x & 31;
    const int o = blockIdx.x * 8 + warp;
    if (o >= BATCH * 1000) return;
    const int b = o / 1000, j = o % 1000;
    const float* xr = g_buf2 + (size_t)b * CD;
    const float* wr = hw + (size_t)j * CD;
    float s = 0.f;
    for (int k = lane; k < CD; k += 32) s += xr[k] * wr[k];
    #pragma unroll
    for (int off = 16; off; off >>= 1) s += __shfl_down_sync(0xffffffffu, s, off);
    if (lane == 0) out[o] = s + hb[j];
}

// ------------------------------ launcher ------------------------------------
static inline int cdiv(int a, int b) { return (a + b - 1) / b; }

static void gemm_bf(const __nv_bfloat16* Ah, const __nv_bfloat16* Al,
                    const __nv_bfloat16* Wh, const __nv_bfloat16* Wl,
                    const float* bias, float* C,
                    __nv_bfloat16* Oh, __nv_bfloat16* Ol,
                    int M, int N, int K, int mode)
{
    if (N == 768) {
        dim3 gr(N / 128, cdiv(M, 64));
        bf_gemm64_kernel<<<gr, 256, GEMM64_SMEM>>>(Ah, Al, Wh, Wl, bias, C,
                                                   Oh, Ol, M, N, K, mode);
    } else {
        dim3 gr(N / 128, cdiv(M, 128));
        bf_gemm_kernel<<<gr, 256, GEMM_SMEM>>>(Ah, Al, Wh, Wl, bias, C, Oh, Ol,
                                               M, N, K, mode, 0, 0, 0);
    }
}

static void wsplit(const float* src, __nv_bfloat16* hi, __nv_bfloat16* lo, size_t n)
{
    long n4 = (long)(n / 4);
    wsplit_kernel<<<(int)((n4 + 255) / 256), 256>>>(
        (const float4*)src, (__nv_bfloat162*)hi, (__nv_bfloat162*)lo, n4);
}

extern "C" void kernel_launch(void* const* d_in, const int* in_sizes, int n_in,
                              void* d_out, int out_size)
{
    const float* x          = (const float*)d_in[0];
    const float* conv_w     = (const float*)d_in[1];
    const float* conv_b     = (const float*)d_in[2];
    const float* cls_token  = (const float*)d_in[3];
    const float* pos_embed  = (const float*)d_in[4];
    const float* time_embed = (const float*)d_in[5];
    const float* tn_w   = (const float*)d_in[6];
    const float* tn_b   = (const float*)d_in[7];
    const float* tqkv_w = (const float*)d_in[8];
    const float* tqkv_b = (const float*)d_in[9];
    const float* tproj_w= (const float*)d_in[10];
    const float* tproj_b= (const float*)d_in[11];
    const float* tfc_w  = (const float*)d_in[12];
    const float* tfc_b  = (const float*)d_in[13];
    const float* n1_w   = (const float*)d_in[14];
    const float* n1_b   = (const float*)d_in[15];
    const float* sqkv_w = (const float*)d_in[16];
    const float* sqkv_b = (const float*)d_in[17];
    const float* sproj_w= (const float*)d_in[18];
    const float* sproj_b= (const float*)d_in[19];
    const float* n2_w   = (const float*)d_in[20];
    const float* n2_b   = (const float*)d_in[21];
    const float* fc1_w  = (const float*)d_in[22];
    const float* fc1_b  = (const float*)d_in[23];
    const float* fc2_w  = (const float*)d_in[24];
    const float* fc2_b  = (const float*)d_in[25];
    const float* norm_w = (const float*)d_in[26];
    const float* norm_b = (const float*)d_in[27];
    const float* head_w = (const float*)d_in[28];
    const float* head_b = (const float*)d_in[29];

    float *xb, *buf3, *qkv, *wc, *bc, *zero;
    cudaGetSymbolAddress((void**)&xb,   g_xb);
    cudaGetSymbolAddress((void**)&buf3, g_buf3);
    cudaGetSymbolAddress((void**)&qkv,  g_qkv);
    cudaGetSymbolAddress((void**)&wc,   g_wc);
    cudaGetSymbolAddress((void**)&bc,   g_bc);
    cudaGetSymbolAddress((void**)&zero, g_zero);

    __nv_bfloat16 *whi, *wlo, *lnh, *lnl, *ath, *atl, *f1h, *f1l, *pah, *pal;
    cudaGetSymbolAddress((void**)&whi, g_w_hi);
    cudaGetSymbolAddress((void**)&wlo, g_w_lo);
    cudaGetSymbolAddress((void**)&lnh, g_ln_hi);
    cudaGetSymbolAddress((void**)&lnl, g_ln_lo);
    cudaGetSymbolAddress((void**)&ath, g_at_hi);
    cudaGetSymbolAddress((void**)&atl, g_at_lo);
    cudaGetSymbolAddress((void**)&f1h, g_f1_hi);
    cudaGetSymbolAddress((void**)&f1l, g_f1_lo);
    cudaGetSymbolAddress((void**)&pah, g_pa_hi);
    cudaGetSymbolAddress((void**)&pal, g_pa_lo);

    cudaFuncSetAttribute(bf_gemm_kernel,
                         cudaFuncAttributeMaxDynamicSharedMemorySize, GEMM_SMEM);
    cudaFuncSetAttribute(bf_gemm64_kernel,
                         cudaFuncAttributeMaxDynamicSharedMemorySize, GEMM64_SMEM);
    cudaFuncSetAttribute(space_attn_kernel,
                         cudaFuncAttributeMaxDynamicSharedMemorySize, SA_SMEM);

    const int EB = 256;

    // ---- split weights into bf16 hi/lo ----
    wsplit(tqkv_w,  whi + W_TQKV,  wlo + W_TQKV,  SZ_TQKV);
    wsplit(tfc_w,   whi + W_TFC,   wlo + W_TFC,   SZ_CC);
    wsplit(sqkv_w,  whi + W_SQKV,  wlo + W_SQKV,  SZ_TQKV);
    wsplit(sproj_w, whi + W_SPROJ, wlo + W_SPROJ, SZ_CC);
    wsplit(fc1_w,   whi + W_FC1,   wlo + W_FC1,   SZ_FC);
    wsplit(fc2_w,   whi + W_FC2,   wlo + W_FC2,   SZ_FC);
    wsplit(conv_w,  whi + W_CONV,  wlo + W_CONV,  (size_t)CD * CD);

    // ---- merge tproj into tfc: Wc = tfc_w @ tproj_w, bc = tfc_w@tproj_b + tfc_b
    {
        dim3 tb(32, 8);
        dim3 tg(CD / 32, CD / 32, DEPTH);
        tsplit_kernel<<<tg, tb>>>(tproj_w, f1h, f1l);
        dim3 gw(CD / 128, CD / 128, DEPTH);
        bf_gemm_kernel<<<gw, 256, GEMM_SMEM>>>(
            whi + W_TFC, wlo + W_TFC, f1h, f1l, zero, wc, nullptr, nullptr,
            CD, CD, CD, 0, (long)CD * CD, (long)CD * CD, (long)CD * CD);
        bias_merge_kernel<<<cdiv(DEPTH * CD, 8), 256>>>(tfc_w, tproj_b, tfc_b);
        wsplit(wc, whi + W_TFC, wlo + W_TFC, SZ_CC);
    }

    // ---- patch embedding + pos/time embed + cls init ----
    patchify_kernel<<<cdiv(RT * CD, EB), EB>>>(x);
    gemm_bf(pah, pal, whi + W_CONV, wlo + W_CONV, conv_b, buf3, nullptr, nullptr,
            RT, CD, CD, 0);
    init_cls_kernel<<<cdiv(BATCH * CD, EB), EB>>>(cls_token, pos_embed);
    init_patch_kernel<<<cdiv(RT * CD, EB), EB>>>(pos_embed, time_embed);

    // ---- transformer blocks ----
    for (int l = 0; l < DEPTH; l++) {
        size_t o3 = (size_t)l * 3 * CD * CD;
        size_t o1 = (size_t)l * CD * CD;
        size_t o4 = (size_t)l * 4 * CD * CD;

        // ===== time attention =====
        ln_hl_kernel<<<RT, 256>>>(xb, tn_w + (size_t)l * CD, tn_b + (size_t)l * CD,
                                  lnh, lnl, 1);
        gemm_bf(lnh, lnl, whi + W_TQKV + o3, wlo + W_TQKV + o3,
                tqkv_b + (size_t)l * 3 * CD, qkv, nullptr, nullptr,
                RT, 3 * CD, CD, 0);
        time_attn_kernel<<<(RT / TT) * NH, 64>>>();
        gemm_bf(ath, atl, whi + W_TFC + o1, wlo + W_TFC + o1,
                bc + (size_t)l * CD, nullptr, nullptr, nullptr,
                RT, CD, CD, 3);                       // merged proj+fc, scatter-add

        // ===== space attention =====
        ln_hl_kernel<<<RS, 256>>>(xb, n1_w + (size_t)l * CD, n1_b + (size_t)l * CD,
                                  lnh, lnl, 2);
        gemm_bf(lnh, lnl, whi + W_SQKV + o3, wlo + W_SQKV + o3,
                sqkv_b + (size_t)l * 3 * CD, qkv, nullptr, nullptr,
                RS, 3 * CD, CD, 0);
        {
            dim3 gr(GROUPS, cdiv(KS, 32));
            space_attn_kernel<<<gr, 256, SA_SMEM>>>();
        }
        gemm_bf(ath, atl, whi + W_SPROJ + o1, wlo + W_SPROJ + o1,
                sproj_b + (size_t)l * CD, nullptr, nullptr, nullptr,
                RS, CD, CD, 5);                       // scatter-add + cls->buf3
        combine_cls_kernel<<<cdiv(BATCH * CD, EB), EB>>>();

        // ===== MLP =====
        ln_hl_kernel<<<RX, 256>>>(xb, n2_w + (size_t)l * CD, n2_b + (size_t)l * CD,
                                  lnh, lnl, 0);
        gemm_bf(lnh, lnl, whi + W_FC1 + o4, wlo + W_FC1 + o4,
                fc1_b + (size_t)l * 4 * CD, nullptr, f1h, f1l,
                RX, 4 * CD, CD, 1);
        gemm_bf(f1h, f1l, whi + W_FC2 + o4, wlo + W_FC2 + o4,
                fc2_b + (size_t)l * CD, nullptr, nullptr, nullptr,
                RX, CD, 4 * CD, 4);                   // residual add into xb
    }

    // ---- final norm (cls rows only) + head ----
    ln_cls_kernel<<<BATCH, 256>>>(norm_w, norm_b);
    head_kernel<<<cdiv(BATCH * 1000, 8), 256>>>(head_w, head_b, (float*)d_out);
}

// round 15
// speedup vs baseline: 1.7995x; 1.0372x over previous
#include <cuda_runtime.h>
#include <cuda_bf16.h>
#include <math.h>
#include <stdint.h>

// ---------------------------------------------------------------------------
// TimeSformer forward. B=2, T=8, N=196, C=768, H=12, hd=64, depth=12.
// GEMMs: bf16x3 tensor-core (hi/lo split). 128x128 CTA for wide-N,
// 64x128 CTA (3-stage) for N=768 GEMMs. tproj*tfc merged; space attn fused
// with float2-vectorized inner loops.
// ---------------------------------------------------------------------------

constexpr int BATCH = 2;
constexpr int TT    = 8;
constexpr int NP    = 196;
constexpr int CD    = 768;
constexpr int NH    = 12;
constexpr int HD    = 64;
constexpr int SEQ   = 1 + TT * NP;          // 1569
constexpr int RT    = BATCH * TT * NP;      // 3136
constexpr int KS    = NP + 1;               // 197
constexpr int RS    = BATCH * TT * KS;      // 3152
constexpr int RX    = BATCH * SEQ;          // 3138
constexpr int GROUPS= BATCH * TT * NH;      // 192
constexpr int DEPTH = 12;

// -------------------------- scratch (device globals) -----------------------
__device__ float g_xb     [(size_t)BATCH * SEQ * CD];
__device__ float g_buf2   [(size_t)BATCH * CD];
__device__ float g_buf3   [(size_t)RS * CD];
__device__ float g_qkv    [(size_t)RS * 3 * CD];
__device__ float g_wc     [(size_t)DEPTH * CD * CD];
__device__ float g_bc     [(size_t)DEPTH * CD];
__device__ float g_zero   [CD];

__device__ __nv_bfloat16 g_ln_hi[(size_t)RS * CD];
__device__ __nv_bfloat16 g_ln_lo[(size_t)RS * CD];
__device__ __nv_bfloat16 g_at_hi[(size_t)RS * CD];
__device__ __nv_bfloat16 g_at_lo[(size_t)RS * CD];
__device__ __nv_bfloat16 g_f1_hi[(size_t)RX * 4 * CD];
__device__ __nv_bfloat16 g_f1_lo[(size_t)RX * 4 * CD];
__device__ __nv_bfloat16 g_pa_hi[(size_t)RT * CD];
__device__ __nv_bfloat16 g_pa_lo[(size_t)RT * CD];

constexpr size_t SZ_TQKV = (size_t)DEPTH * 3 * CD * CD;
constexpr size_t SZ_CC   = (size_t)DEPTH * CD * CD;
constexpr size_t SZ_FC   = (size_t)DEPTH * 4 * CD * CD;
constexpr size_t W_TQKV  = 0;
constexpr size_t W_TFC   = W_TQKV + SZ_TQKV;
constexpr size_t W_SQKV  = W_TFC + SZ_CC;
constexpr size_t W_SPROJ = W_SQKV + SZ_TQKV;
constexpr size_t W_FC1   = W_SPROJ + SZ_CC;
constexpr size_t W_FC2   = W_FC1 + SZ_FC;
constexpr size_t W_CONV  = W_FC2 + SZ_FC;
constexpr size_t W_TOTAL = W_CONV + (size_t)CD * CD;

__device__ __nv_bfloat16 g_w_hi[W_TOTAL];
__device__ __nv_bfloat16 g_w_lo[W_TOTAL];

// ------------------------------ split helper --------------------------------
__device__ __forceinline__ void split2(float x, __nv_bfloat16& h, __nv_bfloat16& l)
{
    h = __float2bfloat16(x);
    l = __float2bfloat16(x - __bfloat162float(h));
}

// ------------------------- weight split kernels ------------------------------
__global__ void __launch_bounds__(256) wsplit_kernel(
    const float4* __restrict__ src, __nv_bfloat162* __restrict__ hi,
    __nv_bfloat162* __restrict__ lo, long n4)
{
    long i = blockIdx.x * (long)blockDim.x + threadIdx.x;
    if (i >= n4) return;
    float4 v = src[i];
    __nv_bfloat16 h0,l0,h1,l1,h2,l2,h3,l3;
    split2(v.x, h0, l0); split2(v.y, h1, l1);
    split2(v.z, h2, l2); split2(v.w, h3, l3);
    hi[2*i]   = __halves2bfloat162(h0, h1);
    hi[2*i+1] = __halves2bfloat162(h2, h3);
    lo[2*i]   = __halves2bfloat162(l0, l1);
    lo[2*i+1] = __halves2bfloat162(l2, l3);
}

__global__ void tsplit_kernel(const float* __restrict__ src,
                              __nv_bfloat16* __restrict__ oh,
                              __nv_bfloat16* __restrict__ ol)
{
    __shared__ float t[32][33];
    const int l = blockIdx.z;
    const int x0 = blockIdx.x * 32, y0 = blockIdx.y * 32;
    const float* s = src + (size_t)l * CD * CD;
    for (int a = threadIdx.y; a < 32; a += 8)
        t[a][threadIdx.x] = s[(size_t)(y0 + a) * CD + x0 + threadIdx.x];
    __syncthreads();
    __nv_bfloat16* ohl = oh + (size_t)l * CD * CD;
    __nv_bfloat16* oll = ol + (size_t)l * CD * CD;
    for (int a = threadIdx.y; a < 32; a += 8) {
        float v = t[threadIdx.x][a];
        size_t idx = (size_t)(x0 + a) * CD + y0 + threadIdx.x;
        split2(v, ohl[idx], oll[idx]);
    }
}

__global__ void __launch_bounds__(256) bias_merge_kernel(
    const float* __restrict__ tfcw, const float* __restrict__ tprojb,
    const float* __restrict__ tfcb)
{
    const int warp = threadIdx.x >> 5, lane = threadIdx.x & 31;
    const int o = blockIdx.x * 8 + warp;
    if (o >= DEPTH * CD) return;
    const int l = o / CD, i = o % CD;
    const float* wr = tfcw + ((size_t)l * CD + i) * CD;
    const float* br = tprojb + (size_t)l * CD;
    float s = 0.f;
    for (int k = lane; k < CD; k += 32) s += wr[k] * br[k];
    #pragma unroll
    for (int off = 16; off; off >>= 1) s += __shfl_down_sync(0xffffffffu, s, off);
    if (lane == 0) g_bc[o] = s + tfcb[o];
}

// ------------------------- GEMM common pieces --------------------------------
__device__ __forceinline__ void cpa16(uint32_t dst, const void* src, int srcsz)
{
    asm volatile("cp.async.ca.shared.global [%0], [%1], 16, %2;"
                 :: "r"(dst), "l"(src), "r"(srcsz));
}
__device__ __forceinline__ void ldmx4(uint32_t& r0, uint32_t& r1,
                                      uint32_t& r2, uint32_t& r3, uint32_t addr)
{
    asm volatile("ldmatrix.sync.aligned.m8n8.x4.shared.b16 {%0,%1,%2,%3}, [%4];"
        : "=r"(r0), "=r"(r1), "=r"(r2), "=r"(r3) : "r"(addr));
}
__device__ __forceinline__ void mma_bf(float* c, const uint32_t* a, const uint32_t* b)
{
    asm volatile("mma.sync.aligned.m16n8k16.row.col.f32.bf16.bf16.f32 "
        "{%0,%1,%2,%3}, {%4,%5,%6,%7}, {%8,%9}, {%0,%1,%2,%3};"
        : "+f"(c[0]), "+f"(c[1]), "+f"(c[2]), "+f"(c[3])
        : "r"(a[0]), "r"(a[1]), "r"(a[2]), "r"(a[3]), "r"(b[0]), "r"(b[1]));
}

// epilogue shared by both GEMMs: handles one (r, cc) float2
// modes: 0 f32->C | 1 GELU->bf16 hi/lo | 2 bf16 hi/lo
//        3 time-scatter += xb | 4 += xb | 5 space-scatter += xb (cls->buf3)
__device__ __forceinline__ void gemm_epilogue_pair(
    int r, int cc, int N, float v0, float v1, int mode,
    float* C, __nv_bfloat16* Oh, __nv_bfloat16* Ol)
{
    if (mode == 0) {
        *(float2*)&C[(size_t)r * N + cc] = make_float2(v0, v1);
    } else if (mode == 1 || mode == 2) {
        if (mode == 1) { v0 = v0 * normcdff(v0); v1 = v1 * normcdff(v1); }
        __nv_bfloat16 h0, l0, h1, l1;
        split2(v0, h0, l0); split2(v1, h1, l1);
        *(__nv_bfloat162*)&Oh[(size_t)r * N + cc] = __halves2bfloat162(h0, h1);
        *(__nv_bfloat162*)&Ol[(size_t)r * N + cc] = __halves2bfloat162(l0, l1);
    } else {
        size_t xbase; bool is_cls = false;
        if (mode == 3) {
            int tt = r % TT; int bn = r / TT; int n = bn % NP; int b = bn / NP;
            xbase = ((size_t)b * SEQ + 1 + tt * NP + n) * CD;
        } else if (mode == 4) {
            xbase = (size_t)r * CD;
        } else {
            int m = r % KS; int bt = r / KS; int tt = bt % TT; int b = bt / TT;
            if (m == 0) { is_cls = true; xbase = (size_t)r * CD; }
            else xbase = ((size_t)b * SEQ + 1 + tt * NP + (m - 1)) * CD;
        }
        if (is_cls) {
            *(float2*)&g_buf3[xbase + cc] = make_float2(v0, v1);
        } else {
            float2 old = *(float2*)&g_xb[xbase + cc];
            old.x += v0; old.y += v1;
            *(float2*)&g_xb[xbase + cc] = old;
        }
    }
}

// ---------------------- bf16x3 GEMM, 128x128 CTA -----------------------------
#define SOFF(s, arr, row, col) (((((s)*4 + (arr))*128 + (row))*40 + (col)))
constexpr int GEMM_SMEM = 2 * 4 * 128 * 40 * 2;   // 81920 bytes

__global__ void __launch_bounds__(256) bf_gemm_kernel(
    const __nv_bfloat16* __restrict__ Ah, const __nv_bfloat16* __restrict__ Al,
    const __nv_bfloat16* __restrict__ Wh, const __nv_bfloat16* __restrict__ Wl,
    const float* __restrict__ bias, float* __restrict__ C,
    __nv_bfloat16* __restrict__ Oh, __nv_bfloat16* __restrict__ Ol,
    int M, int N, int K, int mode, long sA, long sW, long sC)
{
    extern __shared__ __align__(16) __nv_bfloat16 sm[];
    const uint32_t smb = (uint32_t)__cvta_generic_to_shared(sm);

    const long z = blockIdx.z;
    Ah += z * sA; Al += z * sA;
    Wh += z * sW; Wl += z * sW;
    if (C) C += z * sC;

    int bx = blockIdx.x, by = blockIdx.y;
    if (by & 1) bx = gridDim.x - 1 - bx;       // serpentine for L2 reuse

    const int tid  = threadIdx.x;
    const int wid  = tid >> 5;
    const int lane = tid & 31;
    const int wm   = wid >> 2;
    const int wn   = wid & 3;
    const int g    = lane >> 2;
    const int q    = lane & 3;
    const int row0 = by * 128;
    const int col0 = bx * 128;

    float acc[4][4][4];
    #pragma unroll
    for (int i = 0; i < 4; i++)
        #pragma unroll
        for (int j = 0; j < 4; j++)
            #pragma unroll
            for (int v = 0; v < 4; v++) acc[i][j][v] = 0.f;

    const int lrow = tid >> 1;
    const int c0b  = (tid & 1) * 2;
    const int T = K / 32;

    auto prefetch = [&](int t, int s) {
        const int k0 = t * 32;
        int gr = row0 + lrow;
        int av = (gr < M) ? 16 : 0;
        size_t aoff = (size_t)(gr < M ? gr : 0) * K + k0;
        size_t boff = (size_t)(col0 + lrow) * K + k0;
        #pragma unroll
        for (int c = c0b; c < c0b + 2; c++) {
            cpa16(smb + SOFF(s, 0, lrow, c*8) * 2, Ah + aoff + c*8, av);
            cpa16(smb + SOFF(s, 1, lrow, c*8) * 2, Al + aoff + c*8, av);
            cpa16(smb + SOFF(s, 2, lrow, c*8) * 2, Wh + boff + c*8, 16);
            cpa16(smb + SOFF(s, 3, lrow, c*8) * 2, Wl + boff + c*8, 16);
        }
        asm volatile("cp.async.commit_group;" ::: "memory");
    };

    prefetch(0, 0);

    const int fr = lane & 15;
    for (int t = 0; t < T; t++) {
        const int s = t & 1;
        asm volatile("cp.async.wait_group 0;" ::: "memory");
        __syncthreads();
        if (t + 1 < T) prefetch(t + 1, (t + 1) & 1);

        #pragma unroll
        for (int kh = 0; kh < 32; kh += 16) {
            const int fc = kh + (lane >> 4) * 8;
            uint32_t bh[4][2], bl[4][2];
            #pragma unroll
            for (int pr = 0; pr < 2; pr++) {
                int nr = wn * 32 + pr * 16 + fr;
                uint32_t r0, r1, r2, r3;
                ldmx4(r0, r1, r2, r3, smb + SOFF(s, 2, nr, fc) * 2);
                bh[2*pr][0] = r0; bh[2*pr+1][0] = r1;
                bh[2*pr][1] = r2; bh[2*pr+1][1] = r3;
                ldmx4(r0, r1, r2, r3, smb + SOFF(s, 3, nr, fc) * 2);
                bl[2*pr][0] = r0; bl[2*pr+1][0] = r1;
                bl[2*pr][1] = r2; bl[2*pr+1][1] = r3;
            }
            #pragma unroll
            for (int mt = 0; mt < 4; mt++) {
                int mr = wm * 64 + mt * 16 + fr;
                uint32_t ah[4], al[4];
                ldmx4(ah[0], ah[1], ah[2], ah[3], smb + SOFF(s, 0, mr, fc) * 2);
                ldmx4(al[0], al[1], al[2], al[3], smb + SOFF(s, 1, mr, fc) * 2);
                #pragma unroll
                for (int nt = 0; nt < 4; nt++) {
                    mma_bf(acc[mt][nt], ah, bh[nt]);
                    mma_bf(acc[mt][nt], ah, bl[nt]);
                    mma_bf(acc[mt][nt], al, bh[nt]);
                }
            }
        }
        __syncthreads();
    }

    #pragma unroll
    for (int mt = 0; mt < 4; mt++) {
        int r0 = row0 + wm * 64 + mt * 16 + g;
        #pragma unroll
        for (int h = 0; h < 2; h++) {
            int r = r0 + 8 * h;
            if (r >= M) continue;
            #pragma unroll
            for (int nt = 0; nt < 4; nt++) {
                int cc = col0 + wn * 32 + nt * 8 + 2 * q;
                float v0 = acc[mt][nt][2*h]     + bias[cc];
                float v1 = acc[mt][nt][2*h + 1] + bias[cc + 1];
                gemm_epilogue_pair(r, cc, N, v0, v1, mode, C, Oh, Ol);
            }
        }
    }
}

// ---------------------- bf16x3 GEMM, 64x128 CTA, 3-stage ---------------------
constexpr int ST64 = 2*64*40 + 2*128*40;          // 15360 elems per stage
constexpr int GEMM64_SMEM = 3 * ST64 * 2;         // 92160 bytes
#define O64A(s, arr, row, col) ((s)*ST64 + (arr)*64*40 + (row)*40 + (col))
#define O64W(s, arr, row, col) ((s)*ST64 + 2*64*40 + (arr)*128*40 + (row)*40 + (col))

__global__ void __launch_bounds__(256) bf_gemm64_kernel(
    const __nv_bfloat16* __restrict__ Ah, const __nv_bfloat16* __restrict__ Al,
    const __nv_bfloat16* __restrict__ Wh, const __nv_bfloat16* __restrict__ Wl,
    const float* __restrict__ bias, float* __restrict__ C,
    __nv_bfloat16* __restrict__ Oh, __nv_bfloat16* __restrict__ Ol,
    int M, int N, int K, int mode)
{
    extern __shared__ __align__(16) __nv_bfloat16 sm[];
    const uint32_t smb = (uint32_t)__cvta_generic_to_shared(sm);

    int bx = blockIdx.x, by = blockIdx.y;
    if (by & 1) bx = gridDim.x - 1 - bx;

    const int tid  = threadIdx.x;
    const int wid  = tid >> 5;
    const int lane = tid & 31;
    const int wm   = wid >> 2;          // 0..1 (32-row warp tile)
    const int wn   = wid & 3;           // 0..3 (32-col warp tile)
    const int g    = lane >> 2;
    const int q    = lane & 3;
    const int row0 = by * 64;
    const int col0 = bx * 128;

    float acc[2][4][4];
    #pragma unroll
    for (int i = 0; i < 2; i++)
        #pragma unroll
        for (int j = 0; j < 4; j++)
            #pragma unroll
            for (int v = 0; v < 4; v++) acc[i][j][v] = 0.f;

    const int T = K / 32;

    auto prefetch = [&](int t, int s) {
        const int k0 = t * 32;
        {
            int row = tid >> 2, c4 = tid & 3;
            int gr = row0 + row;
            int av = (gr < M) ? 16 : 0;
            size_t aoff = (size_t)(gr < M ? gr : 0) * K + k0 + c4 * 8;
            cpa16(smb + O64A(s, 0, row, c4*8) * 2, Ah + aoff, av);
            cpa16(smb + O64A(s, 1, row, c4*8) * 2, Al + aoff, av);
        }
        #pragma unroll
        for (int i = 0; i < 2; i++) {
            int ch = tid * 2 + i;
            int row = ch >> 2, c4 = ch & 3;
            size_t boff = (size_t)(col0 + row) * K + k0 + c4 * 8;
            cpa16(smb + O64W(s, 0, row, c4*8) * 2, Wh + boff, 16);
            cpa16(smb + O64W(s, 1, row, c4*8) * 2, Wl + boff, 16);
        }
        asm volatile("cp.async.commit_group;" ::: "memory");
    };

    prefetch(0, 0);
    if (T > 1) prefetch(1, 1);

    const int fr = lane & 15;
    for (int t = 0; t < T; t++) {
        const int s = t % 3;
        if (t == T - 1)
            asm volatile("cp.async.wait_group 0;" ::: "memory");
        else
            asm volatile("cp.async.wait_group 1;" ::: "memory");
        __syncthreads();
        if (t + 2 < T) prefetch(t + 2, (t + 2) % 3);

        #pragma unroll
        for (int kh = 0; kh < 32; kh += 16) {
            const int fc = kh + (lane >> 4) * 8;
            uint32_t bh[4][2], bl[4][2];
            #pragma unroll
            for (int pr = 0; pr < 2; pr++) {
                int nr = wn * 32 + pr * 16 + fr;
                uint32_t r0, r1, r2, r3;
                ldmx4(r0, r1, r2, r3, smb + O64W(s, 0, nr, fc) * 2);
                bh[2*pr][0] = r0; bh[2*pr+1][0] = r1;
                bh[2*pr][1] = r2; bh[2*pr+1][1] = r3;
                ldmx4(r0, r1, r2, r3, smb + O64W(s, 1, nr, fc) * 2);
                bl[2*pr][0] = r0; bl[2*pr+1][0] = r1;
                bl[2*pr][1] = r2; bl[2*pr+1][1] = r3;
            }
            #pragma unroll
            for (int mt = 0; mt < 2; mt++) {
                int mr = wm * 32 + mt * 16 + fr;
                uint32_t ah[4], al[4];
                ldmx4(ah[0], ah[1], ah[2], ah[3], smb + O64A(s, 0, mr, fc) * 2);
                ldmx4(al[0], al[1], al[2], al[3], smb + O64A(s, 1, mr, fc) * 2);
                #pragma unroll
                for (int nt = 0; nt < 4; nt++) {
                    mma_bf(acc[mt][nt], ah, bh[nt]);
                    mma_bf(acc[mt][nt], ah, bl[nt]);
                    mma_bf(acc[mt][nt], al, bh[nt]);
                }
            }
        }
        __syncthreads();
    }

    #pragma unroll
    for (int mt = 0; mt < 2; mt++) {
        int r0 = row0 + wm * 32 + mt * 16 + g;
        #pragma unroll
        for (int h = 0; h < 2; h++) {
            int r = r0 + 8 * h;
            if (r >= M) continue;
            #pragma unroll
            for (int nt = 0; nt < 4; nt++) {
                int cc = col0 + wn * 32 + nt * 8 + 2 * q;
                float v0 = acc[mt][nt][2*h]     + bias[cc];
                float v1 = acc[mt][nt][2*h + 1] + bias[cc + 1];
                gemm_epilogue_pair(r, cc, N, v0, v1, mode, C, Oh, Ol);
            }
        }
    }
}

// ------------------------------ LayerNorm -----------------------------------
__device__ __forceinline__ float blk_sum(float v, float* smr)
{
    const int lane = threadIdx.x & 31, w = threadIdx.x >> 5;
    #pragma unroll
    for (int o = 16; o; o >>= 1) v += __shfl_xor_sync(0xffffffffu, v, o);
    if (lane == 0) smr[w] = v;
    __syncthreads();
    if (threadIdx.x == 0) {
        float t = 0.f;
        #pragma unroll
        for (int i = 0; i < 8; i++) t += smr[i];
        smr[8] = t;
    }
    __syncthreads();
    float t = smr[8];
    __syncthreads();
    return t;
}

__global__ void __launch_bounds__(256) ln_hl_kernel(
    const float* __restrict__ in, const float* __restrict__ w,
    const float* __restrict__ b, __nv_bfloat16* __restrict__ oh,
    __nv_bfloat16* __restrict__ ol, int gm)
{
    __shared__ float smr[9];
    const int r = blockIdx.x;
    const float* x;
    if (gm == 0) {
        x = in + (size_t)r * CD;
    } else if (gm == 1) {
        int t = r % TT; int bn = r / TT; int n = bn % NP; int bb = bn / NP;
        x = in + ((size_t)bb * SEQ + 1 + t * NP + n) * CD;
    } else {
        int m = r % KS; int bt = r / KS; int t = bt % TT; int bb = bt / TT;
        x = in + ((m == 0) ? ((size_t)bb * SEQ) * CD
                           : ((size_t)bb * SEQ + 1 + t * NP + (m - 1)) * CD);
    }
    const int t = threadIdx.x;
    float v0 = x[t], v1 = x[t + 256], v2 = x[t + 512];
    float tot = blk_sum(v0 + v1 + v2, smr);
    float mean = tot * (1.0f / CD);
    float d0 = v0 - mean, d1 = v1 - mean, d2 = v2 - mean;
    float tot2 = blk_sum(d0 * d0 + d1 * d1 + d2 * d2, smr);
    float inv = rsqrtf(tot2 * (1.0f / CD) + 1e-6f);
    size_t base = (size_t)r * CD;
    float o0 = d0 * inv * w[t]       + b[t];
    float o1 = d1 * inv * w[t + 256] + b[t + 256];
    float o2 = d2 * inv * w[t + 512] + b[t + 512];
    split2(o0, oh[base + t],       ol[base + t]);
    split2(o1, oh[base + t + 256], ol[base + t + 256]);
    split2(o2, oh[base + t + 512], ol[base + t + 512]);
}

__global__ void __launch_bounds__(256) ln_cls_kernel(
    const float* __restrict__ w, const float* __restrict__ b)
{
    __shared__ float smr[9];
    const float* x = g_xb + (size_t)blockIdx.x * SEQ * CD;
    const int t = threadIdx.x;
    float v0 = x[t], v1 = x[t + 256], v2 = x[t + 512];
    float tot = blk_sum(v0 + v1 + v2, smr);
    float mean = tot * (1.0f / CD);
    float d0 = v0 - mean, d1 = v1 - mean, d2 = v2 - mean;
    float tot2 = blk_sum(d0 * d0 + d1 * d1 + d2 * d2, smr);
    float inv = rsqrtf(tot2 * (1.0f / CD) + 1e-6f);
    float* o = g_buf2 + (size_t)blockIdx.x * CD;
    o[t]       = d0 * inv * w[t]       + b[t];
    o[t + 256] = d1 * inv * w[t + 256] + b[t + 256];
    o[t + 512] = d2 * inv * w[t + 512] + b[t + 512];
}

// ------------------------- Time attention (seq=8) ---------------------------
__global__ void __launch_bounds__(64) time_attn_kernel()
{
    const int g = blockIdx.x;
    const int h = g % NH;
    const int bn = g / NH;
    const int lane = threadIdx.x;
    __shared__ float Q[TT][HD + 1], Kk[TT][HD + 1], V[TT][HD + 1];
    __shared__ float P[TT][TT + 1];
    #pragma unroll
    for (int t = 0; t < TT; t++) {
        size_t base = ((size_t)(bn * TT + t)) * (3 * CD) + h * HD + lane;
        Q[t][lane]  = g_qkv[base];
        Kk[t][lane] = g_qkv[base + CD];
        V[t][lane]  = g_qkv[base + 2 * CD];
    }
    __syncthreads();
    const int tq = lane >> 3, tk = lane & 7;
    float s = 0.f;
    #pragma unroll
    for (int d = 0; d < HD; d++) s += Q[tq][d] * Kk[tk][d];
    P[tq][tk] = s * 0.125f;
    __syncthreads();
    if (lane < TT) {
        float m = -1e30f;
        #pragma unroll
        for (int k = 0; k < TT; k++) m = fmaxf(m, P[lane][k]);
        float sum = 0.f;
        #pragma unroll
        for (int k = 0; k < TT; k++) { float e = expf(P[lane][k] - m); P[lane][k] = e; sum += e; }
        float inv = 1.f / sum;
        #pragma unroll
        for (int k = 0; k < TT; k++) P[lane][k] *= inv;
    }
    __syncthreads();
    #pragma unroll
    for (int t = 0; t < TT; t++) {
        float a = 0.f;
        #pragma unroll
        for (int k = 0; k < TT; k++) a += P[t][k] * V[k][lane];
        size_t idx = ((size_t)(bn * TT + t)) * CD + h * HD + lane;
        split2(a, g_at_hi[idx], g_at_lo[idx]);
    }
}

// ------------------- Fused space attention (seq=197) ------------------------
// Qs/KVs padded to HD+2 (=66) so float2 loads are 8B-aligned.
constexpr int SA_SMEM = (96 * (HD + 2) + 32 * 256) * 4;   // 58112 bytes

__global__ void __launch_bounds__(256) space_attn_kernel()
{
    extern __shared__ float sa[];
    float (*Qs)[HD + 2]  = (float(*)[HD + 2])sa;
    float (*KVs)[HD + 2] = (float(*)[HD + 2])(sa + 32 * (HD + 2));
    float (*Ss)[256]     = (float(*)[256])(sa + 96 * (HD + 2));

    const int g = blockIdx.x;
    const int h = g % NH, bt = g / NH;
    const int q0 = blockIdx.y * 32;
    const int tid = threadIdx.x;
    const int kc = tid & 63, qb = tid >> 6;

    for (int i = tid; i < 32 * 64; i += 256) {
        int r = i >> 6, d = i & 63; int gq = q0 + r;
        Qs[r][d] = (gq < KS)
            ? g_qkv[((size_t)(bt * KS + gq)) * (3 * CD) + h * HD + d] : 0.f;
    }

    // scores: loop K tiles of 64, float2-vectorized over d
    for (int kt = 0; kt < 4; kt++) {
        const int k0 = kt * 64;
        __syncthreads();
        for (int i = tid; i < 64 * 64; i += 256) {
            int r = i >> 6, d = i & 63; int gk = k0 + r;
            KVs[r][d] = (gk < KS)
                ? g_qkv[((size_t)(bt * KS + gk)) * (3 * CD) + CD + h * HD + d] : 0.f;
        }
        __syncthreads();
        float s[8];
        #pragma unroll
        for (int i = 0; i < 8; i++) s[i] = 0.f;
        #pragma unroll
        for (int d = 0; d < HD; d += 2) {
            float2 kv = *(const float2*)&KVs[kc][d];
            #pragma unroll
            for (int i = 0; i < 8; i++) {
                float2 qv = *(const float2*)&Qs[qb + 4 * i][d];
                s[i] = fmaf(qv.x, kv.x, s[i]);
                s[i] = fmaf(qv.y, kv.y, s[i]);
            }
        }
        #pragma unroll
        for (int i = 0; i < 8; i++) Ss[qb + 4 * i][k0 + kc] = s[i] * 0.125f;
    }
    __syncthreads();

    // softmax: warp w handles rows 4w..4w+3
    {
        const int lane = tid & 31;
        const int rbase = (tid >> 5) * 4;
        for (int rr = 0; rr < 4; rr++) {
            const int r = rbase + rr;
            float vals[7];
            float m = -1e30f;
            #pragma unroll
            for (int i = 0; i < 7; i++) {
                int j = lane + 32 * i;
                vals[i] = (j < KS) ? Ss[r][j] : -1e30f;
                m = fmaxf(m, vals[i]);
            }
            #pragma unroll
            for (int o = 16; o; o >>= 1) m = fmaxf(m, __shfl_xor_sync(0xffffffffu, m, o));
            float sum = 0.f;
            #pragma unroll
            for (int i = 0; i < 7; i++) {
                int j = lane + 32 * i;
                if (j < KS) { vals[i] = expf(vals[i] - m); sum += vals[i]; }
            }
            #pragma unroll
            for (int o = 16; o; o >>= 1) sum += __shfl_xor_sync(0xffffffffu, sum, o);
            float inv = 1.f / sum;
            #pragma unroll
            for (int i = 0; i < 7; i++) {
                int j = lane + 32 * i;
                if (j < KS) Ss[r][j] = vals[i] * inv;
            }
        }
    }
    __syncthreads();

    // P @ V: float2-vectorized over kk (V rows >= KS are zero)
    float acc[8];
    #pragma unroll
    for (int i = 0; i < 8; i++) acc[i] = 0.f;
    for (int kt = 0; kt < 4; kt++) {
        const int k0 = kt * 64;
        for (int i = tid; i < 64 * 64; i += 256) {
            int r = i >> 6, d = i & 63; int gk = k0 + r;
            KVs[r][d] = (gk < KS)
                ? g_qkv[((size_t)(bt * KS + gk)) * (3 * CD) + 2 * CD + h * HD + d] : 0.f;
        }
        __syncthreads();
        #pragma unroll
        for (int kk = 0; kk < 64; kk += 2) {
            float v0 = KVs[kk][kc];
            float v1 = KVs[kk + 1][kc];
            #pragma unroll
            for (int i = 0; i < 8; i++) {
                float2 p = *(const float2*)&Ss[qb + 4 * i][k0 + kk];
                acc[i] = fmaf(p.x, v0, acc[i]);
                acc[i] = fmaf(p.y, v1, acc[i]);
            }
        }
        __syncthreads();
    }

    #pragma unroll
    for (int i = 0; i < 8; i++) {
        int gq = q0 + qb + 4 * i;
        if (gq < KS) {
            size_t idx = ((size_t)(bt * KS + gq)) * CD + h * HD + kc;
            split2(acc[i], g_at_hi[idx], g_at_lo[idx]);
        }
    }
}

// --------------------------- elementwise helpers ----------------------------
__global__ void patchify_kernel(const float* __restrict__ x)
{
    int i = blockIdx.x * blockDim.x + threadIdx.x;
    if (i >= RT * CD) return;
    int k = i % CD; int r = i / CD;
    int n = r % NP; int bt = r / NP; int t = bt % TT; int b = bt / TT;
    int ci = k >> 8; int rem = k & 255; int py = rem >> 4; int px = rem & 15;
    int nh = n / 14, nw = n % 14;
    size_t src = ((((size_t)b * 3 + ci) * TT + t) * 224 + (nh * 16 + py)) * 224 + (nw * 16 + px);
    split2(x[src], g_pa_hi[i], g_pa_lo[i]);
}

__global__ void init_cls_kernel(const float* __restrict__ cls_token,
                                const float* __restrict__ pos_embed)
{
    int i = blockIdx.x * blockDim.x + threadIdx.x;
    if (i >= BATCH * CD) return;
    int b = i / CD, c = i % CD;
    g_xb[((size_t)b * SEQ) * CD + c] = cls_token[c] + pos_embed[c];
}

__global__ void init_patch_kernel(const float* __restrict__ pos_embed,
                                  const float* __restrict__ time_embed)
{
    int i = blockIdx.x * blockDim.x + threadIdx.x;
    if (i >= RT * CD) return;
    int c = i % CD; int r = i / CD;
    int n = r % NP; int bt = r / NP; int t = bt % TT; int b = bt / TT;
    g_xb[((size_t)b * SEQ + 1 + t * NP + n) * CD + c] =
        g_buf3[i] + pos_embed[(size_t)(1 + n) * CD + c] + time_embed[(size_t)t * CD + c];
}

__global__ void combine_cls_kernel()
{
    int i = blockIdx.x * blockDim.x + threadIdx.x;
    if (i >= BATCH * CD) return;
    int b = i / CD, c = i % CD;
    float s = 0.f;
    #pragma unroll
    for (int t = 0; t < TT; t++)
        s += g_buf3[((size_t)((b * TT + t) * KS)) * CD + c];
    g_xb[((size_t)b * SEQ) * CD + c] += s * (1.f / TT);
}

// ------------------------------- head ---------------------------------------
__global__ void __launch_bounds__(256) head_kernel(
    const float* __restrict__ hw, const float* __restrict__ hb,
    float* __restrict__ out)
{
    const int warp = threadIdx.x >> 5, lane = threadIdx.x & 31;
    const int o = blockIdx.x * 8 + warp;
    if (o >= BATCH * 1000) return;
    const int b = o / 1000, j = o % 1000;
    const float* xr = g_buf2 + (size_t)b * CD;
    const float* wr = hw + (size_t)j * CD;
    float s = 0.f;
    for (int k = lane; k < CD; k += 32) s += xr[k] * wr[k];
    #pragma unroll
    for (int off = 16; off; off >>= 1) s += __shfl_down_sync(0xffffffffu, s, off);
    if (lane == 0) out[o] = s + hb[j];
}

// ------------------------------ launcher ------------------------------------
static inline int cdiv(int a, int b) { return (a + b - 1) / b; }

static void gemm_bf(const __nv_bfloat16* Ah, const __nv_bfloat16* Al,
                    const __nv_bfloat16* Wh, const __nv_bfloat16* Wl,
                    const float* bias, float* C,
                    __nv_bfloat16* Oh, __nv_bfloat16* Ol,
                    int M, int N, int K, int mode)
{
    if (N == 768) {
        dim3 gr(N / 128, cdiv(M, 64));
        bf_gemm64_kernel<<<gr, 256, GEMM64_SMEM>>>(Ah, Al, Wh, Wl, bias, C,
                                                   Oh, Ol, M, N, K, mode);
    } else {
        dim3 gr(N / 128, cdiv(M, 128));
        bf_gemm_kernel<<<gr, 256, GEMM_SMEM>>>(Ah, Al, Wh, Wl, bias, C, Oh, Ol,
                                               M, N, K, mode, 0, 0, 0);
    }
}

static void wsplit(const float* src, __nv_bfloat16* hi, __nv_bfloat16* lo, size_t n)
{
    long n4 = (long)(n / 4);
    wsplit_kernel<<<(int)((n4 + 255) / 256), 256>>>(
        (const float4*)src, (__nv_bfloat162*)hi, (__nv_bfloat162*)lo, n4);
}

extern "C" void kernel_launch(void* const* d_in, const int* in_sizes, int n_in,
                              void* d_out, int out_size)
{
    const float* x          = (const float*)d_in[0];
    const float* conv_w     = (const float*)d_in[1];
    const float* conv_b     = (const float*)d_in[2];
    const float* cls_token  = (const float*)d_in[3];
    const float* pos_embed  = (const float*)d_in[4];
    const float* time_embed = (const float*)d_in[5];
    const float* tn_w   = (const float*)d_in[6];
    const float* tn_b   = (const float*)d_in[7];
    const float* tqkv_w = (const float*)d_in[8];
    const float* tqkv_b = (const float*)d_in[9];
    const float* tproj_w= (const float*)d_in[10];
    const float* tproj_b= (const float*)d_in[11];
    const float* tfc_w  = (const float*)d_in[12];
    const float* tfc_b  = (const float*)d_in[13];
    const float* n1_w   = (const float*)d_in[14];
    const float* n1_b   = (const float*)d_in[15];
    const float* sqkv_w = (const float*)d_in[16];
    const float* sqkv_b = (const float*)d_in[17];
    const float* sproj_w= (const float*)d_in[18];
    const float* sproj_b= (const float*)d_in[19];
    const float* n2_w   = (const float*)d_in[20];
    const float* n2_b   = (const float*)d_in[21];
    const float* fc1_w  = (const float*)d_in[22];
    const float* fc1_b  = (const float*)d_in[23];
    const float* fc2_w  = (const float*)d_in[24];
    const float* fc2_b  = (const float*)d_in[25];
    const float* norm_w = (const float*)d_in[26];
    const float* norm_b = (const float*)d_in[27];
    const float* head_w = (const float*)d_in[28];
    const float* head_b = (const float*)d_in[29];

    float *xb, *buf3, *qkv, *wc, *bc, *zero;
    cudaGetSymbolAddress((void**)&xb,   g_xb);
    cudaGetSymbolAddress((void**)&buf3, g_buf3);
    cudaGetSymbolAddress((void**)&qkv,  g_qkv);
    cudaGetSymbolAddress((void**)&wc,   g_wc);
    cudaGetSymbolAddress((void**)&bc,   g_bc);
    cudaGetSymbolAddress((void**)&zero, g_zero);

    __nv_bfloat16 *whi, *wlo, *lnh, *lnl, *ath, *atl, *f1h, *f1l, *pah, *pal;
    cudaGetSymbolAddress((void**)&whi, g_w_hi);
    cudaGetSymbolAddress((void**)&wlo, g_w_lo);
    cudaGetSymbolAddress((void**)&lnh, g_ln_hi);
    cudaGetSymbolAddress((void**)&lnl, g_ln_lo);
    cudaGetSymbolAddress((void**)&ath, g_at_hi);
    cudaGetSymbolAddress((void**)&atl, g_at_lo);
    cudaGetSymbolAddress((void**)&f1h, g_f1_hi);
    cudaGetSymbolAddress((void**)&f1l, g_f1_lo);
    cudaGetSymbolAddress((void**)&pah, g_pa_hi);
    cudaGetSymbolAddress((void**)&pal, g_pa_lo);

    cudaFuncSetAttribute(bf_gemm_kernel,
                         cudaFuncAttributeMaxDynamicSharedMemorySize, GEMM_SMEM);
    cudaFuncSetAttribute(bf_gemm64_kernel,
                         cudaFuncAttributeMaxDynamicSharedMemorySize, GEMM64_SMEM);
    cudaFuncSetAttribute(space_attn_kernel,
                         cudaFuncAttributeMaxDynamicSharedMemorySize, SA_SMEM);

    const int EB = 256;

    // ---- split weights into bf16 hi/lo ----
    wsplit(tqkv_w,  whi + W_TQKV,  wlo + W_TQKV,  SZ_TQKV);
    wsplit(tfc_w,   whi + W_TFC,   wlo + W_TFC,   SZ_CC);
    wsplit(sqkv_w,  whi + W_SQKV,  wlo + W_SQKV,  SZ_TQKV);
    wsplit(sproj_w, whi + W_SPROJ, wlo + W_SPROJ, SZ_CC);
    wsplit(fc1_w,   whi + W_FC1,   wlo + W_FC1,   SZ_FC);
    wsplit(fc2_w,   whi + W_FC2,   wlo + W_FC2,   SZ_FC);
    wsplit(conv_w,  whi + W_CONV,  wlo + W_CONV,  (size_t)CD * CD);

    // ---- merge tproj into tfc: Wc = tfc_w @ tproj_w, bc = tfc_w@tproj_b + tfc_b
    {
        dim3 tb(32, 8);
        dim3 tg(CD / 32, CD / 32, DEPTH);
        tsplit_kernel<<<tg, tb>>>(tproj_w, f1h, f1l);
        dim3 gw(CD / 128, CD / 128, DEPTH);
        bf_gemm_kernel<<<gw, 256, GEMM_SMEM>>>(
            whi + W_TFC, wlo + W_TFC, f1h, f1l, zero, wc, nullptr, nullptr,
            CD, CD, CD, 0, (long)CD * CD, (long)CD * CD, (long)CD * CD);
        bias_merge_kernel<<<cdiv(DEPTH * CD, 8), 256>>>(tfc_w, tproj_b, tfc_b);
        wsplit(wc, whi + W_TFC, wlo + W_TFC, SZ_CC);
    }

    // ---- patch embedding + pos/time embed + cls init ----
    patchify_kernel<<<cdiv(RT * CD, EB), EB>>>(x);
    gemm_bf(pah, pal, whi + W_CONV, wlo + W_CONV, conv_b, buf3, nullptr, nullptr,
            RT, CD, CD, 0);
    init_cls_kernel<<<cdiv(BATCH * CD, EB), EB>>>(cls_token, pos_embed);
    init_patch_kernel<<<cdiv(RT * CD, EB), EB>>>(pos_embed, time_embed);

    // ---- transformer blocks ----
    for (int l = 0; l < DEPTH; l++) {
        size_t o3 = (size_t)l * 3 * CD * CD;
        size_t o1 = (size_t)l * CD * CD;
        size_t o4 = (size_t)l * 4 * CD * CD;

        // ===== time attention =====
        ln_hl_kernel<<<RT, 256>>>(xb, tn_w + (size_t)l * CD, tn_b + (size_t)l * CD,
                                  lnh, lnl, 1);
        gemm_bf(lnh, lnl, whi + W_TQKV + o3, wlo + W_TQKV + o3,
                tqkv_b + (size_t)l * 3 * CD, qkv, nullptr, nullptr,
                RT, 3 * CD, CD, 0);
        time_attn_kernel<<<(RT / TT) * NH, 64>>>();
        gemm_bf(ath, atl, whi + W_TFC + o1, wlo + W_TFC + o1,
                bc + (size_t)l * CD, nullptr, nullptr, nullptr,
                RT, CD, CD, 3);                       // merged proj+fc, scatter-add

        // ===== space attention =====
        ln_hl_kernel<<<RS, 256>>>(xb, n1_w + (size_t)l * CD, n1_b + (size_t)l * CD,
                                  lnh, lnl, 2);
        gemm_bf(lnh, lnl, whi + W_SQKV + o3, wlo + W_SQKV + o3,
                sqkv_b + (size_t)l * 3 * CD, qkv, nullptr, nullptr,
                RS, 3 * CD, CD, 0);
        {
            dim3 gr(GROUPS, cdiv(KS, 32));
            space_attn_kernel<<<gr, 256, SA_SMEM>>>();
        }
        gemm_bf(ath, atl, whi + W_SPROJ + o1, wlo + W_SPROJ + o1,
                sproj_b + (size_t)l * CD, nullptr, nullptr, nullptr,
                RS, CD, CD, 5);                       // scatter-add + cls->buf3
        combine_cls_kernel<<<cdiv(BATCH * CD, EB), EB>>>();

        // ===== MLP =====
        ln_hl_kernel<<<RX, 256>>>(xb, n2_w + (size_t)l * CD, n2_b + (size_t)l * CD,
                                  lnh, lnl, 0);
        gemm_bf(lnh, lnl, whi + W_FC1 + o4, wlo + W_FC1 + o4,
                fc1_b + (size_t)l * 4 * CD, nullptr, f1h, f1l,
                RX, 4 * CD, CD, 1);
        gemm_bf(f1h, f1l, whi + W_FC2 + o4, wlo + W_FC2 + o4,
                fc2_b + (size_t)l * CD, nullptr, nullptr, nullptr,
                RX, CD, 4 * CD, 4);                   // residual add into xb
    }

    // ---- final norm (cls rows only) + head ----
    ln_cls_kernel<<<BATCH, 256>>>(norm_w, norm_b);
    head_kernel<<<cdiv(BATCH * 1000, 8), 256>>>(head_w, head_b, (float*)d_out);
}

// round 16
// speedup vs baseline: 1.8608x; 1.0341x over previous
#include <cuda_runtime.h>
#include <cuda_bf16.h>
#include <math.h>
#include <stdint.h>

// ---------------------------------------------------------------------------
// TimeSformer forward. B=2, T=8, N=196, C=768, H=12, hd=64, depth=12.
// GEMMs: bf16x3 tensor-core (hi/lo split). 128x128 CTA for wide-N,
// 64x128 CTA (3-stage) for N=768 GEMMs. tproj*tfc merged; space attn fused.
// Last layer: dead-code elimination — only cls-dependent work is computed.
// ---------------------------------------------------------------------------

constexpr int BATCH = 2;
constexpr int TT    = 8;
constexpr int NP    = 196;
constexpr int CD    = 768;
constexpr int NH    = 12;
constexpr int HD    = 64;
constexpr int SEQ   = 1 + TT * NP;          // 1569
constexpr int RT    = BATCH * TT * NP;      // 3136
constexpr int KS    = NP + 1;               // 197
constexpr int RS    = BATCH * TT * KS;      // 3152
constexpr int RX    = BATCH * SEQ;          // 3138
constexpr int GROUPS= BATCH * TT * NH;      // 192
constexpr int DEPTH = 12;

// -------------------------- scratch (device globals) -----------------------
__device__ float g_xb     [(size_t)BATCH * SEQ * CD];
__device__ float g_buf2   [(size_t)BATCH * CD];
__device__ float g_buf3   [(size_t)RS * CD];
__device__ float g_qkv    [(size_t)RS * 3 * CD];
__device__ float g_wc     [(size_t)DEPTH * CD * CD];
__device__ float g_bc     [(size_t)DEPTH * CD];
__device__ float g_zero   [CD];

__device__ __nv_bfloat16 g_ln_hi[(size_t)RS * CD];
__device__ __nv_bfloat16 g_ln_lo[(size_t)RS * CD];
__device__ __nv_bfloat16 g_at_hi[(size_t)RS * CD];
__device__ __nv_bfloat16 g_at_lo[(size_t)RS * CD];
__device__ __nv_bfloat16 g_f1_hi[(size_t)RX * 4 * CD];
__device__ __nv_bfloat16 g_f1_lo[(size_t)RX * 4 * CD];
__device__ __nv_bfloat16 g_pa_hi[(size_t)RT * CD];
__device__ __nv_bfloat16 g_pa_lo[(size_t)RT * CD];

constexpr size_t SZ_TQKV = (size_t)DEPTH * 3 * CD * CD;
constexpr size_t SZ_CC   = (size_t)DEPTH * CD * CD;
constexpr size_t SZ_FC   = (size_t)DEPTH * 4 * CD * CD;
constexpr size_t W_TQKV  = 0;
constexpr size_t W_TFC   = W_TQKV + SZ_TQKV;
constexpr size_t W_SQKV  = W_TFC + SZ_CC;
constexpr size_t W_SPROJ = W_SQKV + SZ_TQKV;
constexpr size_t W_FC1   = W_SPROJ + SZ_CC;
constexpr size_t W_FC2   = W_FC1 + SZ_FC;
constexpr size_t W_CONV  = W_FC2 + SZ_FC;
constexpr size_t W_TOTAL = W_CONV + (size_t)CD * CD;

__device__ __nv_bfloat16 g_w_hi[W_TOTAL];
__device__ __nv_bfloat16 g_w_lo[W_TOTAL];

// ------------------------------ split helper --------------------------------
__device__ __forceinline__ void split2(float x, __nv_bfloat16& h, __nv_bfloat16& l)
{
    h = __float2bfloat16(x);
    l = __float2bfloat16(x - __bfloat162float(h));
}

// ------------------------- weight split kernels ------------------------------
__global__ void __launch_bounds__(256) wsplit_kernel(
    const float4* __restrict__ src, __nv_bfloat162* __restrict__ hi,
    __nv_bfloat162* __restrict__ lo, long n4)
{
    long i = blockIdx.x * (long)blockDim.x + threadIdx.x;
    if (i >= n4) return;
    float4 v = src[i];
    __nv_bfloat16 h0,l0,h1,l1,h2,l2,h3,l3;
    split2(v.x, h0, l0); split2(v.y, h1, l1);
    split2(v.z, h2, l2); split2(v.w, h3, l3);
    hi[2*i]   = __halves2bfloat162(h0, h1);
    hi[2*i+1] = __halves2bfloat162(h2, h3);
    lo[2*i]   = __halves2bfloat162(l0, l1);
    lo[2*i+1] = __halves2bfloat162(l2, l3);
}

__global__ void tsplit_kernel(const float* __restrict__ src,
                              __nv_bfloat16* __restrict__ oh,
                              __nv_bfloat16* __restrict__ ol)
{
    __shared__ float t[32][33];
    const int l = blockIdx.z;
    const int x0 = blockIdx.x * 32, y0 = blockIdx.y * 32;
    const float* s = src + (size_t)l * CD * CD;
    for (int a = threadIdx.y; a < 32; a += 8)
        t[a][threadIdx.x] = s[(size_t)(y0 + a) * CD + x0 + threadIdx.x];
    __syncthreads();
    __nv_bfloat16* ohl = oh + (size_t)l * CD * CD;
    __nv_bfloat16* oll = ol + (size_t)l * CD * CD;
    for (int a = threadIdx.y; a < 32; a += 8) {
        float v = t[threadIdx.x][a];
        size_t idx = (size_t)(x0 + a) * CD + y0 + threadIdx.x;
        split2(v, ohl[idx], oll[idx]);
    }
}

__global__ void __launch_bounds__(256) bias_merge_kernel(
    const float* __restrict__ tfcw, const float* __restrict__ tprojb,
    const float* __restrict__ tfcb)
{
    const int warp = threadIdx.x >> 5, lane = threadIdx.x & 31;
    const int o = blockIdx.x * 8 + warp;
    if (o >= DEPTH * CD) return;
    const int l = o / CD, i = o % CD;
    const float* wr = tfcw + ((size_t)l * CD + i) * CD;
    const float* br = tprojb + (size_t)l * CD;
    float s = 0.f;
    for (int k = lane; k < CD; k += 32) s += wr[k] * br[k];
    #pragma unroll
    for (int off = 16; off; off >>= 1) s += __shfl_down_sync(0xffffffffu, s, off);
    if (lane == 0) g_bc[o] = s + tfcb[o];
}

// ------------------------- GEMM common pieces --------------------------------
__device__ __forceinline__ void cpa16(uint32_t dst, const void* src, int srcsz)
{
    asm volatile("cp.async.ca.shared.global [%0], [%1], 16, %2;"
                 :: "r"(dst), "l"(src), "r"(srcsz));
}
__device__ __forceinline__ void ldmx4(uint32_t& r0, uint32_t& r1,
                                      uint32_t& r2, uint32_t& r3, uint32_t addr)
{
    asm volatile("ldmatrix.sync.aligned.m8n8.x4.shared.b16 {%0,%1,%2,%3}, [%4];"
        : "=r"(r0), "=r"(r1), "=r"(r2), "=r"(r3) : "r"(addr));
}
__device__ __forceinline__ void mma_bf(float* c, const uint32_t* a, const uint32_t* b)
{
    asm volatile("mma.sync.aligned.m16n8k16.row.col.f32.bf16.bf16.f32 "
        "{%0,%1,%2,%3}, {%4,%5,%6,%7}, {%8,%9}, {%0,%1,%2,%3};"
        : "+f"(c[0]), "+f"(c[1]), "+f"(c[2]), "+f"(c[3])
        : "r"(a[0]), "r"(a[1]), "r"(a[2]), "r"(a[3]), "r"(b[0]), "r"(b[1]));
}

// epilogue shared by both GEMMs: handles one (r, cc) float2
// modes: 0 f32->C | 1 GELU->bf16 hi/lo | 2 bf16 hi/lo
//        3 time-scatter += xb | 4 += xb | 5 space-scatter += xb (cls->buf3)
//        6 += xb cls row of batch r
__device__ __forceinline__ void gemm_epilogue_pair(
    int r, int cc, int ldc, float v0, float v1, int mode,
    float* C, __nv_bfloat16* Oh, __nv_bfloat16* Ol)
{
    if (mode == 0) {
        *(float2*)&C[(size_t)r * ldc + cc] = make_float2(v0, v1);
    } else if (mode == 1 || mode == 2) {
        if (mode == 1) { v0 = v0 * normcdff(v0); v1 = v1 * normcdff(v1); }
        __nv_bfloat16 h0, l0, h1, l1;
        split2(v0, h0, l0); split2(v1, h1, l1);
        *(__nv_bfloat162*)&Oh[(size_t)r * ldc + cc] = __halves2bfloat162(h0, h1);
        *(__nv_bfloat162*)&Ol[(size_t)r * ldc + cc] = __halves2bfloat162(l0, l1);
    } else {
        size_t xbase; bool is_cls = false;
        if (mode == 3) {
            int tt = r % TT; int bn = r / TT; int n = bn % NP; int b = bn / NP;
            xbase = ((size_t)b * SEQ + 1 + tt * NP + n) * CD;
        } else if (mode == 4) {
            xbase = (size_t)r * CD;
        } else if (mode == 6) {
            xbase = (size_t)r * SEQ * CD;
        } else {
            int m = r % KS; int bt = r / KS; int tt = bt % TT; int b = bt / TT;
            if (m == 0) { is_cls = true; xbase = (size_t)r * CD; }
            else xbase = ((size_t)b * SEQ + 1 + tt * NP + (m - 1)) * CD;
        }
        if (is_cls) {
            *(float2*)&g_buf3[xbase + cc] = make_float2(v0, v1);
        } else {
            float2 old = *(float2*)&g_xb[xbase + cc];
            old.x += v0; old.y += v1;
            *(float2*)&g_xb[xbase + cc] = old;
        }
    }
}

// ---------------------- bf16x3 GEMM, 128x128 CTA -----------------------------
#define SOFF(s, arr, row, col) (((((s)*4 + (arr))*128 + (row))*40 + (col)))
constexpr int GEMM_SMEM = 2 * 4 * 128 * 40 * 2;   // 81920 bytes

__global__ void __launch_bounds__(256) bf_gemm_kernel(
    const __nv_bfloat16* __restrict__ Ah, const __nv_bfloat16* __restrict__ Al,
    const __nv_bfloat16* __restrict__ Wh, const __nv_bfloat16* __restrict__ Wl,
    const float* __restrict__ bias, float* __restrict__ C,
    __nv_bfloat16* __restrict__ Oh, __nv_bfloat16* __restrict__ Ol,
    int M, int N, int K, int mode, int ldc, long sA, long sW, long sC)
{
    extern __shared__ __align__(16) __nv_bfloat16 sm[];
    const uint32_t smb = (uint32_t)__cvta_generic_to_shared(sm);

    const long z = blockIdx.z;
    Ah += z * sA; Al += z * sA;
    Wh += z * sW; Wl += z * sW;
    if (C) C += z * sC;

    int bx = blockIdx.x, by = blockIdx.y;
    if (by & 1) bx = gridDim.x - 1 - bx;       // serpentine for L2 reuse

    const int tid  = threadIdx.x;
    const int wid  = tid >> 5;
    const int lane = tid & 31;
    const int wm   = wid >> 2;
    const int wn   = wid & 3;
    const int g    = lane >> 2;
    const int q    = lane & 3;
    const int row0 = by * 128;
    const int col0 = bx * 128;

    float acc[4][4][4];
    #pragma unroll
    for (int i = 0; i < 4; i++)
        #pragma unroll
        for (int j = 0; j < 4; j++)
            #pragma unroll
            for (int v = 0; v < 4; v++) acc[i][j][v] = 0.f;

    const int lrow = tid >> 1;
    const int c0b  = (tid & 1) * 2;
    const int T = K / 32;

    auto prefetch = [&](int t, int s) {
        const int k0 = t * 32;
        int gr = row0 + lrow;
        int av = (gr < M) ? 16 : 0;
        size_t aoff = (size_t)(gr < M ? gr : 0) * K + k0;
        size_t boff = (size_t)(col0 + lrow) * K + k0;
        #pragma unroll
        for (int c = c0b; c < c0b + 2; c++) {
            cpa16(smb + SOFF(s, 0, lrow, c*8) * 2, Ah + aoff + c*8, av);
            cpa16(smb + SOFF(s, 1, lrow, c*8) * 2, Al + aoff + c*8, av);
            cpa16(smb + SOFF(s, 2, lrow, c*8) * 2, Wh + boff + c*8, 16);
            cpa16(smb + SOFF(s, 3, lrow, c*8) * 2, Wl + boff + c*8, 16);
        }
        asm volatile("cp.async.commit_group;" ::: "memory");
    };

    prefetch(0, 0);

    const int fr = lane & 15;
    for (int t = 0; t < T; t++) {
        const int s = t & 1;
        asm volatile("cp.async.wait_group 0;" ::: "memory");
        __syncthreads();
        if (t + 1 < T) prefetch(t + 1, (t + 1) & 1);

        #pragma unroll
        for (int kh = 0; kh < 32; kh += 16) {
            const int fc = kh + (lane >> 4) * 8;
            uint32_t bh[4][2], bl[4][2];
            #pragma unroll
            for (int pr = 0; pr < 2; pr++) {
                int nr = wn * 32 + pr * 16 + fr;
                uint32_t r0, r1, r2, r3;
                ldmx4(r0, r1, r2, r3, smb + SOFF(s, 2, nr, fc) * 2);
                bh[2*pr][0] = r0; bh[2*pr+1][0] = r1;
                bh[2*pr][1] = r2; bh[2*pr+1][1] = r3;
                ldmx4(r0, r1, r2, r3, smb + SOFF(s, 3, nr, fc) * 2);
                bl[2*pr][0] = r0; bl[2*pr+1][0] = r1;
                bl[2*pr][1] = r2; bl[2*pr+1][1] = r3;
            }
            #pragma unroll
            for (int mt = 0; mt < 4; mt++) {
                int mr = wm * 64 + mt * 16 + fr;
                uint32_t ah[4], al[4];
                ldmx4(ah[0], ah[1], ah[2], ah[3], smb + SOFF(s, 0, mr, fc) * 2);
                ldmx4(al[0], al[1], al[2], al[3], smb + SOFF(s, 1, mr, fc) * 2);
                #pragma unroll
                for (int nt = 0; nt < 4; nt++) {
                    mma_bf(acc[mt][nt], ah, bh[nt]);
                    mma_bf(acc[mt][nt], ah, bl[nt]);
                    mma_bf(acc[mt][nt], al, bh[nt]);
                }
            }
        }
        __syncthreads();
    }

    #pragma unroll
    for (int mt = 0; mt < 4; mt++) {
        int r0 = row0 + wm * 64 + mt * 16 + g;
        #pragma unroll
        for (int h = 0; h < 2; h++) {
            int r = r0 + 8 * h;
            if (r >= M) continue;
            #pragma unroll
            for (int nt = 0; nt < 4; nt++) {
                int cc = col0 + wn * 32 + nt * 8 + 2 * q;
                float v0 = acc[mt][nt][2*h]     + bias[cc];
                float v1 = acc[mt][nt][2*h + 1] + bias[cc + 1];
                gemm_epilogue_pair(r, cc, ldc, v0, v1, mode, C, Oh, Ol);
            }
        }
    }
}

// ---------------------- bf16x3 GEMM, 64x128 CTA, 3-stage ---------------------
constexpr int ST64 = 2*64*40 + 2*128*40;          // 15360 elems per stage
constexpr int GEMM64_SMEM = 3 * ST64 * 2;         // 92160 bytes
#define O64A(s, arr, row, col) ((s)*ST64 + (arr)*64*40 + (row)*40 + (col))
#define O64W(s, arr, row, col) ((s)*ST64 + 2*64*40 + (arr)*128*40 + (row)*40 + (col))

__global__ void __launch_bounds__(256) bf_gemm64_kernel(
    const __nv_bfloat16* __restrict__ Ah, const __nv_bfloat16* __restrict__ Al,
    const __nv_bfloat16* __restrict__ Wh, const __nv_bfloat16* __restrict__ Wl,
    const float* __restrict__ bias, float* __restrict__ C,
    __nv_bfloat16* __restrict__ Oh, __nv_bfloat16* __restrict__ Ol,
    int M, int N, int K, int mode, int ldc)
{
    extern __shared__ __align__(16) __nv_bfloat16 sm[];
    const uint32_t smb = (uint32_t)__cvta_generic_to_shared(sm);

    int bx = blockIdx.x, by = blockIdx.y;
    if (by & 1) bx = gridDim.x - 1 - bx;

    const int tid  = threadIdx.x;
    const int wid  = tid >> 5;
    const int lane = tid & 31;
    const int wm   = wid >> 2;          // 0..1 (32-row warp tile)
    const int wn   = wid & 3;           // 0..3 (32-col warp tile)
    const int g    = lane >> 2;
    const int q    = lane & 3;
    const int row0 = by * 64;
    const int col0 = bx * 128;

    float acc[2][4][4];
    #pragma unroll
    for (int i = 0; i < 2; i++)
        #pragma unroll
        for (int j = 0; j < 4; j++)
            #pragma unroll
            for (int v = 0; v < 4; v++) acc[i][j][v] = 0.f;

    const int T = K / 32;

    auto prefetch = [&](int t, int s) {
        const int k0 = t * 32;
        {
            int row = tid >> 2, c4 = tid & 3;
            int gr = row0 + row;
            int av = (gr < M) ? 16 : 0;
            size_t aoff = (size_t)(gr < M ? gr : 0) * K + k0 + c4 * 8;
            cpa16(smb + O64A(s, 0, row, c4*8) * 2, Ah + aoff, av);
            cpa16(smb + O64A(s, 1, row, c4*8) * 2, Al + aoff, av);
        }
        #pragma unroll
        for (int i = 0; i < 2; i++) {
            int ch = tid * 2 + i;
            int row = ch >> 2, c4 = ch & 3;
            size_t boff = (size_t)(col0 + row) * K + k0 + c4 * 8;
            cpa16(smb + O64W(s, 0, row, c4*8) * 2, Wh + boff, 16);
            cpa16(smb + O64W(s, 1, row, c4*8) * 2, Wl + boff, 16);
        }
        asm volatile("cp.async.commit_group;" ::: "memory");
    };

    prefetch(0, 0);
    if (T > 1) prefetch(1, 1);

    const int fr = lane & 15;
    for (int t = 0; t < T; t++) {
        const int s = t % 3;
        if (t == T - 1)
            asm volatile("cp.async.wait_group 0;" ::: "memory");
        else
            asm volatile("cp.async.wait_group 1;" ::: "memory");
        __syncthreads();
        if (t + 2 < T) prefetch(t + 2, (t + 2) % 3);

        #pragma unroll
        for (int kh = 0; kh < 32; kh += 16) {
            const int fc = kh + (lane >> 4) * 8;
            uint32_t bh[4][2], bl[4][2];
            #pragma unroll
            for (int pr = 0; pr < 2; pr++) {
                int nr = wn * 32 + pr * 16 + fr;
                uint32_t r0, r1, r2, r3;
                ldmx4(r0, r1, r2, r3, smb + O64W(s, 0, nr, fc) * 2);
                bh[2*pr][0] = r0; bh[2*pr+1][0] = r1;
                bh[2*pr][1] = r2; bh[2*pr+1][1] = r3;
                ldmx4(r0, r1, r2, r3, smb + O64W(s, 1, nr, fc) * 2);
                bl[2*pr][0] = r0; bl[2*pr+1][0] = r1;
                bl[2*pr][1] = r2; bl[2*pr+1][1] = r3;
            }
            #pragma unroll
            for (int mt = 0; mt < 2; mt++) {
                int mr = wm * 32 + mt * 16 + fr;
                uint32_t ah[4], al[4];
                ldmx4(ah[0], ah[1], ah[2], ah[3], smb + O64A(s, 0, mr, fc) * 2);
                ldmx4(al[0], al[1], al[2], al[3], smb + O64A(s, 1, mr, fc) * 2);
                #pragma unroll
                for (int nt = 0; nt < 4; nt++) {
                    mma_bf(acc[mt][nt], ah, bh[nt]);
                    mma_bf(acc[mt][nt], ah, bl[nt]);
                    mma_bf(acc[mt][nt], al, bh[nt]);
                }
            }
        }
        __syncthreads();
    }

    #pragma unroll
    for (int mt = 0; mt < 2; mt++) {
        int r0 = row0 + wm * 32 + mt * 16 + g;
        #pragma unroll
        for (int h = 0; h < 2; h++) {
            int r = r0 + 8 * h;
            if (r >= M) continue;
            #pragma unroll
            for (int nt = 0; nt < 4; nt++) {
                int cc = col0 + wn * 32 + nt * 8 + 2 * q;
                float v0 = acc[mt][nt][2*h]     + bias[cc];
                float v1 = acc[mt][nt][2*h + 1] + bias[cc + 1];
                gemm_epilogue_pair(r, cc, ldc, v0, v1, mode, C, Oh, Ol);
            }
        }
    }
}

// ------------------------------ LayerNorm -----------------------------------
__device__ __forceinline__ float blk_sum(float v, float* smr)
{
    const int lane = threadIdx.x & 31, w = threadIdx.x >> 5;
    #pragma unroll
    for (int o = 16; o; o >>= 1) v += __shfl_xor_sync(0xffffffffu, v, o);
    if (lane == 0) smr[w] = v;
    __syncthreads();
    if (threadIdx.x == 0) {
        float t = 0.f;
        #pragma unroll
        for (int i = 0; i < 8; i++) t += smr[i];
        smr[8] = t;
    }
    __syncthreads();
    float t = smr[8];
    __syncthreads();
    return t;
}

__global__ void __launch_bounds__(256) ln_hl_kernel(
    const float* __restrict__ in, const float* __restrict__ w,
    const float* __restrict__ b, __nv_bfloat16* __restrict__ oh,
    __nv_bfloat16* __restrict__ ol, int gm)
{
    __shared__ float smr[9];
    const int r = blockIdx.x;
    const float* x;
    if (gm == 0) {
        x = in + (size_t)r * CD;
    } else if (gm == 1) {
        int t = r % TT; int bn = r / TT; int n = bn % NP; int bb = bn / NP;
        x = in + ((size_t)bb * SEQ + 1 + t * NP + n) * CD;
    } else if (gm == 2) {
        int m = r % KS; int bt = r / KS; int t = bt % TT; int bb = bt / TT;
        x = in + ((m == 0) ? ((size_t)bb * SEQ) * CD
                           : ((size_t)bb * SEQ + 1 + t * NP + (m - 1)) * CD);
    } else {                              // gm 3: cls row of batch r
        x = in + (size_t)r * SEQ * CD;
    }
    const int t = threadIdx.x;
    float v0 = x[t], v1 = x[t + 256], v2 = x[t + 512];
    float tot = blk_sum(v0 + v1 + v2, smr);
    float mean = tot * (1.0f / CD);
    float d0 = v0 - mean, d1 = v1 - mean, d2 = v2 - mean;
    float tot2 = blk_sum(d0 * d0 + d1 * d1 + d2 * d2, smr);
    float inv = rsqrtf(tot2 * (1.0f / CD) + 1e-6f);
    size_t base = (size_t)r * CD;
    float o0 = d0 * inv * w[t]       + b[t];
    float o1 = d1 * inv * w[t + 256] + b[t + 256];
    float o2 = d2 * inv * w[t + 512] + b[t + 512];
    split2(o0, oh[base + t],       ol[base + t]);
    split2(o1, oh[base + t + 256], ol[base + t + 256]);
    split2(o2, oh[base + t + 512], ol[base + t + 512]);
}

__global__ void __launch_bounds__(256) ln_cls_kernel(
    const float* __restrict__ w, const float* __restrict__ b)
{
    __shared__ float smr[9];
    const float* x = g_xb + (size_t)blockIdx.x * SEQ * CD;
    const int t = threadIdx.x;
    float v0 = x[t], v1 = x[t + 256], v2 = x[t + 512];
    float tot = blk_sum(v0 + v1 + v2, smr);
    float mean = tot * (1.0f / CD);
    float d0 = v0 - mean, d1 = v1 - mean, d2 = v2 - mean;
    float tot2 = blk_sum(d0 * d0 + d1 * d1 + d2 * d2, smr);
    float inv = rsqrtf(tot2 * (1.0f / CD) + 1e-6f);
    float* o = g_buf2 + (size_t)blockIdx.x * CD;
    o[t]       = d0 * inv * w[t]       + b[t];
    o[t + 256] = d1 * inv * w[t + 256] + b[t + 256];
    o[t + 512] = d2 * inv * w[t + 512] + b[t + 512];
}

// ---------------- fp32 warp-dot for cls rows (last layer) --------------------
// out[(bt*KS)*outStride + j] = sum_k (Ah+Al)[(bt*KS)*CD+k] * W[j*CD+k] + b[j]
__global__ void __launch_bounds__(256) cls_dot_kernel(
    const __nv_bfloat16* __restrict__ Ah, const __nv_bfloat16* __restrict__ Al,
    const float* __restrict__ W, const float* __restrict__ b,
    float* __restrict__ out, long outStride)
{
    const int warp = threadIdx.x >> 5, lane = threadIdx.x & 31;
    const int o = blockIdx.x * 8 + warp;
    if (o >= BATCH * TT * CD) return;
    const int bt = o / CD, j = o % CD;
    const __nv_bfloat16* ah = Ah + (size_t)(bt * KS) * CD;
    const __nv_bfloat16* al = Al + (size_t)(bt * KS) * CD;
    const float* wr = W + (size_t)j * CD;
    float s = 0.f;
    for (int k = lane; k < CD; k += 32)
        s += (__bfloat162float(ah[k]) + __bfloat162float(al[k])) * wr[k];
    #pragma unroll
    for (int off = 16; off; off >>= 1) s += __shfl_down_sync(0xffffffffu, s, off);
    if (lane == 0) out[(size_t)(bt * KS) * outStride + j] = s + b[j];
}

// ------------------------- Time attention (seq=8) ---------------------------
__global__ void __launch_bounds__(64) time_attn_kernel()
{
    const int g = blockIdx.x;
    const int h = g % NH;
    const int bn = g / NH;
    const int lane = threadIdx.x;
    __shared__ float Q[TT][HD + 1], Kk[TT][HD + 1], V[TT][HD + 1];
    __shared__ float P[TT][TT + 1];
    #pragma unroll
    for (int t = 0; t < TT; t++) {
        size_t base = ((size_t)(bn * TT + t)) * (3 * CD) + h * HD + lane;
        Q[t][lane]  = g_qkv[base];
        Kk[t][lane] = g_qkv[base + CD];
        V[t][lane]  = g_qkv[base + 2 * CD];
    }
    __syncthreads();
    const int tq = lane >> 3, tk = lane & 7;
    float s = 0.f;
    #pragma unroll
    for (int d = 0; d < HD; d++) s += Q[tq][d] * Kk[tk][d];
    P[tq][tk] = s * 0.125f;
    __syncthreads();
    if (lane < TT) {
        float m = -1e30f;
        #pragma unroll
        for (int k = 0; k < TT; k++) m = fmaxf(m, P[lane][k]);
        float sum = 0.f;
        #pragma unroll
        for (int k = 0; k < TT; k++) { float e = expf(P[lane][k] - m); P[lane][k] = e; sum += e; }
        float inv = 1.f / sum;
        #pragma unroll
        for (int k = 0; k < TT; k++) P[lane][k] *= inv;
    }
    __syncthreads();
    #pragma unroll
    for (int t = 0; t < TT; t++) {
        float a = 0.f;
        #pragma unroll
        for (int k = 0; k < TT; k++) a += P[t][k] * V[k][lane];
        size_t idx = ((size_t)(bn * TT + t)) * CD + h * HD + lane;
        split2(a, g_at_hi[idx], g_at_lo[idx]);
    }
}

// ------------------- Fused space attention (seq=197) ------------------------
constexpr int SA_SMEM = (96 * (HD + 2) + 32 * 256) * 4;   // 58112 bytes

__global__ void __launch_bounds__(256) space_attn_kernel()
{
    extern __shared__ float sa[];
    float (*Qs)[HD + 2]  = (float(*)[HD + 2])sa;
    float (*KVs)[HD + 2] = (float(*)[HD + 2])(sa + 32 * (HD + 2));
    float (*Ss)[256]     = (float(*)[256])(sa + 96 * (HD + 2));

    const int g = blockIdx.x;
    const int h = g % NH, bt = g / NH;
    const int q0 = blockIdx.y * 32;
    const int tid = threadIdx.x;
    const int kc = tid & 63, qb = tid >> 6;

    for (int i = tid; i < 32 * 64; i += 256) {
        int r = i >> 6, d = i & 63; int gq = q0 + r;
        Qs[r][d] = (gq < KS)
            ? g_qkv[((size_t)(bt * KS + gq)) * (3 * CD) + h * HD + d] : 0.f;
    }

    for (int kt = 0; kt < 4; kt++) {
        const int k0 = kt * 64;
        __syncthreads();
        for (int i = tid; i < 64 * 64; i += 256) {
            int r = i >> 6, d = i & 63; int gk = k0 + r;
            KVs[r][d] = (gk < KS)
                ? g_qkv[((size_t)(bt * KS + gk)) * (3 * CD) + CD + h * HD + d] : 0.f;
        }
        __syncthreads();
        float s[8];
        #pragma unroll
        for (int i = 0; i < 8; i++) s[i] = 0.f;
        #pragma unroll
        for (int d = 0; d < HD; d += 2) {
            float2 kv = *(const float2*)&KVs[kc][d];
            #pragma unroll
            for (int i = 0; i < 8; i++) {
                float2 qv = *(const float2*)&Qs[qb + 4 * i][d];
                s[i] = fmaf(qv.x, kv.x, s[i]);
                s[i] = fmaf(qv.y, kv.y, s[i]);
            }
        }
        #pragma unroll
        for (int i = 0; i < 8; i++) Ss[qb + 4 * i][k0 + kc] = s[i] * 0.125f;
    }
    __syncthreads();

    {
        const int lane = tid & 31;
        const int rbase = (tid >> 5) * 4;
        for (int rr = 0; rr < 4; rr++) {
            const int r = rbase + rr;
            float vals[7];
            float m = -1e30f;
            #pragma unroll
            for (int i = 0; i < 7; i++) {
                int j = lane + 32 * i;
                vals[i] = (j < KS) ? Ss[r][j] : -1e30f;
                m = fmaxf(m, vals[i]);
            }
            #pragma unroll
            for (int o = 16; o; o >>= 1) m = fmaxf(m, __shfl_xor_sync(0xffffffffu, m, o));
            float sum = 0.f;
            #pragma unroll
            for (int i = 0; i < 7; i++) {
                int j = lane + 32 * i;
                if (j < KS) { vals[i] = expf(vals[i] - m); sum += vals[i]; }
            }
            #pragma unroll
            for (int o = 16; o; o >>= 1) sum += __shfl_xor_sync(0xffffffffu, sum, o);
            float inv = 1.f / sum;
            #pragma unroll
            for (int i = 0; i < 7; i++) {
                int j = lane + 32 * i;
                if (j < KS) Ss[r][j] = vals[i] * inv;
            }
        }
    }
    __syncthreads();

    float acc[8];
    #pragma unroll
    for (int i = 0; i < 8; i++) acc[i] = 0.f;
    for (int kt = 0; kt < 4; kt++) {
        const int k0 = kt * 64;
        for (int i = tid; i < 64 * 64; i += 256) {
            int r = i >> 6, d = i & 63; int gk = k0 + r;
            KVs[r][d] = (gk < KS)
                ? g_qkv[((size_t)(bt * KS + gk)) * (3 * CD) + 2 * CD + h * HD + d] : 0.f;
        }
        __syncthreads();
        #pragma unroll
        for (int kk = 0; kk < 64; kk += 2) {
            float v0 = KVs[kk][kc];
            float v1 = KVs[kk + 1][kc];
            #pragma unroll
            for (int i = 0; i < 8; i++) {
                float2 p = *(const float2*)&Ss[qb + 4 * i][k0 + kk];
                acc[i] = fmaf(p.x, v0, acc[i]);
                acc[i] = fmaf(p.y, v1, acc[i]);
            }
        }
        __syncthreads();
    }

    #pragma unroll
    for (int i = 0; i < 8; i++) {
        int gq = q0 + qb + 4 * i;
        if (gq < KS) {
            size_t idx = ((size_t)(bt * KS + gq)) * CD + h * HD + kc;
            split2(acc[i], g_at_hi[idx], g_at_lo[idx]);
        }
    }
}

// --------------------------- elementwise helpers ----------------------------
__global__ void patchify_kernel(const float* __restrict__ x)
{
    int i = blockIdx.x * blockDim.x + threadIdx.x;
    if (i >= RT * CD) return;
    int k = i % CD; int r = i / CD;
    int n = r % NP; int bt = r / NP; int t = bt % TT; int b = bt / TT;
    int ci = k >> 8; int rem = k & 255; int py = rem >> 4; int px = rem & 15;
    int nh = n / 14, nw = n % 14;
    size_t src = ((((size_t)b * 3 + ci) * TT + t) * 224 + (nh * 16 + py)) * 224 + (nw * 16 + px);
    split2(x[src], g_pa_hi[i], g_pa_lo[i]);
}

__global__ void init_cls_kernel(const float* __restrict__ cls_token,
                                const float* __restrict__ pos_embed)
{
    int i = blockIdx.x * blockDim.x + threadIdx.x;
    if (i >= BATCH * CD) return;
    int b = i / CD, c = i % CD;
    g_xb[((size_t)b * SEQ) * CD + c] = cls_token[c] + pos_embed[c];
}

__global__ void init_patch_kernel(const float* __restrict__ pos_embed,
                                  const float* __restrict__ time_embed)
{
    int i = blockIdx.x * blockDim.x + threadIdx.x;
    if (i >= RT * CD) return;
    int c = i % CD; int r = i / CD;
    int n = r % NP; int bt = r / NP; int t = bt % TT; int b = bt / TT;
    g_xb[((size_t)b * SEQ + 1 + t * NP + n) * CD + c] =
        g_buf3[i] + pos_embed[(size_t)(1 + n) * CD + c] + time_embed[(size_t)t * CD + c];
}

__global__ void combine_cls_kernel()
{
    int i = blockIdx.x * blockDim.x + threadIdx.x;
    if (i >= BATCH * CD) return;
    int b = i / CD, c = i % CD;
    float s = 0.f;
    #pragma unroll
    for (int t = 0; t < TT; t++)
        s += g_buf3[((size_t)((b * TT + t) * KS)) * CD + c];
    g_xb[((size_t)b * SEQ) * CD + c] += s * (1.f / TT);
}

// ------------------------------- head ---------------------------------------
__global__ void __launch_bounds__(256) head_kernel(
    const float* __restrict__ hw, const float* __restrict__ hb,
    float* __restrict__ out)
{
    const int warp = threadIdx.x >> 5, lane = threadIdx.x & 31;
    const int o = blockIdx.x * 8 + warp;
    if (o >= BATCH * 1000) return;
    const int b = o / 1000, j = o % 1000;
    const float* xr = g_buf2 + (size_t)b * CD;
    const float* wr = hw + (size_t)j * CD;
    float s = 0.f;
    for (int k = lane; k < CD; k += 32) s += xr[k] * wr[k];
    #pragma unroll
    for (int off = 16; off; off >>= 1) s += __shfl_down_sync(0xffffffffu, s, off);
    if (lane == 0) out[o] = s + hb[j];
}

// ------------------------------ launcher ------------------------------------
static inline int cdiv(int a, int b) { return (a + b - 1) / b; }

static void gemm_bf(const __nv_bfloat16* Ah, const __nv_bfloat16* Al,
                    const __nv_bfloat16* Wh, const __nv_bfloat16* Wl,
                    const float* bias, float* C,
                    __nv_bfloat16* Oh, __nv_bfloat16* Ol,
                    int M, int N, int K, int mode, int ldc = -1)
{
    if (ldc < 0) ldc = N;
    if (N == 768) {
        dim3 gr(N / 128, cdiv(M, 64));
        bf_gemm64_kernel<<<gr, 256, GEMM64_SMEM>>>(Ah, Al, Wh, Wl, bias, C,
                                                   Oh, Ol, M, N, K, mode, ldc);
    } else {
        dim3 gr(N / 128, cdiv(M, 128));
        bf_gemm_kernel<<<gr, 256, GEMM_SMEM>>>(Ah, Al, Wh, Wl, bias, C, Oh, Ol,
                                               M, N, K, mode, ldc, 0, 0, 0);
    }
}

static void wsplit(const float* src, __nv_bfloat16* hi, __nv_bfloat16* lo, size_t n)
{
    long n4 = (long)(n / 4);
    wsplit_kernel<<<(int)((n4 + 255) / 256), 256>>>(
        (const float4*)src, (__nv_bfloat162*)hi, (__nv_bfloat162*)lo, n4);
}

extern "C" void kernel_launch(void* const* d_in, const int* in_sizes, int n_in,
                              void* d_out, int out_size)
{
    const float* x          = (const float*)d_in[0];
    const float* conv_w     = (const float*)d_in[1];
    const float* conv_b     = (const float*)d_in[2];
    const float* cls_token  = (const float*)d_in[3];
    const float* pos_embed  = (const float*)d_in[4];
    const float* time_embed = (const float*)d_in[5];
    const float* tn_w   = (const float*)d_in[6];
    const float* tn_b   = (const float*)d_in[7];
    const float* tqkv_w = (const float*)d_in[8];
    const float* tqkv_b = (const float*)d_in[9];
    const float* tproj_w= (const float*)d_in[10];
    const float* tproj_b= (const float*)d_in[11];
    const float* tfc_w  = (const float*)d_in[12];
    const float* tfc_b  = (const float*)d_in[13];
    const float* n1_w   = (const float*)d_in[14];
    const float* n1_b   = (const float*)d_in[15];
    const float* sqkv_w = (const float*)d_in[16];
    const float* sqkv_b = (const float*)d_in[17];
    const float* sproj_w= (const float*)d_in[18];
    const float* sproj_b= (const float*)d_in[19];
    const float* n2_w   = (const float*)d_in[20];
    const float* n2_b   = (const float*)d_in[21];
    const float* fc1_w  = (const float*)d_in[22];
    const float* fc1_b  = (const float*)d_in[23];
    const float* fc2_w  = (const float*)d_in[24];
    const float* fc2_b  = (const float*)d_in[25];
    const float* norm_w = (const float*)d_in[26];
    const float* norm_b = (const float*)d_in[27];
    const float* head_w = (const float*)d_in[28];
    const float* head_b = (const float*)d_in[29];

    float *xb, *buf3, *qkv, *wc, *bc, *zero;
    cudaGetSymbolAddress((void**)&xb,   g_xb);
    cudaGetSymbolAddress((void**)&buf3, g_buf3);
    cudaGetSymbolAddress((void**)&qkv,  g_qkv);
    cudaGetSymbolAddress((void**)&wc,   g_wc);
    cudaGetSymbolAddress((void**)&bc,   g_bc);
    cudaGetSymbolAddress((void**)&zero, g_zero);

    __nv_bfloat16 *whi, *wlo, *lnh, *lnl, *ath, *atl, *f1h, *f1l, *pah, *pal;
    cudaGetSymbolAddress((void**)&whi, g_w_hi);
    cudaGetSymbolAddress((void**)&wlo, g_w_lo);
    cudaGetSymbolAddress((void**)&lnh, g_ln_hi);
    cudaGetSymbolAddress((void**)&lnl, g_ln_lo);
    cudaGetSymbolAddress((void**)&ath, g_at_hi);
    cudaGetSymbolAddress((void**)&atl, g_at_lo);
    cudaGetSymbolAddress((void**)&f1h, g_f1_hi);
    cudaGetSymbolAddress((void**)&f1l, g_f1_lo);
    cudaGetSymbolAddress((void**)&pah, g_pa_hi);
    cudaGetSymbolAddress((void**)&pal, g_pa_lo);

    cudaFuncSetAttribute(bf_gemm_kernel,
                         cudaFuncAttributeMaxDynamicSharedMemorySize, GEMM_SMEM);
    cudaFuncSetAttribute(bf_gemm64_kernel,
                         cudaFuncAttributeMaxDynamicSharedMemorySize, GEMM64_SMEM);
    cudaFuncSetAttribute(space_attn_kernel,
                         cudaFuncAttributeMaxDynamicSharedMemorySize, SA_SMEM);

    const int EB = 256;

    // ---- split weights into bf16 hi/lo ----
    wsplit(tqkv_w,  whi + W_TQKV,  wlo + W_TQKV,  SZ_TQKV);
    wsplit(tfc_w,   whi + W_TFC,   wlo + W_TFC,   SZ_CC);
    wsplit(sqkv_w,  whi + W_SQKV,  wlo + W_SQKV,  SZ_TQKV);
    wsplit(sproj_w, whi + W_SPROJ, wlo + W_SPROJ, SZ_CC);
    wsplit(fc1_w,   whi + W_FC1,   wlo + W_FC1,   SZ_FC);
    wsplit(fc2_w,   whi + W_FC2,   wlo + W_FC2,   SZ_FC);
    wsplit(conv_w,  whi + W_CONV,  wlo + W_CONV,  (size_t)CD * CD);

    // ---- merge tproj into tfc: Wc = tfc_w @ tproj_w, bc = tfc_w@tproj_b + tfc_b
    {
        dim3 tb(32, 8);
        dim3 tg(CD / 32, CD / 32, DEPTH);
        tsplit_kernel<<<tg, tb>>>(tproj_w, f1h, f1l);
        dim3 gw(CD / 128, CD / 128, DEPTH);
        bf_gemm_kernel<<<gw, 256, GEMM_SMEM>>>(
            whi + W_TFC, wlo + W_TFC, f1h, f1l, zero, wc, nullptr, nullptr,
            CD, CD, CD, 0, CD, (long)CD * CD, (long)CD * CD, (long)CD * CD);
        bias_merge_kernel<<<cdiv(DEPTH * CD, 8), 256>>>(tfc_w, tproj_b, tfc_b);
        wsplit(wc, whi + W_TFC, wlo + W_TFC, SZ_CC);
    }

    // ---- patch embedding + pos/time embed + cls init ----
    patchify_kernel<<<cdiv(RT * CD, EB), EB>>>(x);
    gemm_bf(pah, pal, whi + W_CONV, wlo + W_CONV, conv_b, buf3, nullptr, nullptr,
            RT, CD, CD, 0);
    init_cls_kernel<<<cdiv(BATCH * CD, EB), EB>>>(cls_token, pos_embed);
    init_patch_kernel<<<cdiv(RT * CD, EB), EB>>>(pos_embed, time_embed);

    // ---- transformer blocks ----
    for (int l = 0; l < DEPTH; l++) {
        size_t o3 = (size_t)l * 3 * CD * CD;
        size_t o1 = (size_t)l * CD * CD;
        size_t o4 = (size_t)l * 4 * CD * CD;
        const bool last = (l == DEPTH - 1);

        // ===== time attention (always full — feeds space-attn K/V) =====
        ln_hl_kernel<<<RT, 256>>>(xb, tn_w + (size_t)l * CD, tn_b + (size_t)l * CD,
                                  lnh, lnl, 1);
        gemm_bf(lnh, lnl, whi + W_TQKV + o3, wlo + W_TQKV + o3,
                tqkv_b + (size_t)l * 3 * CD, qkv, nullptr, nullptr,
                RT, 3 * CD, CD, 0);
        time_attn_kernel<<<(RT / TT) * NH, 64>>>();
        gemm_bf(ath, atl, whi + W_TFC + o1, wlo + W_TFC + o1,
                bc + (size_t)l * CD, nullptr, nullptr, nullptr,
                RT, CD, CD, 3);                       // merged proj+fc, scatter-add

        // ===== space attention =====
        ln_hl_kernel<<<RS, 256>>>(xb, n1_w + (size_t)l * CD, n1_b + (size_t)l * CD,
                                  lnh, lnl, 2);
        if (!last) {
            gemm_bf(lnh, lnl, whi + W_SQKV + o3, wlo + W_SQKV + o3,
                    sqkv_b + (size_t)l * 3 * CD, qkv, nullptr, nullptr,
                    RS, 3 * CD, CD, 0);
            {
                dim3 gr(GROUPS, cdiv(KS, 32));
                space_attn_kernel<<<gr, 256, SA_SMEM>>>();
            }
            gemm_bf(ath, atl, whi + W_SPROJ + o1, wlo + W_SPROJ + o1,
                    sproj_b + (size_t)l * CD, nullptr, nullptr, nullptr,
                    RS, CD, CD, 5);                   // scatter-add + cls->buf3
        } else {
            // KV for all rows (cols 768..2303 of qkv)
            {
                dim3 gr(1536 / 128, cdiv(RS, 128));
                bf_gemm_kernel<<<gr, 256, GEMM_SMEM>>>(
                    lnh, lnl,
                    whi + W_SQKV + o3 + (size_t)768 * CD,
                    wlo + W_SQKV + o3 + (size_t)768 * CD,
                    sqkv_b + (size_t)l * 3 * CD + 768,
                    qkv + 768, nullptr, nullptr,
                    RS, 1536, CD, 0, 3 * CD, 0, 0, 0);
            }
            // Q for the 16 cls rows only (fp32 warp-dot)
            cls_dot_kernel<<<cdiv(BATCH * TT * CD, 8), 256>>>(
                lnh, lnl, sqkv_w + o3, sqkv_b + (size_t)l * 3 * CD,
                qkv, 3 * CD);
            // scores/softmax/PV only for the q-tile containing cls
            {
                dim3 gr(GROUPS, 1);
                space_attn_kernel<<<gr, 256, SA_SMEM>>>();
            }
            // sproj for cls rows only -> buf3
            cls_dot_kernel<<<cdiv(BATCH * TT * CD, 8), 256>>>(
                ath, atl, sproj_w + o1, sproj_b + (size_t)l * CD,
                buf3, CD);
        }
        combine_cls_kernel<<<cdiv(BATCH * CD, EB), EB>>>();

        // ===== MLP =====
        if (!last) {
            ln_hl_kernel<<<RX, 256>>>(xb, n2_w + (size_t)l * CD,
                                      n2_b + (size_t)l * CD, lnh, lnl, 0);
            gemm_bf(lnh, lnl, whi + W_FC1 + o4, wlo + W_FC1 + o4,
                    fc1_b + (size_t)l * 4 * CD, nullptr, f1h, f1l,
                    RX, 4 * CD, CD, 1);
            gemm_bf(f1h, f1l, whi + W_FC2 + o4, wlo + W_FC2 + o4,
                    fc2_b + (size_t)l * CD, nullptr, nullptr, nullptr,
                    RX, CD, 4 * CD, 4);               // residual add into xb
        } else {
            // only the 2 cls rows matter for the head
            ln_hl_kernel<<<BATCH, 256>>>(xb, n2_w + (size_t)l * CD,
                                         n2_b + (size_t)l * CD, lnh, lnl, 3);
            gemm_bf(lnh, lnl, whi + W_FC1 + o4, wlo + W_FC1 + o4,
                    fc1_b + (size_t)l * 4 * CD, nullptr, f1h, f1l,
                    BATCH, 4 * CD, CD, 1);
            gemm_bf(f1h, f1l, whi + W_FC2 + o4, wlo + W_FC2 + o4,
                    fc2_b + (size_t)l * CD, nullptr, nullptr, nullptr,
                    BATCH, CD, 4 * CD, 6);            // residual into cls rows
        }
    }

    // ---- final norm (cls rows only) + head ----
    ln_cls_kernel<<<BATCH, 256>>>(norm_w, norm_b);
    head_kernel<<<cdiv(BATCH * 1000, 8), 256>>>(head_w, head_b, (float*)d_out);
}